// round 2
// baseline (speedup 1.0000x reference)
#include <cuda_runtime.h>
#include <math.h>

// ---------------- problem constants ----------------
#define M_TOT   16384      // B*S
#define SEQ     8192
#define KDIM    1024
#define HDIM    1024
#define RANK    16
#define CHUNK   256
#define NCH     32         // chunks per batch
#define NBATCH  2
#define NBC     64         // total chunks
#define LRC     0.02f      // TTT_LR * SCALING = 0.01 * 2
#define SCALE   2.0f       // LORA_ALPHA / LORA_RANK
#define CLIP    1.0f
#define LN_EPS  1e-5f

// ---------------- device scratch (no allocation allowed) ----------------
__device__ __align__(128) float g_shifted[M_TOT * KDIM];        // 64 MB
__device__ __align__(128) float g_V      [M_TOT * KDIM];        // 64 MB
__device__ __align__(128) float g_proj_in [NBC * CHUNK * RANK]; // 1 MB
__device__ __align__(128) float g_proj_err[NBC * CHUNK * RANK]; // 1 MB
__device__ __align__(128) float g_dA  [NBC * HDIM * RANK];      // 4 MB  (becomes accA in-place)
__device__ __align__(128) float g_dB  [NBC * RANK * KDIM];      // 4 MB  (becomes accB in-place)
__device__ __align__(128) float g_Aeff[NBC * HDIM * RANK];      // 4 MB
__device__ __align__(128) float g_Beff[NBC * RANK * KDIM];      // 4 MB
__device__ __align__(128) float g_coef[NBC];

// ---------------- kernel 1: LayerNorm + left shift ----------------
// shifted[b, s-1] = LN(x[b, s]); shifted[b, S-1] = 0
__global__ __launch_bounds__(256) void ln_shift_kernel(
    const float* __restrict__ x,
    const float* __restrict__ gam,
    const float* __restrict__ bet)
{
    int row = blockIdx.x;               // 0..16383 = b*SEQ + s
    int s   = row & (SEQ - 1);
    const float4* xr = (const float4*)(x + (size_t)row * KDIM);
    float4 v = xr[threadIdx.x];         // 256 threads * 4 = 1024 exactly

    float sum = v.x + v.y + v.z + v.w;
    float ssq = v.x*v.x + v.y*v.y + v.z*v.z + v.w*v.w;
    #pragma unroll
    for (int o = 16; o; o >>= 1) {
        sum += __shfl_xor_sync(0xffffffffu, sum, o);
        ssq += __shfl_xor_sync(0xffffffffu, ssq, o);
    }
    __shared__ float s1[8], s2[8];
    int w = threadIdx.x >> 5, l = threadIdx.x & 31;
    if (!l) { s1[w] = sum; s2[w] = ssq; }
    __syncthreads();
    if (threadIdx.x == 0) {
        float a = 0.f, b = 0.f;
        #pragma unroll
        for (int i = 0; i < 8; i++) { a += s1[i]; b += s2[i]; }
        s1[0] = a; s2[0] = b;
    }
    __syncthreads();
    float mu   = s1[0] * (1.0f / KDIM);
    float var  = s2[0] * (1.0f / KDIM) - mu * mu;
    float rstd = rsqrtf(var + LN_EPS);

    if (s == 0) {
        // this row's batch: zero the final shifted row (b*SEQ + SEQ-1)
        float4* d = (float4*)(g_shifted + ((size_t)row + SEQ - 1) * KDIM);
        d[threadIdx.x] = make_float4(0.f, 0.f, 0.f, 0.f);
    } else {
        float4 g4 = ((const float4*)gam)[threadIdx.x];
        float4 b4 = ((const float4*)bet)[threadIdx.x];
        float4 o;
        o.x = (v.x - mu) * rstd * g4.x + b4.x;
        o.y = (v.y - mu) * rstd * g4.y + b4.y;
        o.z = (v.z - mu) * rstd * g4.z + b4.z;
        o.w = (v.w - mu) * rstd * g4.w + b4.w;
        float4* d = (float4*)(g_shifted + (size_t)(row - 1) * KDIM);
        d[threadIdx.x] = o;
    }
}

// ---------------- kernel 2: SGEMM  C[M,N] = A[M,K] @ W[N,K]^T ----------------
// 128x128 block tile, BK=8, 256 threads, 8x8 per thread, register prefetch.
// mode 0: A = arg, C = arg (base_out).  mode 1: A = g_shifted, C = g_V.
__global__ __launch_bounds__(256) void sgemm_nt(
    const float* __restrict__ Ain, const float* __restrict__ W,
    float* __restrict__ Cin, int mode)
{
    const float* A = Ain;
    float* Cm = Cin;
    if (mode == 1) { A = g_shifted; Cm = g_V; }

    __shared__ float As[8][128];
    __shared__ float Ws[8][128];

    int tid  = threadIdx.x;
    int lrow = tid >> 1;            // 0..127
    int lk4  = (tid & 1) << 2;      // 0 or 4
    int tx   = tid & 15;
    int ty   = tid >> 4;

    int mbase = blockIdx.y * 128;
    int nbase = blockIdx.x * 128;

    const float* Aptr = A + (size_t)(mbase + lrow) * KDIM + lk4;
    const float* Wptr = W + (size_t)(nbase + lrow) * KDIM + lk4;

    float acc[8][8];
    #pragma unroll
    for (int i = 0; i < 8; i++)
        #pragma unroll
        for (int j = 0; j < 8; j++) acc[i][j] = 0.f;

    float4 a4 = *(const float4*)(Aptr);
    float4 w4 = *(const float4*)(Wptr);

    for (int k0 = 0; k0 < KDIM; k0 += 8) {
        __syncthreads();
        As[lk4 + 0][lrow] = a4.x; As[lk4 + 1][lrow] = a4.y;
        As[lk4 + 2][lrow] = a4.z; As[lk4 + 3][lrow] = a4.w;
        Ws[lk4 + 0][lrow] = w4.x; Ws[lk4 + 1][lrow] = w4.y;
        Ws[lk4 + 2][lrow] = w4.z; Ws[lk4 + 3][lrow] = w4.w;
        __syncthreads();

        if (k0 + 8 < KDIM) {                 // prefetch next global tile
            a4 = *(const float4*)(Aptr + k0 + 8);
            w4 = *(const float4*)(Wptr + k0 + 8);
        }

        #pragma unroll
        for (int kk = 0; kk < 8; kk++) {
            float4 a0 = *(const float4*)&As[kk][ty * 4];
            float4 a1 = *(const float4*)&As[kk][64 + ty * 4];
            float4 b0 = *(const float4*)&Ws[kk][tx * 4];
            float4 b1 = *(const float4*)&Ws[kk][64 + tx * 4];
            float ar[8] = {a0.x, a0.y, a0.z, a0.w, a1.x, a1.y, a1.z, a1.w};
            float br[8] = {b0.x, b0.y, b0.z, b0.w, b1.x, b1.y, b1.z, b1.w};
            #pragma unroll
            for (int i = 0; i < 8; i++)
                #pragma unroll
                for (int j = 0; j < 8; j++)
                    acc[i][j] += ar[i] * br[j];
        }
    }

    #pragma unroll
    for (int i = 0; i < 8; i++) {
        int row = mbase + ((i < 4) ? (ty * 4 + i) : (64 + ty * 4 + i - 4));
        float* cp = Cm + (size_t)row * HDIM + nbase;
        *(float4*)(cp + tx * 4)      = make_float4(acc[i][0], acc[i][1], acc[i][2], acc[i][3]);
        *(float4*)(cp + 64 + tx * 4) = make_float4(acc[i][4], acc[i][5], acc[i][6], acc[i][7]);
    }
}

// ---------------- kernel 3: fused proj_in / proj_err ----------------
// proj_in [row,r] = sum_k x[row,k] * init_B[r,k]
// proj_err[row,r] = sum_h V[row,h] * init_A[h,r]
__global__ __launch_bounds__(256) void proj_kernel(
    const float* __restrict__ x,
    const float* __restrict__ iA,   // [K,R]  (H==K)
    const float* __restrict__ iB)   // [R,K]
{
    int row = blockIdx.x;
    const float* zr = x   + (size_t)row * KDIM;
    const float* vr = g_V + (size_t)row * KDIM;

    float aI[RANK], aE[RANK];
    #pragma unroll
    for (int r = 0; r < RANK; r++) { aI[r] = 0.f; aE[r] = 0.f; }

    #pragma unroll
    for (int t = 0; t < 4; t++) {
        int k = threadIdx.x + t * 256;
        float zv = zr[k];
        float vv = vr[k];
        const float4* Ak = (const float4*)(iA + (size_t)k * RANK);
        float4 a0 = Ak[0], a1 = Ak[1], a2 = Ak[2], a3 = Ak[3];
        aE[0]  += vv * a0.x; aE[1]  += vv * a0.y; aE[2]  += vv * a0.z; aE[3]  += vv * a0.w;
        aE[4]  += vv * a1.x; aE[5]  += vv * a1.y; aE[6]  += vv * a1.z; aE[7]  += vv * a1.w;
        aE[8]  += vv * a2.x; aE[9]  += vv * a2.y; aE[10] += vv * a2.z; aE[11] += vv * a2.w;
        aE[12] += vv * a3.x; aE[13] += vv * a3.y; aE[14] += vv * a3.z; aE[15] += vv * a3.w;
        #pragma unroll
        for (int r = 0; r < RANK; r++) aI[r] += zv * iB[r * KDIM + k];
    }

    #pragma unroll
    for (int r = 0; r < RANK; r++) {
        #pragma unroll
        for (int o = 16; o; o >>= 1) {
            aI[r] += __shfl_xor_sync(0xffffffffu, aI[r], o);
            aE[r] += __shfl_xor_sync(0xffffffffu, aE[r], o);
        }
    }
    __shared__ float sI[8][RANK], sE[8][RANK];
    int w = threadIdx.x >> 5, l = threadIdx.x & 31;
    if (!l) {
        #pragma unroll
        for (int r = 0; r < RANK; r++) { sI[w][r] = aI[r]; sE[w][r] = aE[r]; }
    }
    __syncthreads();
    if (threadIdx.x < RANK) {
        float si = 0.f, se = 0.f;
        #pragma unroll
        for (int i = 0; i < 8; i++) { si += sI[i][threadIdx.x]; se += sE[i][threadIdx.x]; }
        g_proj_in [(size_t)row * RANK + threadIdx.x] = si;
        g_proj_err[(size_t)row * RANK + threadIdx.x] = se;
    }
}

// ---------------- kernel 4: dA / dB ----------------
// mode 0: dA[c,h,r] = sum_i V[c,i,h]   * proj_in[c,i,r]
// mode 1: dB[c,r,k] = sum_i proj_err[c,i,r] * x[c,i,k]
__global__ __launch_bounds__(128) void delta_kernel(const float* __restrict__ x)
{
    int c = blockIdx.x, part = blockIdx.y, mode = blockIdx.z;
    __shared__ float sp[CHUNK][RANK];   // 16 KB
    const float* P = (mode == 0 ? g_proj_in : g_proj_err) + (size_t)c * CHUNK * RANK;
    for (int i = threadIdx.x; i < CHUNK * RANK; i += 128)
        sp[i >> 4][i & 15] = P[i];
    __syncthreads();

    int col = part * 128 + threadIdx.x;
    const float* src = (mode == 0 ? g_V : x) + (size_t)c * CHUNK * KDIM + col;

    float acc[RANK];
    #pragma unroll
    for (int r = 0; r < RANK; r++) acc[r] = 0.f;

    #pragma unroll 4
    for (int i = 0; i < CHUNK; i++) {
        float v = src[(size_t)i * KDIM];
        #pragma unroll
        for (int r = 0; r < RANK; r++) acc[r] += v * sp[i][r];
    }

    if (mode == 0) {
        float* d = g_dA + (size_t)c * HDIM * RANK + (size_t)col * RANK;
        #pragma unroll
        for (int r = 0; r < RANK; r += 4)
            *(float4*)(d + r) = make_float4(acc[r], acc[r+1], acc[r+2], acc[r+3]);
    } else {
        float* d = g_dB + (size_t)c * RANK * KDIM + col;
        #pragma unroll
        for (int r = 0; r < RANK; r++) d[(size_t)r * KDIM] = acc[r];
    }
}

// ---------------- kernel 5: exclusive cumsum over chunks (in place) ----------------
__global__ __launch_bounds__(256) void cumsum_kernel()
{
    int e = blockIdx.x * 256 + threadIdx.x;    // 0..16383
    int b = blockIdx.y;                        // batch
    float* base = blockIdx.z ? g_dB : g_dA;
    float run = 0.f;
    #pragma unroll
    for (int j = 0; j < NCH; j++) {
        size_t off = ((size_t)(b * NCH + j)) * (HDIM * RANK) + e;
        float t = base[off];
        base[off] = run;
        run += t;
    }
}

// ---------------- kernel 6: joint norm clip coefficient per chunk ----------------
__global__ __launch_bounds__(256) void clip_kernel()
{
    int c = blockIdx.x;
    const float* A = g_dA + (size_t)c * (HDIM * RANK);
    const float* B = g_dB + (size_t)c * (RANK * KDIM);
    float s = 0.f;
    for (int i = threadIdx.x; i < HDIM * RANK; i += 256) {
        float a = A[i]; s += a * a;
        float b = B[i]; s += b * b;
    }
    #pragma unroll
    for (int o = 16; o; o >>= 1) s += __shfl_xor_sync(0xffffffffu, s, o);
    __shared__ float sm[8];
    int w = threadIdx.x >> 5, l = threadIdx.x & 31;
    if (!l) sm[w] = s;
    __syncthreads();
    if (threadIdx.x == 0) {
        float t = 0.f;
        #pragma unroll
        for (int i = 0; i < 8; i++) t += sm[i];
        float norm = LRC * sqrtf(t);
        g_coef[c] = fminf(1.0f, CLIP / (norm + 1e-6f));
    }
}

// ---------------- kernel 7: effective weights ----------------
__global__ __launch_bounds__(256) void eff_kernel(
    const float* __restrict__ iA, const float* __restrict__ iB)
{
    int c = blockIdx.y;
    int i = blockIdx.x * 256 + threadIdx.x;    // 0..16383
    float s = LRC * g_coef[c];
    size_t off = (size_t)c * (HDIM * RANK) + i;
    g_Aeff[off] = iA[i] - s * g_dA[off];
    g_Beff[off] = iB[i] - s * g_dB[off];
}

// ---------------- kernel 8: fused mid + lora epilogue ----------------
// mid[r] = sum_k x[row,k]*B_eff[c,r,k];  out[row,h] += SCALE * sum_r mid[r]*A_eff[c,h,r]
__global__ __launch_bounds__(256) void lora_kernel(
    const float* __restrict__ x, float* __restrict__ out)
{
    int row = blockIdx.x;
    int c = row >> 8;
    const float* zr = x + (size_t)row * KDIM;
    const float* Be = g_Beff + (size_t)c * (RANK * KDIM);

    float acc[RANK];
    #pragma unroll
    for (int r = 0; r < RANK; r++) acc[r] = 0.f;

    #pragma unroll
    for (int t = 0; t < 4; t++) {
        int k = threadIdx.x + t * 256;
        float zv = zr[k];
        #pragma unroll
        for (int r = 0; r < RANK; r++) acc[r] += zv * Be[r * KDIM + k];
    }
    #pragma unroll
    for (int r = 0; r < RANK; r++) {
        #pragma unroll
        for (int o = 16; o; o >>= 1)
            acc[r] += __shfl_xor_sync(0xffffffffu, acc[r], o);
    }
    __shared__ float sR[8][RANK];
    __shared__ float s_mid[RANK];
    int w = threadIdx.x >> 5, l = threadIdx.x & 31;
    if (!l) {
        #pragma unroll
        for (int r = 0; r < RANK; r++) sR[w][r] = acc[r];
    }
    __syncthreads();
    if (threadIdx.x < RANK) {
        float t = 0.f;
        #pragma unroll
        for (int i = 0; i < 8; i++) t += sR[i][threadIdx.x];
        s_mid[threadIdx.x] = t;
    }
    __syncthreads();

    const float* Ae = g_Aeff + (size_t)c * (HDIM * RANK);
    float* orow = out + (size_t)row * HDIM;
    #pragma unroll
    for (int q = 0; q < 4; q++) {
        int h = q * 256 + threadIdx.x;
        const float4* Ah = (const float4*)(Ae + (size_t)h * RANK);
        float4 a0 = Ah[0], a1 = Ah[1], a2 = Ah[2], a3 = Ah[3];
        float v = s_mid[0]  * a0.x + s_mid[1]  * a0.y + s_mid[2]  * a0.z + s_mid[3]  * a0.w
                + s_mid[4]  * a1.x + s_mid[5]  * a1.y + s_mid[6]  * a1.z + s_mid[7]  * a1.w
                + s_mid[8]  * a2.x + s_mid[9]  * a2.y + s_mid[10] * a2.z + s_mid[11] * a2.w
                + s_mid[12] * a3.x + s_mid[13] * a3.y + s_mid[14] * a3.z + s_mid[15] * a3.w;
        orow[h] += SCALE * v;
    }
}

// ---------------- launch ----------------
extern "C" void kernel_launch(void* const* d_in, const int* in_sizes, int n_in,
                              void* d_out, int out_size)
{
    const float* x   = (const float*)d_in[0];
    const float* Wb  = (const float*)d_in[1];
    const float* iA  = (const float*)d_in[2];
    const float* iB  = (const float*)d_in[3];
    const float* gam = (const float*)d_in[4];
    const float* bet = (const float*)d_in[5];
    const float* Wp  = (const float*)d_in[6];
    float* out = (float*)d_out;

    // 1. LayerNorm + shift -> g_shifted
    ln_shift_kernel<<<M_TOT, 256>>>(x, gam, bet);

    // 2. base_out = x @ Wb^T -> d_out
    dim3 gg(HDIM / 128, M_TOT / 128);
    sgemm_nt<<<gg, 256>>>(x, Wb, out, 0);

    // 3. V = shifted @ Wp^T -> g_V
    sgemm_nt<<<gg, 256>>>(nullptr, Wp, nullptr, 1);

    // 4. proj_in / proj_err
    proj_kernel<<<M_TOT, 256>>>(x, iA, iB);

    // 5. dA / dB
    delta_kernel<<<dim3(NBC, KDIM / 128, 2), 128>>>(x);

    // 6. exclusive cumsum over chunks (in place)
    cumsum_kernel<<<dim3((HDIM * RANK) / 256, NBATCH, 2), 256>>>();

    // 7. clip coefficient
    clip_kernel<<<NBC, 256>>>();

    // 8. effective weights
    eff_kernel<<<dim3((HDIM * RANK) / 256, NBC), 256>>>(iA, iB);

    // 9. mid + lora, accumulate into out
    lora_kernel<<<M_TOT, 256>>>(x, out);
}

// round 4
// speedup vs baseline: 1.7606x; 1.7606x over previous
#include <cuda_runtime.h>
#include <math.h>
#include <stdint.h>

// ---------------- problem constants ----------------
#define M_TOT   16384      // B*S
#define SEQ     8192
#define KDIM    1024
#define HDIM    1024
#define RANK    16
#define CHUNK   256
#define NCH     32         // chunks per batch
#define NBATCH  2
#define NBC     64         // total chunks
#define LRC     0.02f      // TTT_LR * SCALING
#define SCALE   2.0f       // LORA_ALPHA / LORA_RANK
#define CLIP    1.0f
#define LN_EPS  1e-5f

// ---------------- GEMM tiling ----------------
#define BM 128
#define BN 128
#define BK 32
#define LDA 36                                  // padded row stride (floats)
#define STAGE_FLOATS ((BM + BN) * LDA)          // 9216
#define SMEM_GEMM (2 * STAGE_FLOATS * 4)        // 73728 bytes
#define NIT (KDIM / BK)                         // 32

// ---------------- device scratch ----------------
__device__ __align__(128) float g_shifted[M_TOT * KDIM];
__device__ __align__(128) float g_V      [M_TOT * KDIM];
__device__ __align__(128) float g_proj_in [NBC * CHUNK * RANK];
__device__ __align__(128) float g_proj_err[NBC * CHUNK * RANK];
__device__ __align__(128) float g_dA  [NBC * HDIM * RANK];
__device__ __align__(128) float g_dB  [NBC * RANK * KDIM];
__device__ __align__(128) float g_Aeff[NBC * HDIM * RANK];
__device__ __align__(128) float g_Beff[NBC * RANK * KDIM];
__device__ __align__(128) float g_coef[NBC];

// ---------------- helpers ----------------
__device__ __forceinline__ uint32_t smem_u32(const void* p) {
    uint32_t a;
    asm("{ .reg .u64 t; cvta.to.shared.u64 t, %1; cvt.u32.u64 %0, t; }" : "=r"(a) : "l"(p));
    return a;
}
__device__ __forceinline__ void cp16(uint32_t d, const void* s) {
    asm volatile("cp.async.cg.shared.global [%0], [%1], 16;" :: "r"(d), "l"(s));
}

// ---------------- kernel 1: LayerNorm + left shift ----------------
__global__ __launch_bounds__(256) void ln_shift_kernel(
    const float* __restrict__ x,
    const float* __restrict__ gam,
    const float* __restrict__ bet)
{
    int row = blockIdx.x;
    int s   = row & (SEQ - 1);
    const float4* xr = (const float4*)(x + (size_t)row * KDIM);
    float4 v = xr[threadIdx.x];

    float sum = v.x + v.y + v.z + v.w;
    float ssq = v.x*v.x + v.y*v.y + v.z*v.z + v.w*v.w;
    #pragma unroll
    for (int o = 16; o; o >>= 1) {
        sum += __shfl_xor_sync(0xffffffffu, sum, o);
        ssq += __shfl_xor_sync(0xffffffffu, ssq, o);
    }
    __shared__ float s1[8], s2[8];
    int w = threadIdx.x >> 5, l = threadIdx.x & 31;
    if (!l) { s1[w] = sum; s2[w] = ssq; }
    __syncthreads();
    if (threadIdx.x == 0) {
        float a = 0.f, b = 0.f;
        #pragma unroll
        for (int i = 0; i < 8; i++) { a += s1[i]; b += s2[i]; }
        s1[0] = a; s2[0] = b;
    }
    __syncthreads();
    float mu   = s1[0] * (1.0f / KDIM);
    float var  = s2[0] * (1.0f / KDIM) - mu * mu;
    float rstd = rsqrtf(var + LN_EPS);

    if (s == 0) {
        float4* d = (float4*)(g_shifted + ((size_t)row + SEQ - 1) * KDIM);
        d[threadIdx.x] = make_float4(0.f, 0.f, 0.f, 0.f);
    } else {
        float4 g4 = ((const float4*)gam)[threadIdx.x];
        float4 b4 = ((const float4*)bet)[threadIdx.x];
        float4 o;
        o.x = (v.x - mu) * rstd * g4.x + b4.x;
        o.y = (v.y - mu) * rstd * g4.y + b4.y;
        o.z = (v.z - mu) * rstd * g4.z + b4.z;
        o.w = (v.w - mu) * rstd * g4.w + b4.w;
        float4* d = (float4*)(g_shifted + (size_t)(row - 1) * KDIM);
        d[threadIdx.x] = o;
    }
}

// ---------------- kernel 2: TF32 mma.sync GEMM  C[M,N] = A[M,K] @ W[N,K]^T ----------------
extern __shared__ float sm_gemm[];

__device__ __forceinline__ void gemm_load_stage(
    float* dst, const float* Ab, const float* Wb, int k0, int tid)
{
    uint32_t sa = smem_u32(dst);
    uint32_t sw = sa + BM * LDA * 4;
    #pragma unroll
    for (int i = 0; i < 4; i++) {       // A: 128 rows x 8 chunks = 1024
        int idx = tid + i * 256;
        int row = idx >> 3, seg = idx & 7;
        cp16(sa + row * (LDA * 4) + seg * 16,
             Ab + (size_t)row * KDIM + k0 + seg * 4);
    }
    #pragma unroll
    for (int i = 0; i < 4; i++) {       // W: 128 rows x 8 chunks = 1024
        int idx = tid + i * 256;
        int row = idx >> 3, seg = idx & 7;
        cp16(sw + row * (LDA * 4) + seg * 16,
             Wb + (size_t)row * KDIM + k0 + seg * 4);
    }
    asm volatile("cp.async.commit_group;" ::: "memory");
}

__global__ __launch_bounds__(256) void gemm_tf32(
    const float* __restrict__ Ain, const float* __restrict__ W,
    float* __restrict__ Cin, int mode)
{
    const float* A = Ain;
    float* C = Cin;
    if (mode == 1) { A = g_shifted; C = g_V; }

    int tid  = threadIdx.x;
    int wid  = tid >> 5;
    int lane = tid & 31;
    int grp  = lane >> 2;       // 0..7
    int tig  = lane & 3;        // 0..3
    int wm   = wid & 1;         // m warp (0..1) -> offset 64
    int wn   = wid >> 1;        // n warp (0..3) -> offset 32

    int mbase = blockIdx.y * BM;
    int nbase = blockIdx.x * BN;
    const float* Ab = A + (size_t)mbase * KDIM;
    const float* Wb = W + (size_t)nbase * KDIM;

    float4 c[4][4];
    #pragma unroll
    for (int i = 0; i < 4; i++)
        #pragma unroll
        for (int j = 0; j < 4; j++) c[i][j] = make_float4(0.f, 0.f, 0.f, 0.f);

    gemm_load_stage(sm_gemm, Ab, Wb, 0, tid);

    for (int it = 0; it < NIT; it++) {
        asm volatile("cp.async.wait_group 0;" ::: "memory");
        __syncthreads();
        if (it + 1 < NIT)
            gemm_load_stage(sm_gemm + ((it + 1) & 1) * STAGE_FLOATS,
                            Ab, Wb, (it + 1) * BK, tid);

        const float* Abuf = sm_gemm + (it & 1) * STAGE_FLOATS;
        const float* Wbuf = Abuf + BM * LDA;

        #pragma unroll
        for (int k8 = 0; k8 < 4; k8++) {
            uint32_t a[4][4], b[4][2];
            #pragma unroll
            for (int mf = 0; mf < 4; mf++) {
                const float* p = Abuf + (wm * 64 + mf * 16 + grp) * LDA + k8 * 8 + tig;
                a[mf][0] = __float_as_uint(p[0]);
                a[mf][1] = __float_as_uint(p[8 * LDA]);
                a[mf][2] = __float_as_uint(p[4]);
                a[mf][3] = __float_as_uint(p[8 * LDA + 4]);
            }
            #pragma unroll
            for (int nf = 0; nf < 4; nf++) {
                const float* p = Wbuf + (wn * 32 + nf * 8 + grp) * LDA + k8 * 8 + tig;
                b[nf][0] = __float_as_uint(p[0]);
                b[nf][1] = __float_as_uint(p[4]);
            }
            #pragma unroll
            for (int mf = 0; mf < 4; mf++)
                #pragma unroll
                for (int nf = 0; nf < 4; nf++) {
                    asm volatile(
                        "mma.sync.aligned.m16n8k8.row.col.f32.tf32.tf32.f32 "
                        "{%0,%1,%2,%3}, {%4,%5,%6,%7}, {%8,%9}, {%0,%1,%2,%3};"
                        : "+f"(c[mf][nf].x), "+f"(c[mf][nf].y),
                          "+f"(c[mf][nf].z), "+f"(c[mf][nf].w)
                        : "r"(a[mf][0]), "r"(a[mf][1]), "r"(a[mf][2]), "r"(a[mf][3]),
                          "r"(b[nf][0]), "r"(b[nf][1]));
                }
        }
        __syncthreads();
    }

    // epilogue: direct float2 stores
    #pragma unroll
    for (int mf = 0; mf < 4; mf++) {
        int row0 = mbase + wm * 64 + mf * 16 + grp;
        #pragma unroll
        for (int nf = 0; nf < 4; nf++) {
            int col = nbase + wn * 32 + nf * 8 + 2 * tig;
            *(float2*)(C + (size_t)row0 * HDIM + col) = make_float2(c[mf][nf].x, c[mf][nf].y);
            *(float2*)(C + (size_t)(row0 + 8) * HDIM + col) = make_float2(c[mf][nf].z, c[mf][nf].w);
        }
    }
}

// ---------------- kernel 3: fused proj_in / proj_err ----------------
__global__ __launch_bounds__(256) void proj_kernel(
    const float* __restrict__ x,
    const float* __restrict__ iA,   // [K,R]
    const float* __restrict__ iB)   // [R,K]
{
    int row = blockIdx.x;
    int k = threadIdx.x * 4;
    const float4 zv = *(const float4*)(x   + (size_t)row * KDIM + k);
    const float4 vv = *(const float4*)(g_V + (size_t)row * KDIM + k);

    float aI[RANK], aE[RANK];
    #pragma unroll
    for (int r = 0; r < RANK; r++) {
        float4 b = *(const float4*)(iB + (size_t)r * KDIM + k);
        aI[r] = zv.x * b.x + zv.y * b.y + zv.z * b.z + zv.w * b.w;
        aE[r] = 0.f;
    }
    float vc[4] = {vv.x, vv.y, vv.z, vv.w};
    #pragma unroll
    for (int j = 0; j < 4; j++) {
        const float4* Ak = (const float4*)(iA + (size_t)(k + j) * RANK);
        float4 a0 = Ak[0], a1 = Ak[1], a2 = Ak[2], a3 = Ak[3];
        float v = vc[j];
        aE[0]  += v * a0.x; aE[1]  += v * a0.y; aE[2]  += v * a0.z; aE[3]  += v * a0.w;
        aE[4]  += v * a1.x; aE[5]  += v * a1.y; aE[6]  += v * a1.z; aE[7]  += v * a1.w;
        aE[8]  += v * a2.x; aE[9]  += v * a2.y; aE[10] += v * a2.z; aE[11] += v * a2.w;
        aE[12] += v * a3.x; aE[13] += v * a3.y; aE[14] += v * a3.z; aE[15] += v * a3.w;
    }

    #pragma unroll
    for (int r = 0; r < RANK; r++) {
        #pragma unroll
        for (int o = 16; o; o >>= 1) {
            aI[r] += __shfl_xor_sync(0xffffffffu, aI[r], o);
            aE[r] += __shfl_xor_sync(0xffffffffu, aE[r], o);
        }
    }
    __shared__ float sI[8][RANK], sE[8][RANK];
    int w = threadIdx.x >> 5, l = threadIdx.x & 31;
    if (!l) {
        #pragma unroll
        for (int r = 0; r < RANK; r++) { sI[w][r] = aI[r]; sE[w][r] = aE[r]; }
    }
    __syncthreads();
    if (threadIdx.x < RANK) {
        float si = 0.f, se = 0.f;
        #pragma unroll
        for (int i = 0; i < 8; i++) { si += sI[i][threadIdx.x]; se += sE[i][threadIdx.x]; }
        g_proj_in [(size_t)row * RANK + threadIdx.x] = si;
        g_proj_err[(size_t)row * RANK + threadIdx.x] = se;
    }
}

// ---------------- kernel 4: dA / dB ----------------
__global__ __launch_bounds__(128) void delta_kernel(const float* __restrict__ x)
{
    int c = blockIdx.x, part = blockIdx.y, mode = blockIdx.z;
    __shared__ float sp[CHUNK][RANK];
    const float* P = (mode == 0 ? g_proj_in : g_proj_err) + (size_t)c * CHUNK * RANK;
    for (int i = threadIdx.x; i < CHUNK * RANK; i += 128)
        sp[i >> 4][i & 15] = P[i];
    __syncthreads();

    int col = part * 128 + threadIdx.x;
    const float* src = (mode == 0 ? g_V : x) + (size_t)c * CHUNK * KDIM + col;

    float acc[RANK];
    #pragma unroll
    for (int r = 0; r < RANK; r++) acc[r] = 0.f;

    #pragma unroll 4
    for (int i = 0; i < CHUNK; i++) {
        float v = src[(size_t)i * KDIM];
        #pragma unroll
        for (int r = 0; r < RANK; r++) acc[r] += v * sp[i][r];
    }

    if (mode == 0) {
        float* d = g_dA + (size_t)c * HDIM * RANK + (size_t)col * RANK;
        #pragma unroll
        for (int r = 0; r < RANK; r += 4)
            *(float4*)(d + r) = make_float4(acc[r], acc[r+1], acc[r+2], acc[r+3]);
    } else {
        float* d = g_dB + (size_t)c * RANK * KDIM + col;
        #pragma unroll
        for (int r = 0; r < RANK; r++) d[(size_t)r * KDIM] = acc[r];
    }
}

// ---------------- kernel 5: exclusive cumsum over chunks ----------------
__global__ __launch_bounds__(256) void cumsum_kernel()
{
    int e = blockIdx.x * 256 + threadIdx.x;
    int b = blockIdx.y;
    float* base = blockIdx.z ? g_dB : g_dA;
    float run = 0.f;
    #pragma unroll
    for (int j = 0; j < NCH; j++) {
        size_t off = ((size_t)(b * NCH + j)) * (HDIM * RANK) + e;
        float t = base[off];
        base[off] = run;
        run += t;
    }
}

// ---------------- kernel 6: joint norm clip coefficient ----------------
__global__ __launch_bounds__(256) void clip_kernel()
{
    int c = blockIdx.x;
    const float* A = g_dA + (size_t)c * (HDIM * RANK);
    const float* B = g_dB + (size_t)c * (RANK * KDIM);
    float s = 0.f;
    for (int i = threadIdx.x; i < HDIM * RANK; i += 256) {
        float a = A[i]; s += a * a;
        float b = B[i]; s += b * b;
    }
    #pragma unroll
    for (int o = 16; o; o >>= 1) s += __shfl_xor_sync(0xffffffffu, s, o);
    __shared__ float sm[8];
    int w = threadIdx.x >> 5, l = threadIdx.x & 31;
    if (!l) sm[w] = s;
    __syncthreads();
    if (threadIdx.x == 0) {
        float t = 0.f;
        #pragma unroll
        for (int i = 0; i < 8; i++) t += sm[i];
        float norm = LRC * sqrtf(t);
        g_coef[c] = fminf(1.0f, CLIP / (norm + 1e-6f));
    }
}

// ---------------- kernel 7: effective weights ----------------
__global__ __launch_bounds__(256) void eff_kernel(
    const float* __restrict__ iA, const float* __restrict__ iB)
{
    int c = blockIdx.y;
    int i = blockIdx.x * 256 + threadIdx.x;
    float s = LRC * g_coef[c];
    size_t off = (size_t)c * (HDIM * RANK) + i;
    g_Aeff[off] = iA[i] - s * g_dA[off];
    g_Beff[off] = iB[i] - s * g_dB[off];
}

// ---------------- kernel 8: fused mid + lora epilogue ----------------
__global__ __launch_bounds__(256) void lora_kernel(
    const float* __restrict__ x, float* __restrict__ out)
{
    int row = blockIdx.x;
    int c = row >> 8;
    const float* zr = x + (size_t)row * KDIM;
    const float* Be = g_Beff + (size_t)c * (RANK * KDIM);

    int k = threadIdx.x * 4;
    const float4 zv = *(const float4*)(zr + k);
    float acc[RANK];
    #pragma unroll
    for (int r = 0; r < RANK; r++) {
        float4 b = *(const float4*)(Be + (size_t)r * KDIM + k);
        acc[r] = zv.x * b.x + zv.y * b.y + zv.z * b.z + zv.w * b.w;
    }
    #pragma unroll
    for (int r = 0; r < RANK; r++) {
        #pragma unroll
        for (int o = 16; o; o >>= 1)
            acc[r] += __shfl_xor_sync(0xffffffffu, acc[r], o);
    }
    __shared__ float sR[8][RANK];
    __shared__ float s_mid[RANK];
    int w = threadIdx.x >> 5, l = threadIdx.x & 31;
    if (!l) {
        #pragma unroll
        for (int r = 0; r < RANK; r++) sR[w][r] = acc[r];
    }
    __syncthreads();
    if (threadIdx.x < RANK) {
        float t = 0.f;
        #pragma unroll
        for (int i = 0; i < 8; i++) t += sR[i][threadIdx.x];
        s_mid[threadIdx.x] = t;
    }
    __syncthreads();

    const float* Ae = g_Aeff + (size_t)c * (HDIM * RANK);
    float* orow = out + (size_t)row * HDIM;
    #pragma unroll
    for (int q = 0; q < 4; q++) {
        int h = q * 256 + threadIdx.x;
        const float4* Ah = (const float4*)(Ae + (size_t)h * RANK);
        float4 a0 = Ah[0], a1 = Ah[1], a2 = Ah[2], a3 = Ah[3];
        float v = s_mid[0]  * a0.x + s_mid[1]  * a0.y + s_mid[2]  * a0.z + s_mid[3]  * a0.w
                + s_mid[4]  * a1.x + s_mid[5]  * a1.y + s_mid[6]  * a1.z + s_mid[7]  * a1.w
                + s_mid[8]  * a2.x + s_mid[9]  * a2.y + s_mid[10] * a2.z + s_mid[11] * a2.w
                + s_mid[12] * a3.x + s_mid[13] * a3.y + s_mid[14] * a3.z + s_mid[15] * a3.w;
        orow[h] += SCALE * v;
    }
}

// ---------------- launch ----------------
extern "C" void kernel_launch(void* const* d_in, const int* in_sizes, int n_in,
                              void* d_out, int out_size)
{
    const float* x   = (const float*)d_in[0];
    const float* Wb  = (const float*)d_in[1];
    const float* iA  = (const float*)d_in[2];
    const float* iB  = (const float*)d_in[3];
    const float* gam = (const float*)d_in[4];
    const float* bet = (const float*)d_in[5];
    const float* Wp  = (const float*)d_in[6];
    float* out = (float*)d_out;

    static int smem_set = 0;
    if (!smem_set) {
        cudaFuncSetAttribute(gemm_tf32, cudaFuncAttributeMaxDynamicSharedMemorySize, SMEM_GEMM);
        smem_set = 1;
    }

    ln_shift_kernel<<<M_TOT, 256>>>(x, gam, bet);

    dim3 gg(HDIM / BN, M_TOT / BM);
    gemm_tf32<<<gg, 256, SMEM_GEMM>>>(x, Wb, out, 0);            // base_out
    gemm_tf32<<<gg, 256, SMEM_GEMM>>>(nullptr, Wp, nullptr, 1);  // V

    proj_kernel<<<M_TOT, 256>>>(x, iA, iB);
    delta_kernel<<<dim3(NBC, KDIM / 128, 2), 128>>>(x);
    cumsum_kernel<<<dim3((HDIM * RANK) / 256, NBATCH, 2), 256>>>();
    clip_kernel<<<NBC, 256>>>();
    eff_kernel<<<dim3((HDIM * RANK) / 256, NBC), 256>>>(iA, iB);
    lora_kernel<<<M_TOT, 256>>>(x, out);
}

// round 5
// speedup vs baseline: 2.7632x; 1.5695x over previous
#include <cuda_runtime.h>
#include <math.h>
#include <stdint.h>

// ---------------- problem constants ----------------
#define M_TOT   16384
#define SEQ     8192
#define KDIM    1024
#define HDIM    1024
#define RANK    16
#define CHUNK   256
#define NCH     32
#define NBATCH  2
#define NBC     64
#define LRC     0.02f
#define SCALE   2.0f
#define CLIP    1.0f
#define LN_EPS  1e-5f

// ---------------- GEMM tiling ----------------
#define BM 128
#define BN 128
#define BK 32
#define LDA 36
#define STAGE_FLOATS ((BM + BN) * LDA)
#define SMEM_GEMM (2 * STAGE_FLOATS * 4)
#define NIT (KDIM / BK)

// proj/mid mma kernels
#define PLDA 36
#define PROJ_STAGE (128 * PLDA)                  // one tile (floats)
#define SMEM_PROJ (2 * 2 * PROJ_STAGE * 4)       // 2 stages x 2 tiles
#define SMEM_MID  (2 * PROJ_STAGE * 4)           // 2 stages x 1 tile

// ---------------- device scratch ----------------
__device__ __align__(128) float g_shifted[M_TOT * KDIM];
__device__ __align__(128) float g_V      [M_TOT * KDIM];
__device__ __align__(128) float g_proj_in [NBC * CHUNK * RANK];
__device__ __align__(128) float g_proj_err[NBC * CHUNK * RANK];
__device__ __align__(128) float g_dA  [NBC * HDIM * RANK];
__device__ __align__(128) float g_dB  [NBC * RANK * KDIM];
__device__ __align__(128) float g_Aeff[NBC * HDIM * RANK];
__device__ __align__(128) float g_Beff[NBC * RANK * KDIM];
__device__ __align__(128) float g_mid [M_TOT * RANK];
__device__ __align__(128) float g_coef[NBC];

// ---------------- helpers ----------------
__device__ __forceinline__ uint32_t smem_u32(const void* p) {
    uint32_t a;
    asm("{ .reg .u64 t; cvta.to.shared.u64 t, %1; cvt.u32.u64 %0, t; }" : "=r"(a) : "l"(p));
    return a;
}
__device__ __forceinline__ void cp16(uint32_t d, const void* s) {
    asm volatile("cp.async.cg.shared.global [%0], [%1], 16;" :: "r"(d), "l"(s));
}
__device__ __forceinline__ void mma_tf32(float4& c, const uint32_t a[4], const uint32_t b[2]) {
    asm volatile(
        "mma.sync.aligned.m16n8k8.row.col.f32.tf32.tf32.f32 "
        "{%0,%1,%2,%3}, {%4,%5,%6,%7}, {%8,%9}, {%0,%1,%2,%3};"
        : "+f"(c.x), "+f"(c.y), "+f"(c.z), "+f"(c.w)
        : "r"(a[0]), "r"(a[1]), "r"(a[2]), "r"(a[3]), "r"(b[0]), "r"(b[1]));
}

// ---------------- kernel 1: LayerNorm + left shift ----------------
__global__ __launch_bounds__(256) void ln_shift_kernel(
    const float* __restrict__ x,
    const float* __restrict__ gam,
    const float* __restrict__ bet)
{
    int row = blockIdx.x;
    int s   = row & (SEQ - 1);
    const float4* xr = (const float4*)(x + (size_t)row * KDIM);
    float4 v = xr[threadIdx.x];

    float sum = v.x + v.y + v.z + v.w;
    float ssq = v.x*v.x + v.y*v.y + v.z*v.z + v.w*v.w;
    #pragma unroll
    for (int o = 16; o; o >>= 1) {
        sum += __shfl_xor_sync(0xffffffffu, sum, o);
        ssq += __shfl_xor_sync(0xffffffffu, ssq, o);
    }
    __shared__ float s1[8], s2[8];
    int w = threadIdx.x >> 5, l = threadIdx.x & 31;
    if (!l) { s1[w] = sum; s2[w] = ssq; }
    __syncthreads();
    if (threadIdx.x == 0) {
        float a = 0.f, b = 0.f;
        #pragma unroll
        for (int i = 0; i < 8; i++) { a += s1[i]; b += s2[i]; }
        s1[0] = a; s2[0] = b;
    }
    __syncthreads();
    float mu   = s1[0] * (1.0f / KDIM);
    float var  = s2[0] * (1.0f / KDIM) - mu * mu;
    float rstd = rsqrtf(var + LN_EPS);

    if (s == 0) {
        float4* d = (float4*)(g_shifted + ((size_t)row + SEQ - 1) * KDIM);
        d[threadIdx.x] = make_float4(0.f, 0.f, 0.f, 0.f);
    } else {
        float4 g4 = ((const float4*)gam)[threadIdx.x];
        float4 b4 = ((const float4*)bet)[threadIdx.x];
        float4 o;
        o.x = (v.x - mu) * rstd * g4.x + b4.x;
        o.y = (v.y - mu) * rstd * g4.y + b4.y;
        o.z = (v.z - mu) * rstd * g4.z + b4.z;
        o.w = (v.w - mu) * rstd * g4.w + b4.w;
        float4* d = (float4*)(g_shifted + (size_t)(row - 1) * KDIM);
        d[threadIdx.x] = o;
    }
}

// ---------------- kernel 2: TF32 mma.sync GEMM  C = A @ W^T ----------------
extern __shared__ float sm_dyn[];

__device__ __forceinline__ void gemm_load_stage(
    float* dst, const float* Ab, const float* Wb, int k0, int tid)
{
    uint32_t sa = smem_u32(dst);
    uint32_t sw = sa + BM * LDA * 4;
    #pragma unroll
    for (int i = 0; i < 4; i++) {
        int idx = tid + i * 256;
        int row = idx >> 3, seg = idx & 7;
        cp16(sa + row * (LDA * 4) + seg * 16, Ab + (size_t)row * KDIM + k0 + seg * 4);
    }
    #pragma unroll
    for (int i = 0; i < 4; i++) {
        int idx = tid + i * 256;
        int row = idx >> 3, seg = idx & 7;
        cp16(sw + row * (LDA * 4) + seg * 16, Wb + (size_t)row * KDIM + k0 + seg * 4);
    }
    asm volatile("cp.async.commit_group;" ::: "memory");
}

__global__ __launch_bounds__(256, 2) void gemm_tf32(
    const float* __restrict__ Ain, const float* __restrict__ W,
    float* __restrict__ Cin, int mode)
{
    const float* A = Ain;
    float* C = Cin;
    if (mode == 1) { A = g_shifted; C = g_V; }

    int tid  = threadIdx.x;
    int wid  = tid >> 5;
    int lane = tid & 31;
    int grp  = lane >> 2;
    int tig  = lane & 3;
    int wm   = wid & 1;
    int wn   = wid >> 1;

    int mbase = blockIdx.y * BM;
    int nbase = blockIdx.x * BN;
    const float* Ab = A + (size_t)mbase * KDIM;
    const float* Wb = W + (size_t)nbase * KDIM;

    float4 c[4][4];
    #pragma unroll
    for (int i = 0; i < 4; i++)
        #pragma unroll
        for (int j = 0; j < 4; j++) c[i][j] = make_float4(0.f, 0.f, 0.f, 0.f);

    gemm_load_stage(sm_dyn, Ab, Wb, 0, tid);

    for (int it = 0; it < NIT; it++) {
        asm volatile("cp.async.wait_group 0;" ::: "memory");
        __syncthreads();
        if (it + 1 < NIT)
            gemm_load_stage(sm_dyn + ((it + 1) & 1) * STAGE_FLOATS, Ab, Wb, (it + 1) * BK, tid);

        const float* Abuf = sm_dyn + (it & 1) * STAGE_FLOATS;
        const float* Wbuf = Abuf + BM * LDA;

        #pragma unroll
        for (int k8 = 0; k8 < 4; k8++) {
            uint32_t a[4][4], b[4][2];
            #pragma unroll
            for (int mf = 0; mf < 4; mf++) {
                const float* p = Abuf + (wm * 64 + mf * 16 + grp) * LDA + k8 * 8 + tig;
                a[mf][0] = __float_as_uint(p[0]);
                a[mf][1] = __float_as_uint(p[8 * LDA]);
                a[mf][2] = __float_as_uint(p[4]);
                a[mf][3] = __float_as_uint(p[8 * LDA + 4]);
            }
            #pragma unroll
            for (int nf = 0; nf < 4; nf++) {
                const float* p = Wbuf + (wn * 32 + nf * 8 + grp) * LDA + k8 * 8 + tig;
                b[nf][0] = __float_as_uint(p[0]);
                b[nf][1] = __float_as_uint(p[4]);
            }
            #pragma unroll
            for (int mf = 0; mf < 4; mf++)
                #pragma unroll
                for (int nf = 0; nf < 4; nf++)
                    mma_tf32(c[mf][nf], a[mf], b[nf]);
        }
        __syncthreads();
    }

    #pragma unroll
    for (int mf = 0; mf < 4; mf++) {
        int row0 = mbase + wm * 64 + mf * 16 + grp;
        #pragma unroll
        for (int nf = 0; nf < 4; nf++) {
            int col = nbase + wn * 32 + nf * 8 + 2 * tig;
            *(float2*)(C + (size_t)row0 * HDIM + col) = make_float2(c[mf][nf].x, c[mf][nf].y);
            *(float2*)(C + (size_t)(row0 + 8) * HDIM + col) = make_float2(c[mf][nf].z, c[mf][nf].w);
        }
    }
}

// ---------------- kernel 3: proj via mma — proj_in = x@iB^T, proj_err = V@iA ----------------
// block: 256 thr (8 warps x m16), 128 rows, K loop in chunks of 32 (double buffered)
__global__ __launch_bounds__(256) void proj_mma_kernel(
    const float* __restrict__ x,
    const float* __restrict__ iA,   // [K, R]
    const float* __restrict__ iB)   // [R, K]
{
    int tid  = threadIdx.x;
    int wid  = tid >> 5;
    int lane = tid & 31;
    int grp  = lane >> 2;
    int tig  = lane & 3;

    int rowbase = blockIdx.x * 128;
    const float* Xb = x   + (size_t)rowbase * KDIM;
    const float* Vb = g_V + (size_t)rowbase * KDIM;

    float4 cI[2], cE[2];
    cI[0] = make_float4(0,0,0,0); cI[1] = make_float4(0,0,0,0);
    cE[0] = make_float4(0,0,0,0); cE[1] = make_float4(0,0,0,0);

    // stage layout: [stage][2 tiles][128][PLDA]
    auto load_stage = [&](int stage, int k0) {
        uint32_t sx = smem_u32(sm_dyn) + stage * (2 * PROJ_STAGE * 4);
        uint32_t sv = sx + PROJ_STAGE * 4;
        #pragma unroll
        for (int i = 0; i < 4; i++) {
            int idx = tid + i * 256;
            int row = idx >> 3, seg = idx & 7;
            cp16(sx + row * (PLDA * 4) + seg * 16, Xb + (size_t)row * KDIM + k0 + seg * 4);
        }
        #pragma unroll
        for (int i = 0; i < 4; i++) {
            int idx = tid + i * 256;
            int row = idx >> 3, seg = idx & 7;
            cp16(sv + row * (PLDA * 4) + seg * 16, Vb + (size_t)row * KDIM + k0 + seg * 4);
        }
        asm volatile("cp.async.commit_group;" ::: "memory");
    };

    load_stage(0, 0);

    for (int it = 0; it < NIT; it++) {
        int k0 = it * BK;
        // preload B fragments for this k-chunk (L1-resident small matrices)
        uint32_t bI[4][2][2], bE[4][2][2];
        #pragma unroll
        for (int kk = 0; kk < 4; kk++) {
            int kidx = k0 + kk * 8 + tig;
            #pragma unroll
            for (int nf = 0; nf < 2; nf++) {
                int n = nf * 8 + grp;
                bI[kk][nf][0] = __float_as_uint(iB[(size_t)n * KDIM + kidx]);
                bI[kk][nf][1] = __float_as_uint(iB[(size_t)n * KDIM + kidx + 4]);
                bE[kk][nf][0] = __float_as_uint(iA[(size_t)kidx * RANK + n]);
                bE[kk][nf][1] = __float_as_uint(iA[(size_t)(kidx + 4) * RANK + n]);
            }
        }

        asm volatile("cp.async.wait_group 0;" ::: "memory");
        __syncthreads();
        if (it + 1 < NIT) load_stage((it + 1) & 1, k0 + BK);

        const float* sx = sm_dyn + (it & 1) * (2 * PROJ_STAGE);
        const float* sv = sx + PROJ_STAGE;

        #pragma unroll
        for (int kk = 0; kk < 4; kk++) {
            uint32_t ax[4], av[4];
            const float* px = sx + (wid * 16 + grp) * PLDA + kk * 8 + tig;
            ax[0] = __float_as_uint(px[0]);
            ax[1] = __float_as_uint(px[8 * PLDA]);
            ax[2] = __float_as_uint(px[4]);
            ax[3] = __float_as_uint(px[8 * PLDA + 4]);
            const float* pv = sv + (wid * 16 + grp) * PLDA + kk * 8 + tig;
            av[0] = __float_as_uint(pv[0]);
            av[1] = __float_as_uint(pv[8 * PLDA]);
            av[2] = __float_as_uint(pv[4]);
            av[3] = __float_as_uint(pv[8 * PLDA + 4]);
            #pragma unroll
            for (int nf = 0; nf < 2; nf++) {
                mma_tf32(cI[nf], ax, bI[kk][nf]);
                mma_tf32(cE[nf], av, bE[kk][nf]);
            }
        }
        __syncthreads();
    }

    int row = rowbase + wid * 16 + grp;
    #pragma unroll
    for (int nf = 0; nf < 2; nf++) {
        int col = nf * 8 + 2 * tig;
        *(float2*)(g_proj_in  + (size_t)row * RANK + col)       = make_float2(cI[nf].x, cI[nf].y);
        *(float2*)(g_proj_in  + (size_t)(row + 8) * RANK + col) = make_float2(cI[nf].z, cI[nf].w);
        *(float2*)(g_proj_err + (size_t)row * RANK + col)       = make_float2(cE[nf].x, cE[nf].y);
        *(float2*)(g_proj_err + (size_t)(row + 8) * RANK + col) = make_float2(cE[nf].z, cE[nf].w);
    }
}

// ---------------- kernel 4: dA / dB ----------------
__global__ __launch_bounds__(128) void delta_kernel(const float* __restrict__ x)
{
    int c = blockIdx.x, part = blockIdx.y, mode = blockIdx.z;
    __shared__ float sp[CHUNK][RANK];
    const float* P = (mode == 0 ? g_proj_in : g_proj_err) + (size_t)c * CHUNK * RANK;
    for (int i = threadIdx.x; i < CHUNK * RANK; i += 128)
        sp[i >> 4][i & 15] = P[i];
    __syncthreads();

    int col = part * 128 + threadIdx.x;
    const float* src = (mode == 0 ? g_V : x) + (size_t)c * CHUNK * KDIM + col;

    float acc[RANK];
    #pragma unroll
    for (int r = 0; r < RANK; r++) acc[r] = 0.f;

    #pragma unroll 4
    for (int i = 0; i < CHUNK; i++) {
        float v = src[(size_t)i * KDIM];
        #pragma unroll
        for (int r = 0; r < RANK; r++) acc[r] += v * sp[i][r];
    }

    if (mode == 0) {
        float* d = g_dA + (size_t)c * HDIM * RANK + (size_t)col * RANK;
        #pragma unroll
        for (int r = 0; r < RANK; r += 4)
            *(float4*)(d + r) = make_float4(acc[r], acc[r+1], acc[r+2], acc[r+3]);
    } else {
        float* d = g_dB + (size_t)c * RANK * KDIM + col;
        #pragma unroll
        for (int r = 0; r < RANK; r++) d[(size_t)r * KDIM] = acc[r];
    }
}

// ---------------- kernel 5: exclusive cumsum over chunks ----------------
__global__ __launch_bounds__(256) void cumsum_kernel()
{
    int e = blockIdx.x * 256 + threadIdx.x;
    int b = blockIdx.y;
    float* base = blockIdx.z ? g_dB : g_dA;
    float run = 0.f;
    #pragma unroll
    for (int j = 0; j < NCH; j++) {
        size_t off = ((size_t)(b * NCH + j)) * (HDIM * RANK) + e;
        float t = base[off];
        base[off] = run;
        run += t;
    }
}

// ---------------- kernel 6: joint norm clip coefficient ----------------
__global__ __launch_bounds__(256) void clip_kernel()
{
    int c = blockIdx.x;
    const float* A = g_dA + (size_t)c * (HDIM * RANK);
    const float* B = g_dB + (size_t)c * (RANK * KDIM);
    float s = 0.f;
    for (int i = threadIdx.x; i < HDIM * RANK; i += 256) {
        float a = A[i]; s += a * a;
        float b = B[i]; s += b * b;
    }
    #pragma unroll
    for (int o = 16; o; o >>= 1) s += __shfl_xor_sync(0xffffffffu, s, o);
    __shared__ float sm[8];
    int w = threadIdx.x >> 5, l = threadIdx.x & 31;
    if (!l) sm[w] = s;
    __syncthreads();
    if (threadIdx.x == 0) {
        float t = 0.f;
        #pragma unroll
        for (int i = 0; i < 8; i++) t += sm[i];
        float norm = LRC * sqrtf(t);
        g_coef[c] = fminf(1.0f, CLIP / (norm + 1e-6f));
    }
}

// ---------------- kernel 7: effective weights ----------------
__global__ __launch_bounds__(256) void eff_kernel(
    const float* __restrict__ iA, const float* __restrict__ iB)
{
    int c = blockIdx.y;
    int i = blockIdx.x * 256 + threadIdx.x;
    float s = LRC * g_coef[c];
    size_t off = (size_t)c * (HDIM * RANK) + i;
    g_Aeff[off] = iA[i] - s * g_dA[off];
    g_Beff[off] = iB[i] - s * g_dB[off];
}

// ---------------- kernel 8: mid = Z @ B_eff^T via mma ----------------
__global__ __launch_bounds__(256) void mid_mma_kernel(const float* __restrict__ x)
{
    int tid  = threadIdx.x;
    int wid  = tid >> 5;
    int lane = tid & 31;
    int grp  = lane >> 2;
    int tig  = lane & 3;

    int rowbase = blockIdx.x * 128;
    int c = rowbase >> 8;
    const float* Xb = x + (size_t)rowbase * KDIM;
    const float* Be = g_Beff + (size_t)c * (RANK * KDIM);   // [R][K]

    float4 cI[2];
    cI[0] = make_float4(0,0,0,0); cI[1] = make_float4(0,0,0,0);

    auto load_stage = [&](int stage, int k0) {
        uint32_t sx = smem_u32(sm_dyn) + stage * (PROJ_STAGE * 4);
        #pragma unroll
        for (int i = 0; i < 4; i++) {
            int idx = tid + i * 256;
            int row = idx >> 3, seg = idx & 7;
            cp16(sx + row * (PLDA * 4) + seg * 16, Xb + (size_t)row * KDIM + k0 + seg * 4);
        }
        asm volatile("cp.async.commit_group;" ::: "memory");
    };

    load_stage(0, 0);

    for (int it = 0; it < NIT; it++) {
        int k0 = it * BK;
        uint32_t bI[4][2][2];
        #pragma unroll
        for (int kk = 0; kk < 4; kk++) {
            int kidx = k0 + kk * 8 + tig;
            #pragma unroll
            for (int nf = 0; nf < 2; nf++) {
                int n = nf * 8 + grp;
                bI[kk][nf][0] = __float_as_uint(Be[(size_t)n * KDIM + kidx]);
                bI[kk][nf][1] = __float_as_uint(Be[(size_t)n * KDIM + kidx + 4]);
            }
        }

        asm volatile("cp.async.wait_group 0;" ::: "memory");
        __syncthreads();
        if (it + 1 < NIT) load_stage((it + 1) & 1, k0 + BK);

        const float* sx = sm_dyn + (it & 1) * PROJ_STAGE;

        #pragma unroll
        for (int kk = 0; kk < 4; kk++) {
            uint32_t ax[4];
            const float* px = sx + (wid * 16 + grp) * PLDA + kk * 8 + tig;
            ax[0] = __float_as_uint(px[0]);
            ax[1] = __float_as_uint(px[8 * PLDA]);
            ax[2] = __float_as_uint(px[4]);
            ax[3] = __float_as_uint(px[8 * PLDA + 4]);
            #pragma unroll
            for (int nf = 0; nf < 2; nf++)
                mma_tf32(cI[nf], ax, bI[kk][nf]);
        }
        __syncthreads();
    }

    int row = rowbase + wid * 16 + grp;
    #pragma unroll
    for (int nf = 0; nf < 2; nf++) {
        int col = nf * 8 + 2 * tig;
        *(float2*)(g_mid + (size_t)row * RANK + col)       = make_float2(cI[nf].x, cI[nf].y);
        *(float2*)(g_mid + (size_t)(row + 8) * RANK + col) = make_float2(cI[nf].z, cI[nf].w);
    }
}

// ---------------- kernel 9: lora apply — out += SCALE * mid @ A_eff^T ----------------
// grid (4 rowgroups, NBC chunks); thread owns 4 h columns, Aeff slice in regs
__global__ __launch_bounds__(256) void lora_apply_kernel(float* __restrict__ out)
{
    int c = blockIdx.y;
    int g = blockIdx.x;
    int row0 = c * CHUNK + g * 64;
    int h0 = threadIdx.x * 4;

    __shared__ float smid[64][RANK];
    for (int i = threadIdx.x; i < 64 * RANK; i += 256)
        smid[i >> 4][i & 15] = g_mid[(size_t)row0 * RANK + i];

    // cache Aeff[h0..h0+3][0..15]
    float4 ae[4][4];
    const float* Ae = g_Aeff + (size_t)c * (HDIM * RANK);
    #pragma unroll
    for (int j = 0; j < 4; j++)
        #pragma unroll
        for (int q = 0; q < 4; q++)
            ae[j][q] = *(const float4*)(Ae + (size_t)(h0 + j) * RANK + q * 4);
    __syncthreads();

    for (int rr = 0; rr < 64; rr++) {
        const float* m = smid[rr];
        float4 m0 = *(const float4*)(m);
        float4 m1 = *(const float4*)(m + 4);
        float4 m2 = *(const float4*)(m + 8);
        float4 m3 = *(const float4*)(m + 12);

        float v[4];
        #pragma unroll
        for (int j = 0; j < 4; j++) {
            v[j] = m0.x * ae[j][0].x + m0.y * ae[j][0].y + m0.z * ae[j][0].z + m0.w * ae[j][0].w
                 + m1.x * ae[j][1].x + m1.y * ae[j][1].y + m1.z * ae[j][1].z + m1.w * ae[j][1].w
                 + m2.x * ae[j][2].x + m2.y * ae[j][2].y + m2.z * ae[j][2].z + m2.w * ae[j][2].w
                 + m3.x * ae[j][3].x + m3.y * ae[j][3].y + m3.z * ae[j][3].z + m3.w * ae[j][3].w;
        }
        float4* op = (float4*)(out + (size_t)(row0 + rr) * HDIM + h0);
        float4 o = *op;
        o.x += SCALE * v[0];
        o.y += SCALE * v[1];
        o.z += SCALE * v[2];
        o.w += SCALE * v[3];
        *op = o;
    }
}

// ---------------- launch ----------------
extern "C" void kernel_launch(void* const* d_in, const int* in_sizes, int n_in,
                              void* d_out, int out_size)
{
    const float* x   = (const float*)d_in[0];
    const float* Wb  = (const float*)d_in[1];
    const float* iA  = (const float*)d_in[2];
    const float* iB  = (const float*)d_in[3];
    const float* gam = (const float*)d_in[4];
    const float* bet = (const float*)d_in[5];
    const float* Wp  = (const float*)d_in[6];
    float* out = (float*)d_out;

    cudaFuncSetAttribute(gemm_tf32,       cudaFuncAttributeMaxDynamicSharedMemorySize, SMEM_GEMM);
    cudaFuncSetAttribute(proj_mma_kernel, cudaFuncAttributeMaxDynamicSharedMemorySize, SMEM_PROJ);
    cudaFuncSetAttribute(mid_mma_kernel,  cudaFuncAttributeMaxDynamicSharedMemorySize, SMEM_MID);

    ln_shift_kernel<<<M_TOT, 256>>>(x, gam, bet);

    dim3 gg(HDIM / BN, M_TOT / BM);
    gemm_tf32<<<gg, 256, SMEM_GEMM>>>(x, Wb, out, 0);            // base_out
    gemm_tf32<<<gg, 256, SMEM_GEMM>>>(nullptr, Wp, nullptr, 1);  // V

    proj_mma_kernel<<<M_TOT / 128, 256, SMEM_PROJ>>>(x, iA, iB);
    delta_kernel<<<dim3(NBC, KDIM / 128, 2), 128>>>(x);
    cumsum_kernel<<<dim3((HDIM * RANK) / 256, NBATCH, 2), 256>>>();
    clip_kernel<<<NBC, 256>>>();
    eff_kernel<<<dim3((HDIM * RANK) / 256, NBC), 256>>>(iA, iB);
    mid_mma_kernel<<<M_TOT / 128, 256, SMEM_MID>>>(x);
    lora_apply_kernel<<<dim3(4, NBC), 256>>>(out);
}

// round 6
// speedup vs baseline: 2.8751x; 1.0405x over previous
#include <cuda_runtime.h>
#include <math.h>
#include <stdint.h>

// ---------------- problem constants ----------------
#define M_TOT   16384
#define SEQ     8192
#define KDIM    1024
#define HDIM    1024
#define RANK    16
#define CHUNK   256
#define NCH     32
#define NBATCH  2
#define NBC     64
#define LRC     0.02f
#define SCALE   2.0f
#define CLIP    1.0f
#define LN_EPS  1e-5f

// ---------------- GEMM tiling ----------------
#define BM 128
#define BN 256
#define BK 32
#define LDA 36
#define STAGE_FLOATS ((BM + BN) * LDA)           // 13824 floats
#define STAGE_BYTES  (STAGE_FLOATS * 4)          // 55296 B
#define NSTAGE 3
#define SMEM_GEMM (NSTAGE * STAGE_BYTES)         // 165888 B
#define NIT (KDIM / BK)                          // 32

// proj/mid mma kernels
#define PLDA 36
#define PROJ_STAGE (128 * PLDA)
#define SMEM_PROJ (2 * 2 * PROJ_STAGE * 4)
#define SMEM_MID  (2 * PROJ_STAGE * 4)

// ---------------- device scratch ----------------
__device__ __align__(128) float g_shifted[M_TOT * KDIM];
__device__ __align__(128) float g_V      [M_TOT * KDIM];
__device__ __align__(128) float g_proj_in [NBC * CHUNK * RANK];
__device__ __align__(128) float g_proj_err[NBC * CHUNK * RANK];
__device__ __align__(128) float g_dA  [NBC * HDIM * RANK];
__device__ __align__(128) float g_dB  [NBC * RANK * KDIM];
__device__ __align__(128) float g_Aeff[NBC * HDIM * RANK];
__device__ __align__(128) float g_Beff[NBC * RANK * KDIM];
__device__ __align__(128) float g_mid [M_TOT * RANK];
__device__ __align__(128) float g_coef[NBC];

// ---------------- helpers ----------------
__device__ __forceinline__ uint32_t smem_u32(const void* p) {
    uint32_t a;
    asm("{ .reg .u64 t; cvta.to.shared.u64 t, %1; cvt.u32.u64 %0, t; }" : "=r"(a) : "l"(p));
    return a;
}
__device__ __forceinline__ void cp16(uint32_t d, const void* s) {
    asm volatile("cp.async.cg.shared.global [%0], [%1], 16;" :: "r"(d), "l"(s));
}
__device__ __forceinline__ void mma_tf32(float4& c, const uint32_t a[4], const uint32_t b[2]) {
    asm volatile(
        "mma.sync.aligned.m16n8k8.row.col.f32.tf32.tf32.f32 "
        "{%0,%1,%2,%3}, {%4,%5,%6,%7}, {%8,%9}, {%0,%1,%2,%3};"
        : "+f"(c.x), "+f"(c.y), "+f"(c.z), "+f"(c.w)
        : "r"(a[0]), "r"(a[1]), "r"(a[2]), "r"(a[3]), "r"(b[0]), "r"(b[1]));
}
__device__ __forceinline__ void ldsm4(uint32_t r[4], uint32_t addr) {
    asm volatile("ldmatrix.sync.aligned.m8n8.x4.shared.b16 {%0,%1,%2,%3}, [%4];"
                 : "=r"(r[0]), "=r"(r[1]), "=r"(r[2]), "=r"(r[3]) : "r"(addr));
}

// ---------------- kernel 1: LayerNorm + left shift ----------------
__global__ __launch_bounds__(256) void ln_shift_kernel(
    const float* __restrict__ x,
    const float* __restrict__ gam,
    const float* __restrict__ bet)
{
    int row = blockIdx.x;
    int s   = row & (SEQ - 1);
    const float4* xr = (const float4*)(x + (size_t)row * KDIM);
    float4 v = xr[threadIdx.x];

    float sum = v.x + v.y + v.z + v.w;
    float ssq = v.x*v.x + v.y*v.y + v.z*v.z + v.w*v.w;
    #pragma unroll
    for (int o = 16; o; o >>= 1) {
        sum += __shfl_xor_sync(0xffffffffu, sum, o);
        ssq += __shfl_xor_sync(0xffffffffu, ssq, o);
    }
    __shared__ float s1[8], s2[8];
    int w = threadIdx.x >> 5, l = threadIdx.x & 31;
    if (!l) { s1[w] = sum; s2[w] = ssq; }
    __syncthreads();
    if (threadIdx.x == 0) {
        float a = 0.f, b = 0.f;
        #pragma unroll
        for (int i = 0; i < 8; i++) { a += s1[i]; b += s2[i]; }
        s1[0] = a; s2[0] = b;
    }
    __syncthreads();
    float mu   = s1[0] * (1.0f / KDIM);
    float var  = s2[0] * (1.0f / KDIM) - mu * mu;
    float rstd = rsqrtf(var + LN_EPS);

    if (s == 0) {
        float4* d = (float4*)(g_shifted + ((size_t)row + SEQ - 1) * KDIM);
        d[threadIdx.x] = make_float4(0.f, 0.f, 0.f, 0.f);
    } else {
        float4 g4 = ((const float4*)gam)[threadIdx.x];
        float4 b4 = ((const float4*)bet)[threadIdx.x];
        float4 o;
        o.x = (v.x - mu) * rstd * g4.x + b4.x;
        o.y = (v.y - mu) * rstd * g4.y + b4.y;
        o.z = (v.z - mu) * rstd * g4.z + b4.z;
        o.w = (v.w - mu) * rstd * g4.w + b4.w;
        float4* d = (float4*)(g_shifted + (size_t)(row - 1) * KDIM);
        d[threadIdx.x] = o;
    }
}

// ---------------- kernel 2: TF32 mma GEMM, ldmatrix + 3-stage pipeline ----------------
extern __shared__ float sm_dyn[];

__device__ __forceinline__ void gemm_load_stage(
    uint32_t sbase, int stage, const float* Ab, const float* Wb, int k0, int tid)
{
    uint32_t sa = sbase + stage * STAGE_BYTES;
    uint32_t sw = sa + BM * LDA * 4;
    #pragma unroll
    for (int i = 0; i < 4; i++) {           // A: 128 rows x 8 segs
        int idx = tid + i * 256;
        int row = idx >> 3, seg = idx & 7;
        cp16(sa + row * (LDA * 4) + seg * 16, Ab + (size_t)row * KDIM + k0 + seg * 4);
    }
    #pragma unroll
    for (int i = 0; i < 8; i++) {           // B: 256 rows x 8 segs
        int idx = tid + i * 256;
        int row = idx >> 3, seg = idx & 7;
        cp16(sw + row * (LDA * 4) + seg * 16, Wb + (size_t)row * KDIM + k0 + seg * 4);
    }
    asm volatile("cp.async.commit_group;" ::: "memory");
}

__global__ __launch_bounds__(256) void gemm_tf32(
    const float* __restrict__ x, const float* __restrict__ Wbm,
    const float* __restrict__ Wpm, float* __restrict__ out)
{
    const float* A;
    const float* W;
    float* C;
    if (blockIdx.z == 0) { A = x;         W = Wbm; C = out; }
    else                 { A = g_shifted; W = Wpm; C = g_V; }

    int tid  = threadIdx.x;
    int wid  = tid >> 5;
    int lane = tid & 31;
    int grp  = lane >> 2;
    int tig  = lane & 3;
    int wm   = wid & 1;          // 2 m-warps x 64
    int wn   = wid >> 1;         // 4 n-warps x 64

    int mbase = blockIdx.y * BM;
    int nbase = blockIdx.x * BN;
    const float* Ab = A + (size_t)mbase * KDIM;
    const float* Wb = W + (size_t)nbase * KDIM;

    uint32_t sbase = smem_u32(sm_dyn);

    // ldmatrix per-lane addresses
    int quad = lane >> 3, lr = lane & 7;
    // A quads: (rowblk = quad&1, kseg = quad>>1)
    uint32_t aOff = ((uint32_t)(wm * 64 + ((quad & 1) << 3) + lr) * LDA +
                     ((quad >> 1) << 2)) * 4;
    // B quads: (nblk = quad>>1, kseg = quad&1)
    uint32_t bOff = (uint32_t)(BM * LDA * 4) +
                    ((uint32_t)(wn * 64 + ((quad >> 1) << 3) + lr) * LDA +
                     ((quad & 1) << 2)) * 4;

    float4 c[4][8];
    #pragma unroll
    for (int i = 0; i < 4; i++)
        #pragma unroll
        for (int j = 0; j < 8; j++) c[i][j] = make_float4(0.f, 0.f, 0.f, 0.f);

    gemm_load_stage(sbase, 0, Ab, Wb, 0, tid);
    gemm_load_stage(sbase, 1, Ab, Wb, BK, tid);

    for (int it = 0; it < NIT; it++) {
        if (it == NIT - 1) asm volatile("cp.async.wait_group 0;" ::: "memory");
        else               asm volatile("cp.async.wait_group 1;" ::: "memory");
        __syncthreads();
        if (it + 2 < NIT)
            gemm_load_stage(sbase, (it + 2) % NSTAGE, Ab, Wb, (it + 2) * BK, tid);

        uint32_t stge = sbase + (it % NSTAGE) * STAGE_BYTES;
        uint32_t aB = stge + aOff;
        uint32_t bB = stge + bOff;

        #pragma unroll
        for (int k8 = 0; k8 < 4; k8++) {
            uint32_t a[4][4], b[8][2];
            #pragma unroll
            for (int mf = 0; mf < 4; mf++)
                ldsm4(a[mf], aB + mf * (16 * LDA * 4) + k8 * 32);
            #pragma unroll
            for (int p = 0; p < 4; p++) {
                uint32_t r[4];
                ldsm4(r, bB + p * (16 * LDA * 4) + k8 * 32);
                b[2*p][0]   = r[0]; b[2*p][1]   = r[1];
                b[2*p+1][0] = r[2]; b[2*p+1][1] = r[3];
            }
            #pragma unroll
            for (int mf = 0; mf < 4; mf++)
                #pragma unroll
                for (int nf = 0; nf < 8; nf++)
                    mma_tf32(c[mf][nf], a[mf], b[nf]);
        }
    }

    #pragma unroll
    for (int mf = 0; mf < 4; mf++) {
        int row0 = mbase + wm * 64 + mf * 16 + grp;
        #pragma unroll
        for (int nf = 0; nf < 8; nf++) {
            int col = nbase + wn * 64 + nf * 8 + 2 * tig;
            *(float2*)(C + (size_t)row0 * HDIM + col)       = make_float2(c[mf][nf].x, c[mf][nf].y);
            *(float2*)(C + (size_t)(row0 + 8) * HDIM + col) = make_float2(c[mf][nf].z, c[mf][nf].w);
        }
    }
}

// ---------------- kernel 3: proj via mma ----------------
__global__ __launch_bounds__(256) void proj_mma_kernel(
    const float* __restrict__ x,
    const float* __restrict__ iA,   // [K, R]
    const float* __restrict__ iB)   // [R, K]
{
    int tid  = threadIdx.x;
    int wid  = tid >> 5;
    int lane = tid & 31;
    int grp  = lane >> 2;
    int tig  = lane & 3;

    int rowbase = blockIdx.x * 128;
    const float* Xb = x   + (size_t)rowbase * KDIM;
    const float* Vb = g_V + (size_t)rowbase * KDIM;

    float4 cI[2], cE[2];
    cI[0] = make_float4(0,0,0,0); cI[1] = make_float4(0,0,0,0);
    cE[0] = make_float4(0,0,0,0); cE[1] = make_float4(0,0,0,0);

    auto load_stage = [&](int stage, int k0) {
        uint32_t sx = smem_u32(sm_dyn) + stage * (2 * PROJ_STAGE * 4);
        uint32_t sv = sx + PROJ_STAGE * 4;
        #pragma unroll
        for (int i = 0; i < 4; i++) {
            int idx = tid + i * 256;
            int row = idx >> 3, seg = idx & 7;
            cp16(sx + row * (PLDA * 4) + seg * 16, Xb + (size_t)row * KDIM + k0 + seg * 4);
        }
        #pragma unroll
        for (int i = 0; i < 4; i++) {
            int idx = tid + i * 256;
            int row = idx >> 3, seg = idx & 7;
            cp16(sv + row * (PLDA * 4) + seg * 16, Vb + (size_t)row * KDIM + k0 + seg * 4);
        }
        asm volatile("cp.async.commit_group;" ::: "memory");
    };

    load_stage(0, 0);

    for (int it = 0; it < NIT; it++) {
        int k0 = it * BK;
        uint32_t bI[4][2][2], bE[4][2][2];
        #pragma unroll
        for (int kk = 0; kk < 4; kk++) {
            int kidx = k0 + kk * 8 + tig;
            #pragma unroll
            for (int nf = 0; nf < 2; nf++) {
                int n = nf * 8 + grp;
                bI[kk][nf][0] = __float_as_uint(iB[(size_t)n * KDIM + kidx]);
                bI[kk][nf][1] = __float_as_uint(iB[(size_t)n * KDIM + kidx + 4]);
                bE[kk][nf][0] = __float_as_uint(iA[(size_t)kidx * RANK + n]);
                bE[kk][nf][1] = __float_as_uint(iA[(size_t)(kidx + 4) * RANK + n]);
            }
        }

        asm volatile("cp.async.wait_group 0;" ::: "memory");
        __syncthreads();
        if (it + 1 < NIT) load_stage((it + 1) & 1, k0 + BK);

        const float* sx = sm_dyn + (it & 1) * (2 * PROJ_STAGE);
        const float* sv = sx + PROJ_STAGE;

        #pragma unroll
        for (int kk = 0; kk < 4; kk++) {
            uint32_t ax[4], av[4];
            const float* px = sx + (wid * 16 + grp) * PLDA + kk * 8 + tig;
            ax[0] = __float_as_uint(px[0]);
            ax[1] = __float_as_uint(px[8 * PLDA]);
            ax[2] = __float_as_uint(px[4]);
            ax[3] = __float_as_uint(px[8 * PLDA + 4]);
            const float* pv = sv + (wid * 16 + grp) * PLDA + kk * 8 + tig;
            av[0] = __float_as_uint(pv[0]);
            av[1] = __float_as_uint(pv[8 * PLDA]);
            av[2] = __float_as_uint(pv[4]);
            av[3] = __float_as_uint(pv[8 * PLDA + 4]);
            #pragma unroll
            for (int nf = 0; nf < 2; nf++) {
                mma_tf32(cI[nf], ax, bI[kk][nf]);
                mma_tf32(cE[nf], av, bE[kk][nf]);
            }
        }
        __syncthreads();
    }

    int row = rowbase + wid * 16 + grp;
    #pragma unroll
    for (int nf = 0; nf < 2; nf++) {
        int col = nf * 8 + 2 * tig;
        *(float2*)(g_proj_in  + (size_t)row * RANK + col)       = make_float2(cI[nf].x, cI[nf].y);
        *(float2*)(g_proj_in  + (size_t)(row + 8) * RANK + col) = make_float2(cI[nf].z, cI[nf].w);
        *(float2*)(g_proj_err + (size_t)row * RANK + col)       = make_float2(cE[nf].x, cE[nf].y);
        *(float2*)(g_proj_err + (size_t)(row + 8) * RANK + col) = make_float2(cE[nf].z, cE[nf].w);
    }
}

// ---------------- kernel 4: dA / dB ----------------
__global__ __launch_bounds__(128) void delta_kernel(const float* __restrict__ x)
{
    int c = blockIdx.x, part = blockIdx.y, mode = blockIdx.z;
    __shared__ float sp[CHUNK][RANK];
    const float* P = (mode == 0 ? g_proj_in : g_proj_err) + (size_t)c * CHUNK * RANK;
    for (int i = threadIdx.x; i < CHUNK * RANK; i += 128)
        sp[i >> 4][i & 15] = P[i];
    __syncthreads();

    int col = part * 128 + threadIdx.x;
    const float* src = (mode == 0 ? g_V : x) + (size_t)c * CHUNK * KDIM + col;

    float acc[RANK];
    #pragma unroll
    for (int r = 0; r < RANK; r++) acc[r] = 0.f;

    #pragma unroll 4
    for (int i = 0; i < CHUNK; i++) {
        float v = src[(size_t)i * KDIM];
        #pragma unroll
        for (int r = 0; r < RANK; r++) acc[r] += v * sp[i][r];
    }

    if (mode == 0) {
        float* d = g_dA + (size_t)c * HDIM * RANK + (size_t)col * RANK;
        #pragma unroll
        for (int r = 0; r < RANK; r += 4)
            *(float4*)(d + r) = make_float4(acc[r], acc[r+1], acc[r+2], acc[r+3]);
    } else {
        float* d = g_dB + (size_t)c * RANK * KDIM + col;
        #pragma unroll
        for (int r = 0; r < RANK; r++) d[(size_t)r * KDIM] = acc[r];
    }
}

// ---------------- kernel 5: exclusive cumsum over chunks ----------------
__global__ __launch_bounds__(256) void cumsum_kernel()
{
    int e = blockIdx.x * 256 + threadIdx.x;
    int b = blockIdx.y;
    float* base = blockIdx.z ? g_dB : g_dA;
    float run = 0.f;
    #pragma unroll
    for (int j = 0; j < NCH; j++) {
        size_t off = ((size_t)(b * NCH + j)) * (HDIM * RANK) + e;
        float t = base[off];
        base[off] = run;
        run += t;
    }
}

// ---------------- kernel 6: joint norm clip coefficient ----------------
__global__ __launch_bounds__(256) void clip_kernel()
{
    int c = blockIdx.x;
    const float* A = g_dA + (size_t)c * (HDIM * RANK);
    const float* B = g_dB + (size_t)c * (RANK * KDIM);
    float s = 0.f;
    for (int i = threadIdx.x; i < HDIM * RANK; i += 256) {
        float a = A[i]; s += a * a;
        float b = B[i]; s += b * b;
    }
    #pragma unroll
    for (int o = 16; o; o >>= 1) s += __shfl_xor_sync(0xffffffffu, s, o);
    __shared__ float sm[8];
    int w = threadIdx.x >> 5, l = threadIdx.x & 31;
    if (!l) sm[w] = s;
    __syncthreads();
    if (threadIdx.x == 0) {
        float t = 0.f;
        #pragma unroll
        for (int i = 0; i < 8; i++) t += sm[i];
        float norm = LRC * sqrtf(t);
        g_coef[c] = fminf(1.0f, CLIP / (norm + 1e-6f));
    }
}

// ---------------- kernel 7: effective weights ----------------
__global__ __launch_bounds__(256) void eff_kernel(
    const float* __restrict__ iA, const float* __restrict__ iB)
{
    int c = blockIdx.y;
    int i = blockIdx.x * 256 + threadIdx.x;
    float s = LRC * g_coef[c];
    size_t off = (size_t)c * (HDIM * RANK) + i;
    g_Aeff[off] = iA[i] - s * g_dA[off];
    g_Beff[off] = iB[i] - s * g_dB[off];
}

// ---------------- kernel 8: mid = Z @ B_eff^T via mma ----------------
__global__ __launch_bounds__(256) void mid_mma_kernel(const float* __restrict__ x)
{
    int tid  = threadIdx.x;
    int wid  = tid >> 5;
    int lane = tid & 31;
    int grp  = lane >> 2;
    int tig  = lane & 3;

    int rowbase = blockIdx.x * 128;
    int c = rowbase >> 8;
    const float* Xb = x + (size_t)rowbase * KDIM;
    const float* Be = g_Beff + (size_t)c * (RANK * KDIM);

    float4 cI[2];
    cI[0] = make_float4(0,0,0,0); cI[1] = make_float4(0,0,0,0);

    auto load_stage = [&](int stage, int k0) {
        uint32_t sx = smem_u32(sm_dyn) + stage * (PROJ_STAGE * 4);
        #pragma unroll
        for (int i = 0; i < 4; i++) {
            int idx = tid + i * 256;
            int row = idx >> 3, seg = idx & 7;
            cp16(sx + row * (PLDA * 4) + seg * 16, Xb + (size_t)row * KDIM + k0 + seg * 4);
        }
        asm volatile("cp.async.commit_group;" ::: "memory");
    };

    load_stage(0, 0);

    for (int it = 0; it < NIT; it++) {
        int k0 = it * BK;
        uint32_t bI[4][2][2];
        #pragma unroll
        for (int kk = 0; kk < 4; kk++) {
            int kidx = k0 + kk * 8 + tig;
            #pragma unroll
            for (int nf = 0; nf < 2; nf++) {
                int n = nf * 8 + grp;
                bI[kk][nf][0] = __float_as_uint(Be[(size_t)n * KDIM + kidx]);
                bI[kk][nf][1] = __float_as_uint(Be[(size_t)n * KDIM + kidx + 4]);
            }
        }

        asm volatile("cp.async.wait_group 0;" ::: "memory");
        __syncthreads();
        if (it + 1 < NIT) load_stage((it + 1) & 1, k0 + BK);

        const float* sx = sm_dyn + (it & 1) * PROJ_STAGE;

        #pragma unroll
        for (int kk = 0; kk < 4; kk++) {
            uint32_t ax[4];
            const float* px = sx + (wid * 16 + grp) * PLDA + kk * 8 + tig;
            ax[0] = __float_as_uint(px[0]);
            ax[1] = __float_as_uint(px[8 * PLDA]);
            ax[2] = __float_as_uint(px[4]);
            ax[3] = __float_as_uint(px[8 * PLDA + 4]);
            #pragma unroll
            for (int nf = 0; nf < 2; nf++)
                mma_tf32(cI[nf], ax, bI[kk][nf]);
        }
        __syncthreads();
    }

    int row = rowbase + wid * 16 + grp;
    #pragma unroll
    for (int nf = 0; nf < 2; nf++) {
        int col = nf * 8 + 2 * tig;
        *(float2*)(g_mid + (size_t)row * RANK + col)       = make_float2(cI[nf].x, cI[nf].y);
        *(float2*)(g_mid + (size_t)(row + 8) * RANK + col) = make_float2(cI[nf].z, cI[nf].w);
    }
}

// ---------------- kernel 9: lora apply ----------------
__global__ __launch_bounds__(256) void lora_apply_kernel(float* __restrict__ out)
{
    int c = blockIdx.y;
    int g = blockIdx.x;
    int row0 = c * CHUNK + g * 64;
    int h0 = threadIdx.x * 4;

    __shared__ float smid[64][RANK];
    for (int i = threadIdx.x; i < 64 * RANK; i += 256)
        smid[i >> 4][i & 15] = g_mid[(size_t)row0 * RANK + i];

    float4 ae[4][4];
    const float* Ae = g_Aeff + (size_t)c * (HDIM * RANK);
    #pragma unroll
    for (int j = 0; j < 4; j++)
        #pragma unroll
        for (int q = 0; q < 4; q++)
            ae[j][q] = *(const float4*)(Ae + (size_t)(h0 + j) * RANK + q * 4);
    __syncthreads();

    for (int rr = 0; rr < 64; rr++) {
        const float* m = smid[rr];
        float4 m0 = *(const float4*)(m);
        float4 m1 = *(const float4*)(m + 4);
        float4 m2 = *(const float4*)(m + 8);
        float4 m3 = *(const float4*)(m + 12);

        float v[4];
        #pragma unroll
        for (int j = 0; j < 4; j++) {
            v[j] = m0.x * ae[j][0].x + m0.y * ae[j][0].y + m0.z * ae[j][0].z + m0.w * ae[j][0].w
                 + m1.x * ae[j][1].x + m1.y * ae[j][1].y + m1.z * ae[j][1].z + m1.w * ae[j][1].w
                 + m2.x * ae[j][2].x + m2.y * ae[j][2].y + m2.z * ae[j][2].z + m2.w * ae[j][2].w
                 + m3.x * ae[j][3].x + m3.y * ae[j][3].y + m3.z * ae[j][3].z + m3.w * ae[j][3].w;
        }
        float4* op = (float4*)(out + (size_t)(row0 + rr) * HDIM + h0);
        float4 o = *op;
        o.x += SCALE * v[0];
        o.y += SCALE * v[1];
        o.z += SCALE * v[2];
        o.w += SCALE * v[3];
        *op = o;
    }
}

// ---------------- launch ----------------
extern "C" void kernel_launch(void* const* d_in, const int* in_sizes, int n_in,
                              void* d_out, int out_size)
{
    const float* x   = (const float*)d_in[0];
    const float* Wb  = (const float*)d_in[1];
    const float* iA  = (const float*)d_in[2];
    const float* iB  = (const float*)d_in[3];
    const float* gam = (const float*)d_in[4];
    const float* bet = (const float*)d_in[5];
    const float* Wp  = (const float*)d_in[6];
    float* out = (float*)d_out;

    cudaFuncSetAttribute(gemm_tf32,       cudaFuncAttributeMaxDynamicSharedMemorySize, SMEM_GEMM);
    cudaFuncSetAttribute(proj_mma_kernel, cudaFuncAttributeMaxDynamicSharedMemorySize, SMEM_PROJ);
    cudaFuncSetAttribute(mid_mma_kernel,  cudaFuncAttributeMaxDynamicSharedMemorySize, SMEM_MID);

    ln_shift_kernel<<<M_TOT, 256>>>(x, gam, bet);

    dim3 gg(HDIM / BN, M_TOT / BM, 2);
    gemm_tf32<<<gg, 256, SMEM_GEMM>>>(x, Wb, Wp, out);   // z=0: base_out, z=1: V

    proj_mma_kernel<<<M_TOT / 128, 256, SMEM_PROJ>>>(x, iA, iB);
    delta_kernel<<<dim3(NBC, KDIM / 128, 2), 128>>>(x);
    cumsum_kernel<<<dim3((HDIM * RANK) / 256, NBATCH, 2), 256>>>();
    clip_kernel<<<NBC, 256>>>();
    eff_kernel<<<dim3((HDIM * RANK) / 256, NBC), 256>>>(iA, iB);
    mid_mma_kernel<<<M_TOT / 128, 256, SMEM_MID>>>(x);
    lora_apply_kernel<<<dim3(4, NBC), 256>>>(out);
}

// round 7
// speedup vs baseline: 2.9029x; 1.0097x over previous
#include <cuda_runtime.h>
#include <math.h>
#include <stdint.h>

// ---------------- problem constants ----------------
#define M_TOT   16384
#define SEQ     8192
#define KDIM    1024
#define HDIM    1024
#define RANK    16
#define CHUNK   256
#define NCH     32
#define NBATCH  2
#define NBC     64
#define LRC     0.02f
#define SCALE   2.0f
#define CLIP    1.0f
#define LN_EPS  1e-5f

// ---------------- GEMM tiling ----------------
#define BM 128
#define BN 128
#define BK 32
#define LDA 36
#define STAGE_FLOATS ((BM + BN) * LDA)           // 9216 floats
#define STAGE_BYTES  (STAGE_FLOATS * 4)          // 36864 B
#define NSTAGE 3
#define SMEM_GEMM (NSTAGE * STAGE_BYTES)         // 110592 B
#define NIT (KDIM / BK)                          // 32

// proj/mid mma kernels
#define PLDA 36
#define PROJ_STAGE (128 * PLDA)
#define SMEM_PROJ (2 * 2 * PROJ_STAGE * 4)
#define SMEM_MID  (2 * PROJ_STAGE * 4)

// ---------------- device scratch ----------------
__device__ __align__(128) float g_shifted[M_TOT * KDIM];
__device__ __align__(128) float g_V      [M_TOT * KDIM];
__device__ __align__(128) float g_proj_in [NBC * CHUNK * RANK];
__device__ __align__(128) float g_proj_err[NBC * CHUNK * RANK];
__device__ __align__(128) float g_dA  [NBC * HDIM * RANK];
__device__ __align__(128) float g_dB  [NBC * RANK * KDIM];
__device__ __align__(128) float g_Aeff[NBC * HDIM * RANK];
__device__ __align__(128) float g_Beff[NBC * RANK * KDIM];
__device__ __align__(128) float g_mid [M_TOT * RANK];

// ---------------- helpers ----------------
__device__ __forceinline__ uint32_t smem_u32(const void* p) {
    uint32_t a;
    asm("{ .reg .u64 t; cvta.to.shared.u64 t, %1; cvt.u32.u64 %0, t; }" : "=r"(a) : "l"(p));
    return a;
}
__device__ __forceinline__ void cp16(uint32_t d, const void* s) {
    asm volatile("cp.async.cg.shared.global [%0], [%1], 16;" :: "r"(d), "l"(s));
}
__device__ __forceinline__ void mma_tf32(float4& c, const uint32_t a[4], const uint32_t b[2]) {
    asm volatile(
        "mma.sync.aligned.m16n8k8.row.col.f32.tf32.tf32.f32 "
        "{%0,%1,%2,%3}, {%4,%5,%6,%7}, {%8,%9}, {%0,%1,%2,%3};"
        : "+f"(c.x), "+f"(c.y), "+f"(c.z), "+f"(c.w)
        : "r"(a[0]), "r"(a[1]), "r"(a[2]), "r"(a[3]), "r"(b[0]), "r"(b[1]));
}
__device__ __forceinline__ void ldsm4(uint32_t r[4], uint32_t addr) {
    asm volatile("ldmatrix.sync.aligned.m8n8.x4.shared.b16 {%0,%1,%2,%3}, [%4];"
                 : "=r"(r[0]), "=r"(r[1]), "=r"(r[2]), "=r"(r[3]) : "r"(addr));
}

// ---------------- kernel 1: LayerNorm + left shift ----------------
__global__ __launch_bounds__(256) void ln_shift_kernel(
    const float* __restrict__ x,
    const float* __restrict__ gam,
    const float* __restrict__ bet)
{
    int row = blockIdx.x;
    int s   = row & (SEQ - 1);
    const float4* xr = (const float4*)(x + (size_t)row * KDIM);
    float4 v = xr[threadIdx.x];

    float sum = v.x + v.y + v.z + v.w;
    float ssq = v.x*v.x + v.y*v.y + v.z*v.z + v.w*v.w;
    #pragma unroll
    for (int o = 16; o; o >>= 1) {
        sum += __shfl_xor_sync(0xffffffffu, sum, o);
        ssq += __shfl_xor_sync(0xffffffffu, ssq, o);
    }
    __shared__ float s1[8], s2[8];
    int w = threadIdx.x >> 5, l = threadIdx.x & 31;
    if (!l) { s1[w] = sum; s2[w] = ssq; }
    __syncthreads();
    if (threadIdx.x == 0) {
        float a = 0.f, b = 0.f;
        #pragma unroll
        for (int i = 0; i < 8; i++) { a += s1[i]; b += s2[i]; }
        s1[0] = a; s2[0] = b;
    }
    __syncthreads();
    float mu   = s1[0] * (1.0f / KDIM);
    float var  = s2[0] * (1.0f / KDIM) - mu * mu;
    float rstd = rsqrtf(var + LN_EPS);

    if (s == 0) {
        float4* d = (float4*)(g_shifted + ((size_t)row + SEQ - 1) * KDIM);
        d[threadIdx.x] = make_float4(0.f, 0.f, 0.f, 0.f);
    } else {
        float4 g4 = ((const float4*)gam)[threadIdx.x];
        float4 b4 = ((const float4*)bet)[threadIdx.x];
        float4 o;
        o.x = (v.x - mu) * rstd * g4.x + b4.x;
        o.y = (v.y - mu) * rstd * g4.y + b4.y;
        o.z = (v.z - mu) * rstd * g4.z + b4.z;
        o.w = (v.w - mu) * rstd * g4.w + b4.w;
        float4* d = (float4*)(g_shifted + (size_t)(row - 1) * KDIM);
        d[threadIdx.x] = o;
    }
}

// ---------------- kernel 2: TF32 mma GEMM, ldmatrix + 3-stage, 2 CTAs/SM ----------------
extern __shared__ float sm_dyn[];

__device__ __forceinline__ void gemm_load_stage(
    uint32_t sbase, int stage, const float* Ab, const float* Wb, int k0, int tid)
{
    uint32_t sa = sbase + stage * STAGE_BYTES;
    uint32_t sw = sa + BM * LDA * 4;
    #pragma unroll
    for (int i = 0; i < 4; i++) {           // A: 128 rows x 8 segs
        int idx = tid + i * 256;
        int row = idx >> 3, seg = idx & 7;
        cp16(sa + row * (LDA * 4) + seg * 16, Ab + (size_t)row * KDIM + k0 + seg * 4);
    }
    #pragma unroll
    for (int i = 0; i < 4; i++) {           // B: 128 rows x 8 segs
        int idx = tid + i * 256;
        int row = idx >> 3, seg = idx & 7;
        cp16(sw + row * (LDA * 4) + seg * 16, Wb + (size_t)row * KDIM + k0 + seg * 4);
    }
    asm volatile("cp.async.commit_group;" ::: "memory");
}

__global__ __launch_bounds__(256, 2) void gemm_tf32(
    const float* __restrict__ x, const float* __restrict__ Wbm,
    const float* __restrict__ Wpm, float* __restrict__ out)
{
    const float* A;
    const float* W;
    float* C;
    if (blockIdx.z == 0) { A = x;         W = Wbm; C = out; }
    else                 { A = g_shifted; W = Wpm; C = g_V; }

    int tid  = threadIdx.x;
    int wid  = tid >> 5;
    int lane = tid & 31;
    int grp  = lane >> 2;
    int tig  = lane & 3;
    int wm   = wid & 1;          // 2 m-warps x 64
    int wn   = wid >> 1;         // 4 n-warps x 32

    int mbase = blockIdx.y * BM;
    int nbase = blockIdx.x * BN;
    const float* Ab = A + (size_t)mbase * KDIM;
    const float* Wb = W + (size_t)nbase * KDIM;

    uint32_t sbase = smem_u32(sm_dyn);

    // ldmatrix per-lane addresses
    int quad = lane >> 3, lr = lane & 7;
    uint32_t aOff = ((uint32_t)(wm * 64 + ((quad & 1) << 3) + lr) * LDA +
                     ((quad >> 1) << 2)) * 4;
    uint32_t bOff = (uint32_t)(BM * LDA * 4) +
                    ((uint32_t)(wn * 32 + ((quad >> 1) << 3) + lr) * LDA +
                     ((quad & 1) << 2)) * 4;

    float4 c[4][4];
    #pragma unroll
    for (int i = 0; i < 4; i++)
        #pragma unroll
        for (int j = 0; j < 4; j++) c[i][j] = make_float4(0.f, 0.f, 0.f, 0.f);

    gemm_load_stage(sbase, 0, Ab, Wb, 0, tid);
    gemm_load_stage(sbase, 1, Ab, Wb, BK, tid);

    for (int it = 0; it < NIT; it++) {
        if (it == NIT - 1) asm volatile("cp.async.wait_group 0;" ::: "memory");
        else               asm volatile("cp.async.wait_group 1;" ::: "memory");
        __syncthreads();
        if (it + 2 < NIT)
            gemm_load_stage(sbase, (it + 2) % NSTAGE, Ab, Wb, (it + 2) * BK, tid);

        uint32_t stge = sbase + (it % NSTAGE) * STAGE_BYTES;
        uint32_t aB = stge + aOff;
        uint32_t bB = stge + bOff;

        #pragma unroll
        for (int k8 = 0; k8 < 4; k8++) {
            uint32_t a[4][4], b[4][2];
            #pragma unroll
            for (int mf = 0; mf < 4; mf++)
                ldsm4(a[mf], aB + mf * (16 * LDA * 4) + k8 * 32);
            #pragma unroll
            for (int p = 0; p < 2; p++) {
                uint32_t r[4];
                ldsm4(r, bB + p * (16 * LDA * 4) + k8 * 32);
                b[2*p][0]   = r[0]; b[2*p][1]   = r[1];
                b[2*p+1][0] = r[2]; b[2*p+1][1] = r[3];
            }
            #pragma unroll
            for (int mf = 0; mf < 4; mf++)
                #pragma unroll
                for (int nf = 0; nf < 4; nf++)
                    mma_tf32(c[mf][nf], a[mf], b[nf]);
        }
    }

    #pragma unroll
    for (int mf = 0; mf < 4; mf++) {
        int row0 = mbase + wm * 64 + mf * 16 + grp;
        #pragma unroll
        for (int nf = 0; nf < 4; nf++) {
            int col = nbase + wn * 32 + nf * 8 + 2 * tig;
            *(float2*)(C + (size_t)row0 * HDIM + col)       = make_float2(c[mf][nf].x, c[mf][nf].y);
            *(float2*)(C + (size_t)(row0 + 8) * HDIM + col) = make_float2(c[mf][nf].z, c[mf][nf].w);
        }
    }
}

// ---------------- kernel 3: proj via mma ----------------
__global__ __launch_bounds__(256) void proj_mma_kernel(
    const float* __restrict__ x,
    const float* __restrict__ iA,   // [K, R]
    const float* __restrict__ iB)   // [R, K]
{
    int tid  = threadIdx.x;
    int wid  = tid >> 5;
    int lane = tid & 31;
    int grp  = lane >> 2;
    int tig  = lane & 3;

    int rowbase = blockIdx.x * 128;
    const float* Xb = x   + (size_t)rowbase * KDIM;
    const float* Vb = g_V + (size_t)rowbase * KDIM;

    float4 cI[2], cE[2];
    cI[0] = make_float4(0,0,0,0); cI[1] = make_float4(0,0,0,0);
    cE[0] = make_float4(0,0,0,0); cE[1] = make_float4(0,0,0,0);

    auto load_stage = [&](int stage, int k0) {
        uint32_t sx = smem_u32(sm_dyn) + stage * (2 * PROJ_STAGE * 4);
        uint32_t sv = sx + PROJ_STAGE * 4;
        #pragma unroll
        for (int i = 0; i < 4; i++) {
            int idx = tid + i * 256;
            int row = idx >> 3, seg = idx & 7;
            cp16(sx + row * (PLDA * 4) + seg * 16, Xb + (size_t)row * KDIM + k0 + seg * 4);
        }
        #pragma unroll
        for (int i = 0; i < 4; i++) {
            int idx = tid + i * 256;
            int row = idx >> 3, seg = idx & 7;
            cp16(sv + row * (PLDA * 4) + seg * 16, Vb + (size_t)row * KDIM + k0 + seg * 4);
        }
        asm volatile("cp.async.commit_group;" ::: "memory");
    };

    load_stage(0, 0);

    for (int it = 0; it < NIT; it++) {
        int k0 = it * BK;
        uint32_t bI[4][2][2], bE[4][2][2];
        #pragma unroll
        for (int kk = 0; kk < 4; kk++) {
            int kidx = k0 + kk * 8 + tig;
            #pragma unroll
            for (int nf = 0; nf < 2; nf++) {
                int n = nf * 8 + grp;
                bI[kk][nf][0] = __float_as_uint(iB[(size_t)n * KDIM + kidx]);
                bI[kk][nf][1] = __float_as_uint(iB[(size_t)n * KDIM + kidx + 4]);
                bE[kk][nf][0] = __float_as_uint(iA[(size_t)kidx * RANK + n]);
                bE[kk][nf][1] = __float_as_uint(iA[(size_t)(kidx + 4) * RANK + n]);
            }
        }

        asm volatile("cp.async.wait_group 0;" ::: "memory");
        __syncthreads();
        if (it + 1 < NIT) load_stage((it + 1) & 1, k0 + BK);

        const float* sx = sm_dyn + (it & 1) * (2 * PROJ_STAGE);
        const float* sv = sx + PROJ_STAGE;

        #pragma unroll
        for (int kk = 0; kk < 4; kk++) {
            uint32_t ax[4], av[4];
            const float* px = sx + (wid * 16 + grp) * PLDA + kk * 8 + tig;
            ax[0] = __float_as_uint(px[0]);
            ax[1] = __float_as_uint(px[8 * PLDA]);
            ax[2] = __float_as_uint(px[4]);
            ax[3] = __float_as_uint(px[8 * PLDA + 4]);
            const float* pv = sv + (wid * 16 + grp) * PLDA + kk * 8 + tig;
            av[0] = __float_as_uint(pv[0]);
            av[1] = __float_as_uint(pv[8 * PLDA]);
            av[2] = __float_as_uint(pv[4]);
            av[3] = __float_as_uint(pv[8 * PLDA + 4]);
            #pragma unroll
            for (int nf = 0; nf < 2; nf++) {
                mma_tf32(cI[nf], ax, bI[kk][nf]);
                mma_tf32(cE[nf], av, bE[kk][nf]);
            }
        }
        __syncthreads();
    }

    int row = rowbase + wid * 16 + grp;
    #pragma unroll
    for (int nf = 0; nf < 2; nf++) {
        int col = nf * 8 + 2 * tig;
        *(float2*)(g_proj_in  + (size_t)row * RANK + col)       = make_float2(cI[nf].x, cI[nf].y);
        *(float2*)(g_proj_in  + (size_t)(row + 8) * RANK + col) = make_float2(cI[nf].z, cI[nf].w);
        *(float2*)(g_proj_err + (size_t)row * RANK + col)       = make_float2(cE[nf].x, cE[nf].y);
        *(float2*)(g_proj_err + (size_t)(row + 8) * RANK + col) = make_float2(cE[nf].z, cE[nf].w);
    }
}

// ---------------- kernel 4: dA / dB (256-thread blocks) ----------------
__global__ __launch_bounds__(256) void delta_kernel(const float* __restrict__ x)
{
    int c = blockIdx.x, part = blockIdx.y, mode = blockIdx.z;
    __shared__ float sp[CHUNK][RANK];
    const float* P = (mode == 0 ? g_proj_in : g_proj_err) + (size_t)c * CHUNK * RANK;
    for (int i = threadIdx.x; i < CHUNK * RANK; i += 256)
        sp[i >> 4][i & 15] = P[i];
    __syncthreads();

    int col = part * 256 + threadIdx.x;
    const float* src = (mode == 0 ? g_V : x) + (size_t)c * CHUNK * KDIM + col;

    float acc[RANK];
    #pragma unroll
    for (int r = 0; r < RANK; r++) acc[r] = 0.f;

    #pragma unroll 4
    for (int i = 0; i < CHUNK; i++) {
        float v = src[(size_t)i * KDIM];
        #pragma unroll
        for (int r = 0; r < RANK; r++) acc[r] += v * sp[i][r];
    }

    if (mode == 0) {
        float* d = g_dA + (size_t)c * HDIM * RANK + (size_t)col * RANK;
        #pragma unroll
        for (int r = 0; r < RANK; r += 4)
            *(float4*)(d + r) = make_float4(acc[r], acc[r+1], acc[r+2], acc[r+3]);
    } else {
        float* d = g_dB + (size_t)c * RANK * KDIM + col;
        #pragma unroll
        for (int r = 0; r < RANK; r++) d[(size_t)r * KDIM] = acc[r];
    }
}

// ---------------- kernel 5: exclusive cumsum over chunks ----------------
__global__ __launch_bounds__(256) void cumsum_kernel()
{
    int e = blockIdx.x * 256 + threadIdx.x;
    int b = blockIdx.y;
    float* base = blockIdx.z ? g_dB : g_dA;
    float run = 0.f;
    #pragma unroll
    for (int j = 0; j < NCH; j++) {
        size_t off = ((size_t)(b * NCH + j)) * (HDIM * RANK) + e;
        float t = base[off];
        base[off] = run;
        run += t;
    }
}

// ---------------- kernel 6: fused clip + effective weights ----------------
__global__ __launch_bounds__(256) void clip_eff_kernel(
    const float* __restrict__ iA, const float* __restrict__ iB)
{
    int c = blockIdx.x;
    const float* A = g_dA + (size_t)c * (HDIM * RANK);
    const float* B = g_dB + (size_t)c * (RANK * KDIM);
    float s = 0.f;
    for (int i = threadIdx.x; i < HDIM * RANK; i += 256) {
        float a = A[i]; s += a * a;
        float b = B[i]; s += b * b;
    }
    #pragma unroll
    for (int o = 16; o; o >>= 1) s += __shfl_xor_sync(0xffffffffu, s, o);
    __shared__ float sm[8];
    __shared__ float s_coef;
    int w = threadIdx.x >> 5, l = threadIdx.x & 31;
    if (!l) sm[w] = s;
    __syncthreads();
    if (threadIdx.x == 0) {
        float t = 0.f;
        #pragma unroll
        for (int i = 0; i < 8; i++) t += sm[i];
        float norm = LRC * sqrtf(t);
        s_coef = LRC * fminf(1.0f, CLIP / (norm + 1e-6f));
    }
    __syncthreads();
    float sc = s_coef;
    float* Ae = g_Aeff + (size_t)c * (HDIM * RANK);
    float* Be = g_Beff + (size_t)c * (RANK * KDIM);
    for (int i = threadIdx.x; i < HDIM * RANK; i += 256) {
        Ae[i] = iA[i] - sc * A[i];
        Be[i] = iB[i] - sc * B[i];
    }
}

// ---------------- kernel 7: mid = Z @ B_eff^T via mma ----------------
__global__ __launch_bounds__(256) void mid_mma_kernel(const float* __restrict__ x)
{
    int tid  = threadIdx.x;
    int wid  = tid >> 5;
    int lane = tid & 31;
    int grp  = lane >> 2;
    int tig  = lane & 3;

    int rowbase = blockIdx.x * 128;
    int c = rowbase >> 8;
    const float* Xb = x + (size_t)rowbase * KDIM;
    const float* Be = g_Beff + (size_t)c * (RANK * KDIM);

    float4 cI[2];
    cI[0] = make_float4(0,0,0,0); cI[1] = make_float4(0,0,0,0);

    auto load_stage = [&](int stage, int k0) {
        uint32_t sx = smem_u32(sm_dyn) + stage * (PROJ_STAGE * 4);
        #pragma unroll
        for (int i = 0; i < 4; i++) {
            int idx = tid + i * 256;
            int row = idx >> 3, seg = idx & 7;
            cp16(sx + row * (PLDA * 4) + seg * 16, Xb + (size_t)row * KDIM + k0 + seg * 4);
        }
        asm volatile("cp.async.commit_group;" ::: "memory");
    };

    load_stage(0, 0);

    for (int it = 0; it < NIT; it++) {
        int k0 = it * BK;
        uint32_t bI[4][2][2];
        #pragma unroll
        for (int kk = 0; kk < 4; kk++) {
            int kidx = k0 + kk * 8 + tig;
            #pragma unroll
            for (int nf = 0; nf < 2; nf++) {
                int n = nf * 8 + grp;
                bI[kk][nf][0] = __float_as_uint(Be[(size_t)n * KDIM + kidx]);
                bI[kk][nf][1] = __float_as_uint(Be[(size_t)n * KDIM + kidx + 4]);
            }
        }

        asm volatile("cp.async.wait_group 0;" ::: "memory");
        __syncthreads();
        if (it + 1 < NIT) load_stage((it + 1) & 1, k0 + BK);

        const float* sx = sm_dyn + (it & 1) * PROJ_STAGE;

        #pragma unroll
        for (int kk = 0; kk < 4; kk++) {
            uint32_t ax[4];
            const float* px = sx + (wid * 16 + grp) * PLDA + kk * 8 + tig;
            ax[0] = __float_as_uint(px[0]);
            ax[1] = __float_as_uint(px[8 * PLDA]);
            ax[2] = __float_as_uint(px[4]);
            ax[3] = __float_as_uint(px[8 * PLDA + 4]);
            #pragma unroll
            for (int nf = 0; nf < 2; nf++)
                mma_tf32(cI[nf], ax, bI[kk][nf]);
        }
        __syncthreads();
    }

    int row = rowbase + wid * 16 + grp;
    #pragma unroll
    for (int nf = 0; nf < 2; nf++) {
        int col = nf * 8 + 2 * tig;
        *(float2*)(g_mid + (size_t)row * RANK + col)       = make_float2(cI[nf].x, cI[nf].y);
        *(float2*)(g_mid + (size_t)(row + 8) * RANK + col) = make_float2(cI[nf].z, cI[nf].w);
    }
}

// ---------------- kernel 8: lora apply ----------------
__global__ __launch_bounds__(256) void lora_apply_kernel(float* __restrict__ out)
{
    int c = blockIdx.y;
    int g = blockIdx.x;
    int row0 = c * CHUNK + g * 64;
    int h0 = threadIdx.x * 4;

    __shared__ float smid[64][RANK];
    for (int i = threadIdx.x; i < 64 * RANK; i += 256)
        smid[i >> 4][i & 15] = g_mid[(size_t)row0 * RANK + i];

    float4 ae[4][4];
    const float* Ae = g_Aeff + (size_t)c * (HDIM * RANK);
    #pragma unroll
    for (int j = 0; j < 4; j++)
        #pragma unroll
        for (int q = 0; q < 4; q++)
            ae[j][q] = *(const float4*)(Ae + (size_t)(h0 + j) * RANK + q * 4);
    __syncthreads();

    for (int rr = 0; rr < 64; rr++) {
        const float* m = smid[rr];
        float4 m0 = *(const float4*)(m);
        float4 m1 = *(const float4*)(m + 4);
        float4 m2 = *(const float4*)(m + 8);
        float4 m3 = *(const float4*)(m + 12);

        float v[4];
        #pragma unroll
        for (int j = 0; j < 4; j++) {
            v[j] = m0.x * ae[j][0].x + m0.y * ae[j][0].y + m0.z * ae[j][0].z + m0.w * ae[j][0].w
                 + m1.x * ae[j][1].x + m1.y * ae[j][1].y + m1.z * ae[j][1].z + m1.w * ae[j][1].w
                 + m2.x * ae[j][2].x + m2.y * ae[j][2].y + m2.z * ae[j][2].z + m2.w * ae[j][2].w
                 + m3.x * ae[j][3].x + m3.y * ae[j][3].y + m3.z * ae[j][3].z + m3.w * ae[j][3].w;
        }
        float4* op = (float4*)(out + (size_t)(row0 + rr) * HDIM + h0);
        float4 o = *op;
        o.x += SCALE * v[0];
        o.y += SCALE * v[1];
        o.z += SCALE * v[2];
        o.w += SCALE * v[3];
        *op = o;
    }
}

// ---------------- launch ----------------
extern "C" void kernel_launch(void* const* d_in, const int* in_sizes, int n_in,
                              void* d_out, int out_size)
{
    const float* x   = (const float*)d_in[0];
    const float* Wb  = (const float*)d_in[1];
    const float* iA  = (const float*)d_in[2];
    const float* iB  = (const float*)d_in[3];
    const float* gam = (const float*)d_in[4];
    const float* bet = (const float*)d_in[5];
    const float* Wp  = (const float*)d_in[6];
    float* out = (float*)d_out;

    cudaFuncSetAttribute(gemm_tf32,       cudaFuncAttributeMaxDynamicSharedMemorySize, SMEM_GEMM);
    cudaFuncSetAttribute(proj_mma_kernel, cudaFuncAttributeMaxDynamicSharedMemorySize, SMEM_PROJ);
    cudaFuncSetAttribute(mid_mma_kernel,  cudaFuncAttributeMaxDynamicSharedMemorySize, SMEM_MID);

    ln_shift_kernel<<<M_TOT, 256>>>(x, gam, bet);

    dim3 gg(HDIM / BN, M_TOT / BM, 2);
    gemm_tf32<<<gg, 256, SMEM_GEMM>>>(x, Wb, Wp, out);   // z=0: base_out, z=1: V

    proj_mma_kernel<<<M_TOT / 128, 256, SMEM_PROJ>>>(x, iA, iB);
    delta_kernel<<<dim3(NBC, KDIM / 256, 2), 256>>>(x);
    cumsum_kernel<<<dim3((HDIM * RANK) / 256, NBATCH, 2), 256>>>();
    clip_eff_kernel<<<NBC, 256>>>(iA, iB);
    mid_mma_kernel<<<M_TOT / 128, 256, SMEM_MID>>>(x);
    lora_apply_kernel<<<dim3(4, NBC), 256>>>(out);
}

// round 10
// speedup vs baseline: 2.9257x; 1.0079x over previous
#include <cuda_runtime.h>
#include <math.h>
#include <stdint.h>

// ---------------- problem constants ----------------
#define M_TOT   16384
#define SEQ     8192
#define KDIM    1024
#define HDIM    1024
#define RANK    16
#define CHUNK   256
#define NCH     32
#define NBATCH  2
#define NBC     64
#define LRC     0.02f
#define SCALE   2.0f
#define CLIP    1.0f
#define LN_EPS  1e-5f

// ---------------- GEMM tiling ----------------
#define BM 128
#define BN 128
#define BK 32
#define LDA 36
#define STAGE_FLOATS ((BM + BN) * LDA)
#define STAGE_BYTES  (STAGE_FLOATS * 4)
#define NSTAGE 3
#define SMEM_GEMM (NSTAGE * STAGE_BYTES)         // 110592 B
#define NIT (KDIM / BK)

// proj/mid mma kernels
#define PLDA 36
#define PROJ_STAGE (128 * PLDA)
#define SMEM_PROJ (2 * 2 * PROJ_STAGE * 4)
#define SMEM_MID  (2 * PROJ_STAGE * 4)

// ---------------- device scratch ----------------
__device__ __align__(128) float g_shifted[M_TOT * KDIM];
__device__ __align__(128) float g_V      [M_TOT * KDIM];
__device__ __align__(128) float g_proj_in [NBC * CHUNK * RANK];
__device__ __align__(128) float g_proj_err[NBC * CHUNK * RANK];
__device__ __align__(128) float g_dA  [NBC * HDIM * RANK];
__device__ __align__(128) float g_dB  [NBC * RANK * KDIM];
__device__ __align__(128) float g_Aeff[NBC * HDIM * RANK];
__device__ __align__(128) float g_Beff[NBC * RANK * KDIM];
__device__ __align__(128) float g_mid [M_TOT * RANK];

// ---------------- helpers ----------------
__device__ __forceinline__ uint32_t smem_u32(const void* p) {
    uint32_t a;
    asm("{ .reg .u64 t; cvta.to.shared.u64 t, %1; cvt.u32.u64 %0, t; }" : "=r"(a) : "l"(p));
    return a;
}
__device__ __forceinline__ void cp16(uint32_t d, const void* s) {
    asm volatile("cp.async.cg.shared.global [%0], [%1], 16;" :: "r"(d), "l"(s));
}
__device__ __forceinline__ void mma_tf32(float4& c, const uint32_t a[4], const uint32_t b[2]) {
    asm volatile(
        "mma.sync.aligned.m16n8k8.row.col.f32.tf32.tf32.f32 "
        "{%0,%1,%2,%3}, {%4,%5,%6,%7}, {%8,%9}, {%0,%1,%2,%3};"
        : "+f"(c.x), "+f"(c.y), "+f"(c.z), "+f"(c.w)
        : "r"(a[0]), "r"(a[1]), "r"(a[2]), "r"(a[3]), "r"(b[0]), "r"(b[1]));
}
__device__ __forceinline__ void ldsm4(uint32_t r[4], uint32_t addr) {
    asm volatile("ldmatrix.sync.aligned.m8n8.x4.shared.b16 {%0,%1,%2,%3}, [%4];"
                 : "=r"(r[0]), "=r"(r[1]), "=r"(r[2]), "=r"(r[3]) : "r"(addr));
}

// ---------------- kernel 1: LayerNorm + left shift ----------------
__global__ __launch_bounds__(256) void ln_shift_kernel(
    const float* __restrict__ x,
    const float* __restrict__ gam,
    const float* __restrict__ bet)
{
    int row = blockIdx.x;
    int s   = row & (SEQ - 1);
    const float4* xr = (const float4*)(x + (size_t)row * KDIM);
    float4 v = xr[threadIdx.x];

    float sum = v.x + v.y + v.z + v.w;
    float ssq = v.x*v.x + v.y*v.y + v.z*v.z + v.w*v.w;
    #pragma unroll
    for (int o = 16; o; o >>= 1) {
        sum += __shfl_xor_sync(0xffffffffu, sum, o);
        ssq += __shfl_xor_sync(0xffffffffu, ssq, o);
    }
    __shared__ float s1[8], s2[8];
    int w = threadIdx.x >> 5, l = threadIdx.x & 31;
    if (!l) { s1[w] = sum; s2[w] = ssq; }
    __syncthreads();
    if (threadIdx.x == 0) {
        float a = 0.f, b = 0.f;
        #pragma unroll
        for (int i = 0; i < 8; i++) { a += s1[i]; b += s2[i]; }
        s1[0] = a; s2[0] = b;
    }
    __syncthreads();
    float mu   = s1[0] * (1.0f / KDIM);
    float var  = s2[0] * (1.0f / KDIM) - mu * mu;
    float rstd = rsqrtf(var + LN_EPS);

    if (s == 0) {
        float4* d = (float4*)(g_shifted + ((size_t)row + SEQ - 1) * KDIM);
        d[threadIdx.x] = make_float4(0.f, 0.f, 0.f, 0.f);
    } else {
        float4 g4 = ((const float4*)gam)[threadIdx.x];
        float4 b4 = ((const float4*)bet)[threadIdx.x];
        float4 o;
        o.x = (v.x - mu) * rstd * g4.x + b4.x;
        o.y = (v.y - mu) * rstd * g4.y + b4.y;
        o.z = (v.z - mu) * rstd * g4.z + b4.z;
        o.w = (v.w - mu) * rstd * g4.w + b4.w;
        float4* d = (float4*)(g_shifted + (size_t)(row - 1) * KDIM);
        d[threadIdx.x] = o;
    }
}

// ---------------- kernel 2: TF32 mma GEMM (combined z=2 launch) ----------------
extern __shared__ float sm_dyn[];

__device__ __forceinline__ void gemm_load_stage(
    uint32_t sbase, int stage, const float* Ab, const float* Wb, int k0, int tid)
{
    uint32_t sa = sbase + stage * STAGE_BYTES;
    uint32_t sw = sa + BM * LDA * 4;
    #pragma unroll
    for (int i = 0; i < 4; i++) {
        int idx = tid + i * 256;
        int row = idx >> 3, seg = idx & 7;
        cp16(sa + row * (LDA * 4) + seg * 16, Ab + (size_t)row * KDIM + k0 + seg * 4);
    }
    #pragma unroll
    for (int i = 0; i < 4; i++) {
        int idx = tid + i * 256;
        int row = idx >> 3, seg = idx & 7;
        cp16(sw + row * (LDA * 4) + seg * 16, Wb + (size_t)row * KDIM + k0 + seg * 4);
    }
    asm volatile("cp.async.commit_group;" ::: "memory");
}

__global__ __launch_bounds__(256, 2) void gemm_tf32(
    const float* __restrict__ x, const float* __restrict__ Wbm,
    const float* __restrict__ Wpm, float* __restrict__ out)
{
    const float* A;
    const float* W;
    float* C;
    if (blockIdx.z == 0) { A = x;         W = Wbm; C = out; }
    else                 { A = g_shifted; W = Wpm; C = g_V; }

    int tid  = threadIdx.x;
    int wid  = tid >> 5;
    int lane = tid & 31;
    int grp  = lane >> 2;
    int tig  = lane & 3;
    int wm   = wid & 1;
    int wn   = wid >> 1;

    int mbase = blockIdx.y * BM;
    int nbase = blockIdx.x * BN;
    const float* Ab = A + (size_t)mbase * KDIM;
    const float* Wb = W + (size_t)nbase * KDIM;

    uint32_t sbase = smem_u32(sm_dyn);

    int quad = lane >> 3, lr = lane & 7;
    uint32_t aOff = ((uint32_t)(wm * 64 + ((quad & 1) << 3) + lr) * LDA +
                     ((quad >> 1) << 2)) * 4;
    uint32_t bOff = (uint32_t)(BM * LDA * 4) +
                    ((uint32_t)(wn * 32 + ((quad >> 1) << 3) + lr) * LDA +
                     ((quad & 1) << 2)) * 4;

    float4 c[4][4];
    #pragma unroll
    for (int i = 0; i < 4; i++)
        #pragma unroll
        for (int j = 0; j < 4; j++) c[i][j] = make_float4(0.f, 0.f, 0.f, 0.f);

    gemm_load_stage(sbase, 0, Ab, Wb, 0, tid);
    gemm_load_stage(sbase, 1, Ab, Wb, BK, tid);

    for (int it = 0; it < NIT; it++) {
        if (it == NIT - 1) asm volatile("cp.async.wait_group 0;" ::: "memory");
        else               asm volatile("cp.async.wait_group 1;" ::: "memory");
        __syncthreads();
        if (it + 2 < NIT)
            gemm_load_stage(sbase, (it + 2) % NSTAGE, Ab, Wb, (it + 2) * BK, tid);

        uint32_t stge = sbase + (it % NSTAGE) * STAGE_BYTES;
        uint32_t aB = stge + aOff;
        uint32_t bB = stge + bOff;

        #pragma unroll
        for (int k8 = 0; k8 < 4; k8++) {
            uint32_t a[4][4], b[4][2];
            #pragma unroll
            for (int mf = 0; mf < 4; mf++)
                ldsm4(a[mf], aB + mf * (16 * LDA * 4) + k8 * 32);
            #pragma unroll
            for (int p = 0; p < 2; p++) {
                uint32_t r[4];
                ldsm4(r, bB + p * (16 * LDA * 4) + k8 * 32);
                b[2*p][0]   = r[0]; b[2*p][1]   = r[1];
                b[2*p+1][0] = r[2]; b[2*p+1][1] = r[3];
            }
            #pragma unroll
            for (int mf = 0; mf < 4; mf++)
                #pragma unroll
                for (int nf = 0; nf < 4; nf++)
                    mma_tf32(c[mf][nf], a[mf], b[nf]);
        }
    }

    #pragma unroll
    for (int mf = 0; mf < 4; mf++) {
        int row0 = mbase + wm * 64 + mf * 16 + grp;
        #pragma unroll
        for (int nf = 0; nf < 4; nf++) {
            int col = nbase + wn * 32 + nf * 8 + 2 * tig;
            *(float2*)(C + (size_t)row0 * HDIM + col)       = make_float2(c[mf][nf].x, c[mf][nf].y);
            *(float2*)(C + (size_t)(row0 + 8) * HDIM + col) = make_float2(c[mf][nf].z, c[mf][nf].w);
        }
    }
}

// ---------------- kernel 3: proj via mma ----------------
__global__ __launch_bounds__(256) void proj_mma_kernel(
    const float* __restrict__ x,
    const float* __restrict__ iA,
    const float* __restrict__ iB)
{
    int tid  = threadIdx.x;
    int wid  = tid >> 5;
    int lane = tid & 31;
    int grp  = lane >> 2;
    int tig  = lane & 3;

    int rowbase = blockIdx.x * 128;
    const float* Xb = x   + (size_t)rowbase * KDIM;
    const float* Vb = g_V + (size_t)rowbase * KDIM;

    float4 cI[2], cE[2];
    cI[0] = make_float4(0,0,0,0); cI[1] = make_float4(0,0,0,0);
    cE[0] = make_float4(0,0,0,0); cE[1] = make_float4(0,0,0,0);

    auto load_stage = [&](int stage, int k0) {
        uint32_t sx = smem_u32(sm_dyn) + stage * (2 * PROJ_STAGE * 4);
        uint32_t sv = sx + PROJ_STAGE * 4;
        #pragma unroll
        for (int i = 0; i < 4; i++) {
            int idx = tid + i * 256;
            int row = idx >> 3, seg = idx & 7;
            cp16(sx + row * (PLDA * 4) + seg * 16, Xb + (size_t)row * KDIM + k0 + seg * 4);
        }
        #pragma unroll
        for (int i = 0; i < 4; i++) {
            int idx = tid + i * 256;
            int row = idx >> 3, seg = idx & 7;
            cp16(sv + row * (PLDA * 4) + seg * 16, Vb + (size_t)row * KDIM + k0 + seg * 4);
        }
        asm volatile("cp.async.commit_group;" ::: "memory");
    };

    load_stage(0, 0);

    for (int it = 0; it < NIT; it++) {
        int k0 = it * BK;
        uint32_t bI[4][2][2], bE[4][2][2];
        #pragma unroll
        for (int kk = 0; kk < 4; kk++) {
            int kidx = k0 + kk * 8 + tig;
            #pragma unroll
            for (int nf = 0; nf < 2; nf++) {
                int n = nf * 8 + grp;
                bI[kk][nf][0] = __float_as_uint(iB[(size_t)n * KDIM + kidx]);
                bI[kk][nf][1] = __float_as_uint(iB[(size_t)n * KDIM + kidx + 4]);
                bE[kk][nf][0] = __float_as_uint(iA[(size_t)kidx * RANK + n]);
                bE[kk][nf][1] = __float_as_uint(iA[(size_t)(kidx + 4) * RANK + n]);
            }
        }

        asm volatile("cp.async.wait_group 0;" ::: "memory");
        __syncthreads();
        if (it + 1 < NIT) load_stage((it + 1) & 1, k0 + BK);

        const float* sx = sm_dyn + (it & 1) * (2 * PROJ_STAGE);
        const float* sv = sx + PROJ_STAGE;

        #pragma unroll
        for (int kk = 0; kk < 4; kk++) {
            uint32_t ax[4], av[4];
            const float* px = sx + (wid * 16 + grp) * PLDA + kk * 8 + tig;
            ax[0] = __float_as_uint(px[0]);
            ax[1] = __float_as_uint(px[8 * PLDA]);
            ax[2] = __float_as_uint(px[4]);
            ax[3] = __float_as_uint(px[8 * PLDA + 4]);
            const float* pv = sv + (wid * 16 + grp) * PLDA + kk * 8 + tig;
            av[0] = __float_as_uint(pv[0]);
            av[1] = __float_as_uint(pv[8 * PLDA]);
            av[2] = __float_as_uint(pv[4]);
            av[3] = __float_as_uint(pv[8 * PLDA + 4]);
            #pragma unroll
            for (int nf = 0; nf < 2; nf++) {
                mma_tf32(cI[nf], ax, bI[kk][nf]);
                mma_tf32(cE[nf], av, bE[kk][nf]);
            }
        }
        __syncthreads();
    }

    int row = rowbase + wid * 16 + grp;
    #pragma unroll
    for (int nf = 0; nf < 2; nf++) {
        int col = nf * 8 + 2 * tig;
        *(float2*)(g_proj_in  + (size_t)row * RANK + col)       = make_float2(cI[nf].x, cI[nf].y);
        *(float2*)(g_proj_in  + (size_t)(row + 8) * RANK + col) = make_float2(cI[nf].z, cI[nf].w);
        *(float2*)(g_proj_err + (size_t)row * RANK + col)       = make_float2(cE[nf].x, cE[nf].y);
        *(float2*)(g_proj_err + (size_t)(row + 8) * RANK + col) = make_float2(cE[nf].z, cE[nf].w);
    }
}

// ---------------- kernel 4: dA / dB (128-thread blocks) ----------------
__global__ __launch_bounds__(128) void delta_kernel(const float* __restrict__ x)
{
    int c = blockIdx.x, part = blockIdx.y, mode = blockIdx.z;
    __shared__ float sp[CHUNK][RANK];
    const float* P = (mode == 0 ? g_proj_in : g_proj_err) + (size_t)c * CHUNK * RANK;
    for (int i = threadIdx.x; i < CHUNK * RANK; i += 128)
        sp[i >> 4][i & 15] = P[i];
    __syncthreads();

    int col = part * 128 + threadIdx.x;
    const float* src = (mode == 0 ? g_V : x) + (size_t)c * CHUNK * KDIM + col;

    float acc[RANK];
    #pragma unroll
    for (int r = 0; r < RANK; r++) acc[r] = 0.f;

    #pragma unroll 4
    for (int i = 0; i < CHUNK; i++) {
        float v = src[(size_t)i * KDIM];
        #pragma unroll
        for (int r = 0; r < RANK; r++) acc[r] += v * sp[i][r];
    }

    if (mode == 0) {
        float* d = g_dA + (size_t)c * HDIM * RANK + (size_t)col * RANK;
        #pragma unroll
        for (int r = 0; r < RANK; r += 4)
            *(float4*)(d + r) = make_float4(acc[r], acc[r+1], acc[r+2], acc[r+3]);
    } else {
        float* d = g_dB + (size_t)c * RANK * KDIM + col;
        #pragma unroll
        for (int r = 0; r < RANK; r++) d[(size_t)r * KDIM] = acc[r];
    }
}

// ---------------- kernel 5: exclusive cumsum over chunks ----------------
__global__ __launch_bounds__(256) void cumsum_kernel()
{
    int e = blockIdx.x * 256 + threadIdx.x;
    int b = blockIdx.y;
    float* base = blockIdx.z ? g_dB : g_dA;
    float run = 0.f;
    #pragma unroll
    for (int j = 0; j < NCH; j++) {
        size_t off = ((size_t)(b * NCH + j)) * (HDIM * RANK) + e;
        float t = base[off];
        base[off] = run;
        run += t;
    }
}

// ---------------- kernel 6: fused clip + effective weights ----------------
__global__ __launch_bounds__(256) void clip_eff_kernel(
    const float* __restrict__ iA, const float* __restrict__ iB)
{
    int c = blockIdx.x;
    const float* A = g_dA + (size_t)c * (HDIM * RANK);
    const float* B = g_dB + (size_t)c * (RANK * KDIM);
    float s = 0.f;
    for (int i = threadIdx.x; i < HDIM * RANK; i += 256) {
        float a = A[i]; s += a * a;
        float b = B[i]; s += b * b;
    }
    #pragma unroll
    for (int o = 16; o; o >>= 1) s += __shfl_xor_sync(0xffffffffu, s, o);
    __shared__ float sm[8];
    __shared__ float s_coef;
    int w = threadIdx.x >> 5, l = threadIdx.x & 31;
    if (!l) sm[w] = s;
    __syncthreads();
    if (threadIdx.x == 0) {
        float t = 0.f;
        #pragma unroll
        for (int i = 0; i < 8; i++) t += sm[i];
        float norm = LRC * sqrtf(t);
        s_coef = LRC * fminf(1.0f, CLIP / (norm + 1e-6f));
    }
    __syncthreads();
    float sc = s_coef;
    float* Ae = g_Aeff + (size_t)c * (HDIM * RANK);
    float* Be = g_Beff + (size_t)c * (RANK * KDIM);
    for (int i = threadIdx.x; i < HDIM * RANK; i += 256) {
        Ae[i] = iA[i] - sc * A[i];
        Be[i] = iB[i] - sc * B[i];
    }
}

// ---------------- kernel 7: mid = Z @ B_eff^T via mma ----------------
__global__ __launch_bounds__(256) void mid_mma_kernel(const float* __restrict__ x)
{
    int tid  = threadIdx.x;
    int wid  = tid >> 5;
    int lane = tid & 31;
    int grp  = lane >> 2;
    int tig  = lane & 3;

    int rowbase = blockIdx.x * 128;
    int c = rowbase >> 8;
    const float* Xb = x + (size_t)rowbase * KDIM;
    const float* Be = g_Beff + (size_t)c * (RANK * KDIM);

    float4 cI[2];
    cI[0] = make_float4(0,0,0,0); cI[1] = make_float4(0,0,0,0);

    auto load_stage = [&](int stage, int k0) {
        uint32_t sx = smem_u32(sm_dyn) + stage * (PROJ_STAGE * 4);
        #pragma unroll
        for (int i = 0; i < 4; i++) {
            int idx = tid + i * 256;
            int row = idx >> 3, seg = idx & 7;
            cp16(sx + row * (PLDA * 4) + seg * 16, Xb + (size_t)row * KDIM + k0 + seg * 4);
        }
        asm volatile("cp.async.commit_group;" ::: "memory");
    };

    load_stage(0, 0);

    for (int it = 0; it < NIT; it++) {
        int k0 = it * BK;
        uint32_t bI[4][2][2];
        #pragma unroll
        for (int kk = 0; kk < 4; kk++) {
            int kidx = k0 + kk * 8 + tig;
            #pragma unroll
            for (int nf = 0; nf < 2; nf++) {
                int n = nf * 8 + grp;
                bI[kk][nf][0] = __float_as_uint(Be[(size_t)n * KDIM + kidx]);
                bI[kk][nf][1] = __float_as_uint(Be[(size_t)n * KDIM + kidx + 4]);
            }
        }

        asm volatile("cp.async.wait_group 0;" ::: "memory");
        __syncthreads();
        if (it + 1 < NIT) load_stage((it + 1) & 1, k0 + BK);

        const float* sx = sm_dyn + (it & 1) * PROJ_STAGE;

        #pragma unroll
        for (int kk = 0; kk < 4; kk++) {
            uint32_t ax[4];
            const float* px = sx + (wid * 16 + grp) * PLDA + kk * 8 + tig;
            ax[0] = __float_as_uint(px[0]);
            ax[1] = __float_as_uint(px[8 * PLDA]);
            ax[2] = __float_as_uint(px[4]);
            ax[3] = __float_as_uint(px[8 * PLDA + 4]);
            #pragma unroll
            for (int nf = 0; nf < 2; nf++)
                mma_tf32(cI[nf], ax, bI[kk][nf]);
        }
        __syncthreads();
    }

    int row = rowbase + wid * 16 + grp;
    #pragma unroll
    for (int nf = 0; nf < 2; nf++) {
        int col = nf * 8 + 2 * tig;
        *(float2*)(g_mid + (size_t)row * RANK + col)       = make_float2(cI[nf].x, cI[nf].y);
        *(float2*)(g_mid + (size_t)(row + 8) * RANK + col) = make_float2(cI[nf].z, cI[nf].w);
    }
}

// ---------------- kernel 8: lora apply ----------------
__global__ __launch_bounds__(256) void lora_apply_kernel(float* __restrict__ out)
{
    int c = blockIdx.y;
    int g = blockIdx.x;
    int row0 = c * CHUNK + g * 64;
    int h0 = threadIdx.x * 4;

    __shared__ float smid[64][RANK];
    for (int i = threadIdx.x; i < 64 * RANK; i += 256)
        smid[i >> 4][i & 15] = g_mid[(size_t)row0 * RANK + i];

    float4 ae[4][4];
    const float* Ae = g_Aeff + (size_t)c * (HDIM * RANK);
    #pragma unroll
    for (int j = 0; j < 4; j++)
        #pragma unroll
        for (int q = 0; q < 4; q++)
            ae[j][q] = *(const float4*)(Ae + (size_t)(h0 + j) * RANK + q * 4);
    __syncthreads();

    for (int rr = 0; rr < 64; rr++) {
        const float* m = smid[rr];
        float4 m0 = *(const float4*)(m);
        float4 m1 = *(const float4*)(m + 4);
        float4 m2 = *(const float4*)(m + 8);
        float4 m3 = *(const float4*)(m + 12);

        float v[4];
        #pragma unroll
        for (int j = 0; j < 4; j++) {
            v[j] = m0.x * ae[j][0].x + m0.y * ae[j][0].y + m0.z * ae[j][0].z + m0.w * ae[j][0].w
                 + m1.x * ae[j][1].x + m1.y * ae[j][1].y + m1.z * ae[j][1].z + m1.w * ae[j][1].w
                 + m2.x * ae[j][2].x + m2.y * ae[j][2].y + m2.z * ae[j][2].z + m2.w * ae[j][2].w
                 + m3.x * ae[j][3].x + m3.y * ae[j][3].y + m3.z * ae[j][3].z + m3.w * ae[j][3].w;
        }
        float4* op = (float4*)(out + (size_t)(row0 + rr) * HDIM + h0);
        float4 o = *op;
        o.x += SCALE * v[0];
        o.y += SCALE * v[1];
        o.z += SCALE * v[2];
        o.w += SCALE * v[3];
        *op = o;
    }
}

// ---------------- launch ----------------
extern "C" void kernel_launch(void* const* d_in, const int* in_sizes, int n_in,
                              void* d_out, int out_size)
{
    const float* x   = (const float*)d_in[0];
    const float* Wb  = (const float*)d_in[1];
    const float* iA  = (const float*)d_in[2];
    const float* iB  = (const float*)d_in[3];
    const float* gam = (const float*)d_in[4];
    const float* bet = (const float*)d_in[5];
    const float* Wp  = (const float*)d_in[6];
    float* out = (float*)d_out;

    cudaFuncSetAttribute(gemm_tf32,       cudaFuncAttributeMaxDynamicSharedMemorySize, SMEM_GEMM);
    cudaFuncSetAttribute(proj_mma_kernel, cudaFuncAttributeMaxDynamicSharedMemorySize, SMEM_PROJ);
    cudaFuncSetAttribute(mid_mma_kernel,  cudaFuncAttributeMaxDynamicSharedMemorySize, SMEM_MID);

    ln_shift_kernel<<<M_TOT, 256>>>(x, gam, bet);

    dim3 gg(HDIM / BN, M_TOT / BM, 2);
    gemm_tf32<<<gg, 256, SMEM_GEMM>>>(x, Wb, Wp, out);   // z=0: base_out, z=1: V

    proj_mma_kernel<<<M_TOT / 128, 256, SMEM_PROJ>>>(x, iA, iB);
    delta_kernel<<<dim3(NBC, KDIM / 128, 2), 128>>>(x);
    cumsum_kernel<<<dim3((HDIM * RANK) / 256, NBATCH, 2), 256>>>();
    clip_eff_kernel<<<NBC, 256>>>(iA, iB);
    mid_mma_kernel<<<M_TOT / 128, 256, SMEM_MID>>>(x);
    lora_apply_kernel<<<dim3(4, NBC), 256>>>(out);
}

// round 12
// speedup vs baseline: 3.0694x; 1.0491x over previous
#include <cuda_runtime.h>
#include <math.h>
#include <stdint.h>

// ---------------- problem constants ----------------
#define M_TOT   16384
#define SEQ     8192
#define KDIM    1024
#define HDIM    1024
#define RANK    16
#define CHUNK   256
#define NCH     32
#define NBATCH  2
#define NBC     64
#define LRC     0.02f
#define SCALE   2.0f
#define CLIP    1.0f
#define LN_EPS  1e-5f

// ---------------- GEMM tiling ----------------
#define BM 128
#define BN 128
#define BK 32
#define LDA 36
#define STAGE_FLOATS ((BM + BN) * LDA)
#define STAGE_BYTES  (STAGE_FLOATS * 4)
#define NSTAGE 3
#define SMEM_GEMM (NSTAGE * STAGE_BYTES)         // 110592 B
#define NIT (KDIM / BK)

// proj/mid mma kernels
#define PLDA 36
#define PROJ_STAGE (128 * PLDA)
#define SMEM_PROJ (2 * 2 * PROJ_STAGE * 4)
#define SMEM_MID  (2 * PROJ_STAGE * 4)

// ---------------- device scratch ----------------
__device__ __align__(128) float g_shifted[M_TOT * KDIM];
__device__ __align__(128) float g_V      [M_TOT * KDIM];
__device__ __align__(128) float g_proj_in [NBC * CHUNK * RANK];
__device__ __align__(128) float g_proj_err[NBC * CHUNK * RANK];
__device__ __align__(128) float g_dA  [NBC * HDIM * RANK];
__device__ __align__(128) float g_dB  [NBC * RANK * KDIM];
__device__ __align__(128) float g_Aeff[NBC * HDIM * RANK];
__device__ __align__(128) float g_Beff[NBC * RANK * KDIM];
__device__ __align__(128) float g_mid [M_TOT * RANK];

// ---------------- helpers ----------------
__device__ __forceinline__ uint32_t smem_u32(const void* p) {
    uint32_t a;
    asm("{ .reg .u64 t; cvta.to.shared.u64 t, %1; cvt.u32.u64 %0, t; }" : "=r"(a) : "l"(p));
    return a;
}
__device__ __forceinline__ void cp16(uint32_t d, const void* s) {
    asm volatile("cp.async.cg.shared.global [%0], [%1], 16;" :: "r"(d), "l"(s));
}
__device__ __forceinline__ void mma_tf32(float4& c, const uint32_t a[4], const uint32_t b[2]) {
    asm volatile(
        "mma.sync.aligned.m16n8k8.row.col.f32.tf32.tf32.f32 "
        "{%0,%1,%2,%3}, {%4,%5,%6,%7}, {%8,%9}, {%0,%1,%2,%3};"
        : "+f"(c.x), "+f"(c.y), "+f"(c.z), "+f"(c.w)
        : "r"(a[0]), "r"(a[1]), "r"(a[2]), "r"(a[3]), "r"(b[0]), "r"(b[1]));
}
__device__ __forceinline__ void ldsm4(uint32_t r[4], uint32_t addr) {
    asm volatile("ldmatrix.sync.aligned.m8n8.x4.shared.b16 {%0,%1,%2,%3}, [%4];"
                 : "=r"(r[0]), "=r"(r[1]), "=r"(r[2]), "=r"(r[3]) : "r"(addr));
}

// ---------------- kernel 1: LayerNorm + left shift ----------------
__global__ __launch_bounds__(256) void ln_shift_kernel(
    const float* __restrict__ x,
    const float* __restrict__ gam,
    const float* __restrict__ bet)
{
    int row = blockIdx.x;
    int s   = row & (SEQ - 1);
    const float4* xr = (const float4*)(x + (size_t)row * KDIM);
    float4 v = xr[threadIdx.x];

    float sum = v.x + v.y + v.z + v.w;
    float ssq = v.x*v.x + v.y*v.y + v.z*v.z + v.w*v.w;
    #pragma unroll
    for (int o = 16; o; o >>= 1) {
        sum += __shfl_xor_sync(0xffffffffu, sum, o);
        ssq += __shfl_xor_sync(0xffffffffu, ssq, o);
    }
    __shared__ float s1[8], s2[8];
    int w = threadIdx.x >> 5, l = threadIdx.x & 31;
    if (!l) { s1[w] = sum; s2[w] = ssq; }
    __syncthreads();
    if (threadIdx.x == 0) {
        float a = 0.f, b = 0.f;
        #pragma unroll
        for (int i = 0; i < 8; i++) { a += s1[i]; b += s2[i]; }
        s1[0] = a; s2[0] = b;
    }
    __syncthreads();
    float mu   = s1[0] * (1.0f / KDIM);
    float var  = s2[0] * (1.0f / KDIM) - mu * mu;
    float rstd = rsqrtf(var + LN_EPS);

    if (s == 0) {
        float4* d = (float4*)(g_shifted + ((size_t)row + SEQ - 1) * KDIM);
        d[threadIdx.x] = make_float4(0.f, 0.f, 0.f, 0.f);
    } else {
        float4 g4 = ((const float4*)gam)[threadIdx.x];
        float4 b4 = ((const float4*)bet)[threadIdx.x];
        float4 o;
        o.x = (v.x - mu) * rstd * g4.x + b4.x;
        o.y = (v.y - mu) * rstd * g4.y + b4.y;
        o.z = (v.z - mu) * rstd * g4.z + b4.z;
        o.w = (v.w - mu) * rstd * g4.w + b4.w;
        float4* d = (float4*)(g_shifted + (size_t)(row - 1) * KDIM);
        d[threadIdx.x] = o;
    }
}

// ---------------- kernel 2: TF32 mma GEMM ----------------
// mode 0: C = x @ Wb^T + SCALE * mid @ Aeff^T   (writes out; runs LAST)
// mode 1: C = g_shifted @ Wp^T                   (writes g_V)
extern __shared__ float sm_dyn[];

__device__ __forceinline__ void gemm_load_stage(
    uint32_t sbase, int stage, const float* Ab, const float* Wb, int k0, int tid)
{
    uint32_t sa = sbase + stage * STAGE_BYTES;
    uint32_t sw = sa + BM * LDA * 4;
    #pragma unroll
    for (int i = 0; i < 4; i++) {
        int idx = tid + i * 256;
        int row = idx >> 3, seg = idx & 7;
        cp16(sa + row * (LDA * 4) + seg * 16, Ab + (size_t)row * KDIM + k0 + seg * 4);
    }
    #pragma unroll
    for (int i = 0; i < 4; i++) {
        int idx = tid + i * 256;
        int row = idx >> 3, seg = idx & 7;
        cp16(sw + row * (LDA * 4) + seg * 16, Wb + (size_t)row * KDIM + k0 + seg * 4);
    }
    asm volatile("cp.async.commit_group;" ::: "memory");
}

__global__ __launch_bounds__(256, 2) void gemm_tf32(
    const float* __restrict__ x, const float* __restrict__ Wbm,
    const float* __restrict__ Wpm, float* __restrict__ out, int mode)
{
    const float* A;
    const float* W;
    float* C;
    if (mode == 0) { A = x;         W = Wbm; C = out; }
    else           { A = g_shifted; W = Wpm; C = g_V; }

    int tid  = threadIdx.x;
    int wid  = tid >> 5;
    int lane = tid & 31;
    int grp  = lane >> 2;
    int tig  = lane & 3;
    int wm   = wid & 1;
    int wn   = wid >> 1;

    int mbase = blockIdx.y * BM;
    int nbase = blockIdx.x * BN;
    const float* Ab = A + (size_t)mbase * KDIM;
    const float* Wb = W + (size_t)nbase * KDIM;

    uint32_t sbase = smem_u32(sm_dyn);

    int quad = lane >> 3, lr = lane & 7;
    uint32_t aOff = ((uint32_t)(wm * 64 + ((quad & 1) << 3) + lr) * LDA +
                     ((quad >> 1) << 2)) * 4;
    uint32_t bOff = (uint32_t)(BM * LDA * 4) +
                    ((uint32_t)(wn * 32 + ((quad >> 1) << 3) + lr) * LDA +
                     ((quad & 1) << 2)) * 4;

    float4 c[4][4];
    #pragma unroll
    for (int i = 0; i < 4; i++)
        #pragma unroll
        for (int j = 0; j < 4; j++) c[i][j] = make_float4(0.f, 0.f, 0.f, 0.f);

    gemm_load_stage(sbase, 0, Ab, Wb, 0, tid);
    gemm_load_stage(sbase, 1, Ab, Wb, BK, tid);

    for (int it = 0; it < NIT; it++) {
        if (it == NIT - 1) asm volatile("cp.async.wait_group 0;" ::: "memory");
        else               asm volatile("cp.async.wait_group 1;" ::: "memory");
        __syncthreads();
        if (it + 2 < NIT)
            gemm_load_stage(sbase, (it + 2) % NSTAGE, Ab, Wb, (it + 2) * BK, tid);

        uint32_t stge = sbase + (it % NSTAGE) * STAGE_BYTES;
        uint32_t aB = stge + aOff;
        uint32_t bB = stge + bOff;

        #pragma unroll
        for (int k8 = 0; k8 < 4; k8++) {
            uint32_t a[4][4], b[4][2];
            #pragma unroll
            for (int mf = 0; mf < 4; mf++)
                ldsm4(a[mf], aB + mf * (16 * LDA * 4) + k8 * 32);
            #pragma unroll
            for (int p = 0; p < 2; p++) {
                uint32_t r[4];
                ldsm4(r, bB + p * (16 * LDA * 4) + k8 * 32);
                b[2*p][0]   = r[0]; b[2*p][1]   = r[1];
                b[2*p+1][0] = r[2]; b[2*p+1][1] = r[3];
            }
            #pragma unroll
            for (int mf = 0; mf < 4; mf++)
                #pragma unroll
                for (int nf = 0; nf < 4; nf++)
                    mma_tf32(c[mf][nf], a[mf], b[nf]);
        }
    }

    // mode 0: fold lora into accumulators: c += (SCALE*mid) @ Aeff^T
    // (rank 16 = two k8 steps; pre-scaling mid by SCALE lets mma accumulate
    //  directly into c with no extra accumulator registers)
    if (mode == 0) {
        int cch = mbase >> 8;
        const float* midp = g_mid + (size_t)mbase * RANK;
        const float* Ae   = g_Aeff + (size_t)cch * (HDIM * RANK);
        #pragma unroll
        for (int ks = 0; ks < 2; ks++) {
            uint32_t a[4][4], b[4][2];
            #pragma unroll
            for (int mf = 0; mf < 4; mf++) {
                int r0 = wm * 64 + mf * 16 + grp;
                a[mf][0] = __float_as_uint(SCALE * midp[(size_t)r0 * RANK + ks * 8 + tig]);
                a[mf][1] = __float_as_uint(SCALE * midp[(size_t)(r0 + 8) * RANK + ks * 8 + tig]);
                a[mf][2] = __float_as_uint(SCALE * midp[(size_t)r0 * RANK + ks * 8 + tig + 4]);
                a[mf][3] = __float_as_uint(SCALE * midp[(size_t)(r0 + 8) * RANK + ks * 8 + tig + 4]);
            }
            #pragma unroll
            for (int nf = 0; nf < 4; nf++) {
                int col = nbase + wn * 32 + nf * 8 + grp;
                b[nf][0] = __float_as_uint(Ae[(size_t)col * RANK + ks * 8 + tig]);
                b[nf][1] = __float_as_uint(Ae[(size_t)col * RANK + ks * 8 + tig + 4]);
            }
            #pragma unroll
            for (int mf = 0; mf < 4; mf++)
                #pragma unroll
                for (int nf = 0; nf < 4; nf++)
                    mma_tf32(c[mf][nf], a[mf], b[nf]);
        }
    }

    #pragma unroll
    for (int mf = 0; mf < 4; mf++) {
        int row0 = mbase + wm * 64 + mf * 16 + grp;
        #pragma unroll
        for (int nf = 0; nf < 4; nf++) {
            int col = nbase + wn * 32 + nf * 8 + 2 * tig;
            *(float2*)(C + (size_t)row0 * HDIM + col)       = make_float2(c[mf][nf].x, c[mf][nf].y);
            *(float2*)(C + (size_t)(row0 + 8) * HDIM + col) = make_float2(c[mf][nf].z, c[mf][nf].w);
        }
    }
}

// ---------------- kernel 3: proj via mma ----------------
__global__ __launch_bounds__(256) void proj_mma_kernel(
    const float* __restrict__ x,
    const float* __restrict__ iA,
    const float* __restrict__ iB)
{
    int tid  = threadIdx.x;
    int wid  = tid >> 5;
    int lane = tid & 31;
    int grp  = lane >> 2;
    int tig  = lane & 3;

    int rowbase = blockIdx.x * 128;
    const float* Xb = x   + (size_t)rowbase * KDIM;
    const float* Vb = g_V + (size_t)rowbase * KDIM;

    float4 cI[2], cE[2];
    cI[0] = make_float4(0,0,0,0); cI[1] = make_float4(0,0,0,0);
    cE[0] = make_float4(0,0,0,0); cE[1] = make_float4(0,0,0,0);

    auto load_stage = [&](int stage, int k0) {
        uint32_t sx = smem_u32(sm_dyn) + stage * (2 * PROJ_STAGE * 4);
        uint32_t sv = sx + PROJ_STAGE * 4;
        #pragma unroll
        for (int i = 0; i < 4; i++) {
            int idx = tid + i * 256;
            int row = idx >> 3, seg = idx & 7;
            cp16(sx + row * (PLDA * 4) + seg * 16, Xb + (size_t)row * KDIM + k0 + seg * 4);
        }
        #pragma unroll
        for (int i = 0; i < 4; i++) {
            int idx = tid + i * 256;
            int row = idx >> 3, seg = idx & 7;
            cp16(sv + row * (PLDA * 4) + seg * 16, Vb + (size_t)row * KDIM + k0 + seg * 4);
        }
        asm volatile("cp.async.commit_group;" ::: "memory");
    };

    load_stage(0, 0);

    for (int it = 0; it < NIT; it++) {
        int k0 = it * BK;
        uint32_t bI[4][2][2], bE[4][2][2];
        #pragma unroll
        for (int kk = 0; kk < 4; kk++) {
            int kidx = k0 + kk * 8 + tig;
            #pragma unroll
            for (int nf = 0; nf < 2; nf++) {
                int n = nf * 8 + grp;
                bI[kk][nf][0] = __float_as_uint(iB[(size_t)n * KDIM + kidx]);
                bI[kk][nf][1] = __float_as_uint(iB[(size_t)n * KDIM + kidx + 4]);
                bE[kk][nf][0] = __float_as_uint(iA[(size_t)kidx * RANK + n]);
                bE[kk][nf][1] = __float_as_uint(iA[(size_t)(kidx + 4) * RANK + n]);
            }
        }

        asm volatile("cp.async.wait_group 0;" ::: "memory");
        __syncthreads();
        if (it + 1 < NIT) load_stage((it + 1) & 1, k0 + BK);

        const float* sx = sm_dyn + (it & 1) * (2 * PROJ_STAGE);
        const float* sv = sx + PROJ_STAGE;

        #pragma unroll
        for (int kk = 0; kk < 4; kk++) {
            uint32_t ax[4], av[4];
            const float* px = sx + (wid * 16 + grp) * PLDA + kk * 8 + tig;
            ax[0] = __float_as_uint(px[0]);
            ax[1] = __float_as_uint(px[8 * PLDA]);
            ax[2] = __float_as_uint(px[4]);
            ax[3] = __float_as_uint(px[8 * PLDA + 4]);
            const float* pv = sv + (wid * 16 + grp) * PLDA + kk * 8 + tig;
            av[0] = __float_as_uint(pv[0]);
            av[1] = __float_as_uint(pv[8 * PLDA]);
            av[2] = __float_as_uint(pv[4]);
            av[3] = __float_as_uint(pv[8 * PLDA + 4]);
            #pragma unroll
            for (int nf = 0; nf < 2; nf++) {
                mma_tf32(cI[nf], ax, bI[kk][nf]);
                mma_tf32(cE[nf], av, bE[kk][nf]);
            }
        }
        __syncthreads();
    }

    int row = rowbase + wid * 16 + grp;
    #pragma unroll
    for (int nf = 0; nf < 2; nf++) {
        int col = nf * 8 + 2 * tig;
        *(float2*)(g_proj_in  + (size_t)row * RANK + col)       = make_float2(cI[nf].x, cI[nf].y);
        *(float2*)(g_proj_in  + (size_t)(row + 8) * RANK + col) = make_float2(cI[nf].z, cI[nf].w);
        *(float2*)(g_proj_err + (size_t)row * RANK + col)       = make_float2(cE[nf].x, cE[nf].y);
        *(float2*)(g_proj_err + (size_t)(row + 8) * RANK + col) = make_float2(cE[nf].z, cE[nf].w);
    }
}

// ---------------- kernel 4: dA / dB (128-thread blocks) ----------------
__global__ __launch_bounds__(128) void delta_kernel(const float* __restrict__ x)
{
    int c = blockIdx.x, part = blockIdx.y, mode = blockIdx.z;
    __shared__ float sp[CHUNK][RANK];
    const float* P = (mode == 0 ? g_proj_in : g_proj_err) + (size_t)c * CHUNK * RANK;
    for (int i = threadIdx.x; i < CHUNK * RANK; i += 128)
        sp[i >> 4][i & 15] = P[i];
    __syncthreads();

    int col = part * 128 + threadIdx.x;
    const float* src = (mode == 0 ? g_V : x) + (size_t)c * CHUNK * KDIM + col;

    float acc[RANK];
    #pragma unroll
    for (int r = 0; r < RANK; r++) acc[r] = 0.f;

    #pragma unroll 4
    for (int i = 0; i < CHUNK; i++) {
        float v = src[(size_t)i * KDIM];
        #pragma unroll
        for (int r = 0; r < RANK; r++) acc[r] += v * sp[i][r];
    }

    if (mode == 0) {
        float* d = g_dA + (size_t)c * HDIM * RANK + (size_t)col * RANK;
        #pragma unroll
        for (int r = 0; r < RANK; r += 4)
            *(float4*)(d + r) = make_float4(acc[r], acc[r+1], acc[r+2], acc[r+3]);
    } else {
        float* d = g_dB + (size_t)c * RANK * KDIM + col;
        #pragma unroll
        for (int r = 0; r < RANK; r++) d[(size_t)r * KDIM] = acc[r];
    }
}

// ---------------- kernel 5: exclusive cumsum over chunks ----------------
__global__ __launch_bounds__(256) void cumsum_kernel()
{
    int e = blockIdx.x * 256 + threadIdx.x;
    int b = blockIdx.y;
    float* base = blockIdx.z ? g_dB : g_dA;
    float run = 0.f;
    #pragma unroll
    for (int j = 0; j < NCH; j++) {
        size_t off = ((size_t)(b * NCH + j)) * (HDIM * RANK) + e;
        float t = base[off];
        base[off] = run;
        run += t;
    }
}

// ---------------- kernel 6: fused clip + effective weights ----------------
__global__ __launch_bounds__(256) void clip_eff_kernel(
    const float* __restrict__ iA, const float* __restrict__ iB)
{
    int c = blockIdx.x;
    const float* A = g_dA + (size_t)c * (HDIM * RANK);
    const float* B = g_dB + (size_t)c * (RANK * KDIM);
    float s = 0.f;
    for (int i = threadIdx.x; i < HDIM * RANK; i += 256) {
        float a = A[i]; s += a * a;
        float b = B[i]; s += b * b;
    }
    #pragma unroll
    for (int o = 16; o; o >>= 1) s += __shfl_xor_sync(0xffffffffu, s, o);
    __shared__ float sm[8];
    __shared__ float s_coef;
    int w = threadIdx.x >> 5, l = threadIdx.x & 31;
    if (!l) sm[w] = s;
    __syncthreads();
    if (threadIdx.x == 0) {
        float t = 0.f;
        #pragma unroll
        for (int i = 0; i < 8; i++) t += sm[i];
        float norm = LRC * sqrtf(t);
        s_coef = LRC * fminf(1.0f, CLIP / (norm + 1e-6f));
    }
    __syncthreads();
    float sc = s_coef;
    float* Ae = g_Aeff + (size_t)c * (HDIM * RANK);
    float* Be = g_Beff + (size_t)c * (RANK * KDIM);
    for (int i = threadIdx.x; i < HDIM * RANK; i += 256) {
        Ae[i] = iA[i] - sc * A[i];
        Be[i] = iB[i] - sc * B[i];
    }
}

// ---------------- kernel 7: mid = Z @ B_eff^T via mma ----------------
__global__ __launch_bounds__(256) void mid_mma_kernel(const float* __restrict__ x)
{
    int tid  = threadIdx.x;
    int wid  = tid >> 5;
    int lane = tid & 31;
    int grp  = lane >> 2;
    int tig  = lane & 3;

    int rowbase = blockIdx.x * 128;
    int c = rowbase >> 8;
    const float* Xb = x + (size_t)rowbase * KDIM;
    const float* Be = g_Beff + (size_t)c * (RANK * KDIM);

    float4 cI[2];
    cI[0] = make_float4(0,0,0,0); cI[1] = make_float4(0,0,0,0);

    auto load_stage = [&](int stage, int k0) {
        uint32_t sx = smem_u32(sm_dyn) + stage * (PROJ_STAGE * 4);
        #pragma unroll
        for (int i = 0; i < 4; i++) {
            int idx = tid + i * 256;
            int row = idx >> 3, seg = idx & 7;
            cp16(sx + row * (PLDA * 4) + seg * 16, Xb + (size_t)row * KDIM + k0 + seg * 4);
        }
        asm volatile("cp.async.commit_group;" ::: "memory");
    };

    load_stage(0, 0);

    for (int it = 0; it < NIT; it++) {
        int k0 = it * BK;
        uint32_t bI[4][2][2];
        #pragma unroll
        for (int kk = 0; kk < 4; kk++) {
            int kidx = k0 + kk * 8 + tig;
            #pragma unroll
            for (int nf = 0; nf < 2; nf++) {
                int n = nf * 8 + grp;
                bI[kk][nf][0] = __float_as_uint(Be[(size_t)n * KDIM + kidx]);
                bI[kk][nf][1] = __float_as_uint(Be[(size_t)n * KDIM + kidx + 4]);
            }
        }

        asm volatile("cp.async.wait_group 0;" ::: "memory");
        __syncthreads();
        if (it + 1 < NIT) load_stage((it + 1) & 1, k0 + BK);

        const float* sx = sm_dyn + (it & 1) * PROJ_STAGE;

        #pragma unroll
        for (int kk = 0; kk < 4; kk++) {
            uint32_t ax[4];
            const float* px = sx + (wid * 16 + grp) * PLDA + kk * 8 + tig;
            ax[0] = __float_as_uint(px[0]);
            ax[1] = __float_as_uint(px[8 * PLDA]);
            ax[2] = __float_as_uint(px[4]);
            ax[3] = __float_as_uint(px[8 * PLDA + 4]);
            #pragma unroll
            for (int nf = 0; nf < 2; nf++)
                mma_tf32(cI[nf], ax, bI[kk][nf]);
        }
        __syncthreads();
    }

    int row = rowbase + wid * 16 + grp;
    #pragma unroll
    for (int nf = 0; nf < 2; nf++) {
        int col = nf * 8 + 2 * tig;
        *(float2*)(g_mid + (size_t)row * RANK + col)       = make_float2(cI[nf].x, cI[nf].y);
        *(float2*)(g_mid + (size_t)(row + 8) * RANK + col) = make_float2(cI[nf].z, cI[nf].w);
    }
}

// ---------------- launch ----------------
extern "C" void kernel_launch(void* const* d_in, const int* in_sizes, int n_in,
                              void* d_out, int out_size)
{
    const float* x   = (const float*)d_in[0];
    const float* Wb  = (const float*)d_in[1];
    const float* iA  = (const float*)d_in[2];
    const float* iB  = (const float*)d_in[3];
    const float* gam = (const float*)d_in[4];
    const float* bet = (const float*)d_in[5];
    const float* Wp  = (const float*)d_in[6];
    float* out = (float*)d_out;

    cudaFuncSetAttribute(gemm_tf32,       cudaFuncAttributeMaxDynamicSharedMemorySize, SMEM_GEMM);
    cudaFuncSetAttribute(proj_mma_kernel, cudaFuncAttributeMaxDynamicSharedMemorySize, SMEM_PROJ);
    cudaFuncSetAttribute(mid_mma_kernel,  cudaFuncAttributeMaxDynamicSharedMemorySize, SMEM_MID);

    dim3 gg(HDIM / BN, M_TOT / BM);

    ln_shift_kernel<<<M_TOT, 256>>>(x, gam, bet);
    gemm_tf32<<<gg, 256, SMEM_GEMM>>>(x, Wb, Wp, out, 1);      // V = shifted @ Wp^T
    proj_mma_kernel<<<M_TOT / 128, 256, SMEM_PROJ>>>(x, iA, iB);
    delta_kernel<<<dim3(NBC, KDIM / 128, 2), 128>>>(x);
    cumsum_kernel<<<dim3((HDIM * RANK) / 256, NBATCH, 2), 256>>>();
    clip_eff_kernel<<<NBC, 256>>>(iA, iB);
    mid_mma_kernel<<<M_TOT / 128, 256, SMEM_MID>>>(x);
    gemm_tf32<<<gg, 256, SMEM_GEMM>>>(x, Wb, Wp, out, 0);      // out = x @ Wb^T + lora
}

// round 13
// speedup vs baseline: 3.6281x; 1.1820x over previous
#include <cuda_runtime.h>
#include <cuda_fp16.h>
#include <math.h>
#include <stdint.h>

// ---------------- problem constants ----------------
#define M_TOT   16384
#define SEQ     8192
#define KDIM    1024
#define HDIM    1024
#define RANK    16
#define CHUNK   256
#define NCH     32
#define NBATCH  2
#define NBC     64
#define LRC     0.02f
#define SCALE   2.0f
#define CLIP    1.0f
#define LN_EPS  1e-5f

// ---------------- fp16 GEMM tiling ----------------
#define BM 128
#define BN 128
#define BK 32
#define LDAH 40                                  // halves per smem row (80 B)
#define ROW_B 80                                 // bytes per smem row
#define A_REGION (BM * ROW_B)                    // 10240 B
#define STAGE_BYTES_H ((BM + BN) * ROW_B)        // 20480 B
#define NSTAGE 3
#define SMEM_GEMM (NSTAGE * STAGE_BYTES_H)       // 61440 B
#define NIT (KDIM / BK)                          // 32

// proj/mid mma kernels (tf32, unchanged)
#define PLDA 36
#define PROJ_STAGE (128 * PLDA)
#define SMEM_PROJ (2 * 2 * PROJ_STAGE * 4)
#define SMEM_MID  (2 * PROJ_STAGE * 4)

// ---------------- device scratch ----------------
__device__ __align__(128) __half g_x_h      [M_TOT * KDIM];   // 32 MB
__device__ __align__(128) __half g_shifted_h[M_TOT * KDIM];   // 32 MB
__device__ __align__(128) __half g_Wb_h     [HDIM * KDIM];    // 2 MB
__device__ __align__(128) __half g_Wp_h     [HDIM * KDIM];    // 2 MB
__device__ __align__(128) float g_V      [M_TOT * KDIM];
__device__ __align__(128) float g_proj_in [NBC * CHUNK * RANK];
__device__ __align__(128) float g_proj_err[NBC * CHUNK * RANK];
__device__ __align__(128) float g_dA  [NBC * HDIM * RANK];
__device__ __align__(128) float g_dB  [NBC * RANK * KDIM];
__device__ __align__(128) float g_Aeff[NBC * HDIM * RANK];
__device__ __align__(128) float g_Beff[NBC * RANK * KDIM];
__device__ __align__(128) float g_mid [M_TOT * RANK];

// ---------------- helpers ----------------
__device__ __forceinline__ uint32_t smem_u32(const void* p) {
    uint32_t a;
    asm("{ .reg .u64 t; cvta.to.shared.u64 t, %1; cvt.u32.u64 %0, t; }" : "=r"(a) : "l"(p));
    return a;
}
__device__ __forceinline__ void cp16(uint32_t d, const void* s) {
    asm volatile("cp.async.cg.shared.global [%0], [%1], 16;" :: "r"(d), "l"(s));
}
__device__ __forceinline__ void mma_tf32(float4& c, const uint32_t a[4], const uint32_t b[2]) {
    asm volatile(
        "mma.sync.aligned.m16n8k8.row.col.f32.tf32.tf32.f32 "
        "{%0,%1,%2,%3}, {%4,%5,%6,%7}, {%8,%9}, {%0,%1,%2,%3};"
        : "+f"(c.x), "+f"(c.y), "+f"(c.z), "+f"(c.w)
        : "r"(a[0]), "r"(a[1]), "r"(a[2]), "r"(a[3]), "r"(b[0]), "r"(b[1]));
}
__device__ __forceinline__ void mma_f16(float4& c, const uint32_t a[4], const uint32_t b[2]) {
    asm volatile(
        "mma.sync.aligned.m16n8k16.row.col.f32.f16.f16.f32 "
        "{%0,%1,%2,%3}, {%4,%5,%6,%7}, {%8,%9}, {%0,%1,%2,%3};"
        : "+f"(c.x), "+f"(c.y), "+f"(c.z), "+f"(c.w)
        : "r"(a[0]), "r"(a[1]), "r"(a[2]), "r"(a[3]), "r"(b[0]), "r"(b[1]));
}
__device__ __forceinline__ void ldsm4(uint32_t r[4], uint32_t addr) {
    asm volatile("ldmatrix.sync.aligned.m8n8.x4.shared.b16 {%0,%1,%2,%3}, [%4];"
                 : "=r"(r[0]), "=r"(r[1]), "=r"(r[2]), "=r"(r[3]) : "r"(addr));
}
__device__ __forceinline__ uint32_t packh2(float x, float y) {
    __half2 h = __floats2half2_rn(x, y);
    return *reinterpret_cast<uint32_t*>(&h);
}

// ---------------- kernel 0: fp32 -> fp16 convert (8 elems / thread) ----------------
__global__ __launch_bounds__(256) void conv_h_kernel(
    const float* __restrict__ s, __half* __restrict__ d)
{
    int i = blockIdx.x * 256 + threadIdx.x;
    float4 v0 = ((const float4*)s)[2 * i];
    float4 v1 = ((const float4*)s)[2 * i + 1];
    uint4 o;
    o.x = packh2(v0.x, v0.y);
    o.y = packh2(v0.z, v0.w);
    o.z = packh2(v1.x, v1.y);
    o.w = packh2(v1.z, v1.w);
    ((uint4*)d)[i] = o;
}

// ---------------- kernel 1: LayerNorm + left shift (fp16 out) ----------------
__global__ __launch_bounds__(256) void ln_shift_kernel(
    const float* __restrict__ x,
    const float* __restrict__ gam,
    const float* __restrict__ bet)
{
    int row = blockIdx.x;
    int s   = row & (SEQ - 1);
    const float4* xr = (const float4*)(x + (size_t)row * KDIM);
    float4 v = xr[threadIdx.x];

    float sum = v.x + v.y + v.z + v.w;
    float ssq = v.x*v.x + v.y*v.y + v.z*v.z + v.w*v.w;
    #pragma unroll
    for (int o = 16; o; o >>= 1) {
        sum += __shfl_xor_sync(0xffffffffu, sum, o);
        ssq += __shfl_xor_sync(0xffffffffu, ssq, o);
    }
    __shared__ float s1[8], s2[8];
    int w = threadIdx.x >> 5, l = threadIdx.x & 31;
    if (!l) { s1[w] = sum; s2[w] = ssq; }
    __syncthreads();
    if (threadIdx.x == 0) {
        float a = 0.f, b = 0.f;
        #pragma unroll
        for (int i = 0; i < 8; i++) { a += s1[i]; b += s2[i]; }
        s1[0] = a; s2[0] = b;
    }
    __syncthreads();
    float mu   = s1[0] * (1.0f / KDIM);
    float var  = s2[0] * (1.0f / KDIM) - mu * mu;
    float rstd = rsqrtf(var + LN_EPS);

    if (s == 0) {
        uint2* d = (uint2*)(g_shifted_h + ((size_t)row + SEQ - 1) * KDIM);
        d[threadIdx.x] = make_uint2(0u, 0u);
    } else {
        float4 g4 = ((const float4*)gam)[threadIdx.x];
        float4 b4 = ((const float4*)bet)[threadIdx.x];
        float ox = (v.x - mu) * rstd * g4.x + b4.x;
        float oy = (v.y - mu) * rstd * g4.y + b4.y;
        float oz = (v.z - mu) * rstd * g4.z + b4.z;
        float ow = (v.w - mu) * rstd * g4.w + b4.w;
        uint2* d = (uint2*)(g_shifted_h + (size_t)(row - 1) * KDIM);
        d[threadIdx.x] = make_uint2(packh2(ox, oy), packh2(oz, ow));
    }
}

// ---------------- kernel 2: FP16 mma GEMM ----------------
// mode 0: out = x_h @ Wb_h^T + SCALE * mid @ Aeff^T   (runs LAST)
// mode 1: g_V = shifted_h @ Wp_h^T
extern __shared__ float sm_dyn[];

__device__ __forceinline__ void gemm_load_stage_h(
    uint32_t sbase, int stage, const __half* Ah, const __half* Wh, int k0, int tid)
{
    uint32_t sa = sbase + stage * STAGE_BYTES_H;
    #pragma unroll
    for (int i = 0; i < 4; i++) {
        int idx = tid + i * 256;          // 0..1023
        int row = idx >> 2;               // 0..255
        int seg = idx & 3;                // 8-half (16 B) segment
        if (row < BM) {
            cp16(sa + row * ROW_B + seg * 16,
                 Ah + (size_t)row * KDIM + k0 + seg * 8);
        } else {
            int rb = row - BM;
            cp16(sa + A_REGION + rb * ROW_B + seg * 16,
                 Wh + (size_t)rb * KDIM + k0 + seg * 8);
        }
    }
    asm volatile("cp.async.commit_group;" ::: "memory");
}

__global__ __launch_bounds__(256, 2) void gemm_f16(
    float* __restrict__ out, int mode)
{
    const __half* A;
    const __half* W;
    float* C;
    if (mode == 0) { A = g_x_h;       W = g_Wb_h; C = out; }
    else           { A = g_shifted_h; W = g_Wp_h; C = g_V; }

    int tid  = threadIdx.x;
    int wid  = tid >> 5;
    int lane = tid & 31;
    int grp  = lane >> 2;
    int tig  = lane & 3;
    int wm   = wid & 1;
    int wn   = wid >> 1;

    int mbase = blockIdx.y * BM;
    int nbase = blockIdx.x * BN;
    const __half* Ab = A + (size_t)mbase * KDIM;
    const __half* Wb = W + (size_t)nbase * KDIM;

    uint32_t sbase = smem_u32(sm_dyn);

    int quad = lane >> 3, lr = lane & 7;
    // A: quad&1 -> row block (+8), quad>>1 -> k block (+8 halves = 16 B)
    uint32_t aOff = (uint32_t)(wm * 64 + ((quad & 1) << 3) + lr) * ROW_B +
                    ((quad >> 1) << 4);
    // B: same pattern over 16-row n blocks
    uint32_t bOff = (uint32_t)A_REGION +
                    (uint32_t)(wn * 32 + ((quad & 1) << 3) + lr) * ROW_B +
                    ((quad >> 1) << 4);

    float4 c[4][4];
    #pragma unroll
    for (int i = 0; i < 4; i++)
        #pragma unroll
        for (int j = 0; j < 4; j++) c[i][j] = make_float4(0.f, 0.f, 0.f, 0.f);

    gemm_load_stage_h(sbase, 0, Ab, Wb, 0, tid);
    gemm_load_stage_h(sbase, 1, Ab, Wb, BK, tid);

    for (int it = 0; it < NIT; it++) {
        if (it == NIT - 1) asm volatile("cp.async.wait_group 0;" ::: "memory");
        else               asm volatile("cp.async.wait_group 1;" ::: "memory");
        __syncthreads();
        if (it + 2 < NIT)
            gemm_load_stage_h(sbase, (it + 2) % NSTAGE, Ab, Wb, (it + 2) * BK, tid);

        uint32_t stge = sbase + (it % NSTAGE) * STAGE_BYTES_H;
        uint32_t aB = stge + aOff;
        uint32_t bB = stge + bOff;

        #pragma unroll
        for (int k16 = 0; k16 < 2; k16++) {
            uint32_t a[4][4], b[4][2];
            #pragma unroll
            for (int mf = 0; mf < 4; mf++)
                ldsm4(a[mf], aB + mf * (16 * ROW_B) + k16 * 32);
            #pragma unroll
            for (int p = 0; p < 2; p++) {
                uint32_t r[4];
                ldsm4(r, bB + p * (16 * ROW_B) + k16 * 32);
                // r0=(n+0..7,k lo) r1=(n+8..15,k lo) r2=(n+0..7,k hi) r3=(n+8..15,k hi)
                b[2*p][0]   = r[0]; b[2*p][1]   = r[2];
                b[2*p+1][0] = r[1]; b[2*p+1][1] = r[3];
            }
            #pragma unroll
            for (int mf = 0; mf < 4; mf++)
                #pragma unroll
                for (int nf = 0; nf < 4; nf++)
                    mma_f16(c[mf][nf], a[mf], b[nf]);
        }
    }

    // mode 0: fold lora: c += (SCALE*mid) @ Aeff^T  (rank 16 = one k16 mma)
    if (mode == 0) {
        int cch = mbase >> 8;
        const float* midp = g_mid + (size_t)mbase * RANK;
        const float* Ae   = g_Aeff + (size_t)cch * (HDIM * RANK);
        uint32_t a[4][4], b[4][2];
        #pragma unroll
        for (int mf = 0; mf < 4; mf++) {
            int r0 = wm * 64 + mf * 16 + grp;
            const float* m0 = midp + (size_t)r0 * RANK;
            const float* m1 = midp + (size_t)(r0 + 8) * RANK;
            a[mf][0] = packh2(SCALE * m0[2*tig],     SCALE * m0[2*tig + 1]);
            a[mf][1] = packh2(SCALE * m1[2*tig],     SCALE * m1[2*tig + 1]);
            a[mf][2] = packh2(SCALE * m0[8 + 2*tig], SCALE * m0[8 + 2*tig + 1]);
            a[mf][3] = packh2(SCALE * m1[8 + 2*tig], SCALE * m1[8 + 2*tig + 1]);
        }
        #pragma unroll
        for (int nf = 0; nf < 4; nf++) {
            int col = nbase + wn * 32 + nf * 8 + grp;
            const float* ap = Ae + (size_t)col * RANK;
            b[nf][0] = packh2(ap[2*tig],     ap[2*tig + 1]);
            b[nf][1] = packh2(ap[8 + 2*tig], ap[8 + 2*tig + 1]);
        }
        #pragma unroll
        for (int mf = 0; mf < 4; mf++)
            #pragma unroll
            for (int nf = 0; nf < 4; nf++)
                mma_f16(c[mf][nf], a[mf], b[nf]);
    }

    #pragma unroll
    for (int mf = 0; mf < 4; mf++) {
        int row0 = mbase + wm * 64 + mf * 16 + grp;
        #pragma unroll
        for (int nf = 0; nf < 4; nf++) {
            int col = nbase + wn * 32 + nf * 8 + 2 * tig;
            *(float2*)(C + (size_t)row0 * HDIM + col)       = make_float2(c[mf][nf].x, c[mf][nf].y);
            *(float2*)(C + (size_t)(row0 + 8) * HDIM + col) = make_float2(c[mf][nf].z, c[mf][nf].w);
        }
    }
}

// ---------------- kernel 3: proj via tf32 mma ----------------
__global__ __launch_bounds__(256) void proj_mma_kernel(
    const float* __restrict__ x,
    const float* __restrict__ iA,
    const float* __restrict__ iB)
{
    int tid  = threadIdx.x;
    int wid  = tid >> 5;
    int lane = tid & 31;
    int grp  = lane >> 2;
    int tig  = lane & 3;

    int rowbase = blockIdx.x * 128;
    const float* Xb = x   + (size_t)rowbase * KDIM;
    const float* Vb = g_V + (size_t)rowbase * KDIM;

    float4 cI[2], cE[2];
    cI[0] = make_float4(0,0,0,0); cI[1] = make_float4(0,0,0,0);
    cE[0] = make_float4(0,0,0,0); cE[1] = make_float4(0,0,0,0);

    auto load_stage = [&](int stage, int k0) {
        uint32_t sx = smem_u32(sm_dyn) + stage * (2 * PROJ_STAGE * 4);
        uint32_t sv = sx + PROJ_STAGE * 4;
        #pragma unroll
        for (int i = 0; i < 4; i++) {
            int idx = tid + i * 256;
            int row = idx >> 3, seg = idx & 7;
            cp16(sx + row * (PLDA * 4) + seg * 16, Xb + (size_t)row * KDIM + k0 + seg * 4);
        }
        #pragma unroll
        for (int i = 0; i < 4; i++) {
            int idx = tid + i * 256;
            int row = idx >> 3, seg = idx & 7;
            cp16(sv + row * (PLDA * 4) + seg * 16, Vb + (size_t)row * KDIM + k0 + seg * 4);
        }
        asm volatile("cp.async.commit_group;" ::: "memory");
    };

    load_stage(0, 0);

    const int NITP = KDIM / 32;
    for (int it = 0; it < NITP; it++) {
        int k0 = it * 32;
        uint32_t bI[4][2][2], bE[4][2][2];
        #pragma unroll
        for (int kk = 0; kk < 4; kk++) {
            int kidx = k0 + kk * 8 + tig;
            #pragma unroll
            for (int nf = 0; nf < 2; nf++) {
                int n = nf * 8 + grp;
                bI[kk][nf][0] = __float_as_uint(iB[(size_t)n * KDIM + kidx]);
                bI[kk][nf][1] = __float_as_uint(iB[(size_t)n * KDIM + kidx + 4]);
                bE[kk][nf][0] = __float_as_uint(iA[(size_t)kidx * RANK + n]);
                bE[kk][nf][1] = __float_as_uint(iA[(size_t)(kidx + 4) * RANK + n]);
            }
        }

        asm volatile("cp.async.wait_group 0;" ::: "memory");
        __syncthreads();
        if (it + 1 < NITP) load_stage((it + 1) & 1, k0 + 32);

        const float* sx = sm_dyn + (it & 1) * (2 * PROJ_STAGE);
        const float* sv = sx + PROJ_STAGE;

        #pragma unroll
        for (int kk = 0; kk < 4; kk++) {
            uint32_t ax[4], av[4];
            const float* px = sx + (wid * 16 + grp) * PLDA + kk * 8 + tig;
            ax[0] = __float_as_uint(px[0]);
            ax[1] = __float_as_uint(px[8 * PLDA]);
            ax[2] = __float_as_uint(px[4]);
            ax[3] = __float_as_uint(px[8 * PLDA + 4]);
            const float* pv = sv + (wid * 16 + grp) * PLDA + kk * 8 + tig;
            av[0] = __float_as_uint(pv[0]);
            av[1] = __float_as_uint(pv[8 * PLDA]);
            av[2] = __float_as_uint(pv[4]);
            av[3] = __float_as_uint(pv[8 * PLDA + 4]);
            #pragma unroll
            for (int nf = 0; nf < 2; nf++) {
                mma_tf32(cI[nf], ax, bI[kk][nf]);
                mma_tf32(cE[nf], av, bE[kk][nf]);
            }
        }
        __syncthreads();
    }

    int row = rowbase + wid * 16 + grp;
    #pragma unroll
    for (int nf = 0; nf < 2; nf++) {
        int col = nf * 8 + 2 * tig;
        *(float2*)(g_proj_in  + (size_t)row * RANK + col)       = make_float2(cI[nf].x, cI[nf].y);
        *(float2*)(g_proj_in  + (size_t)(row + 8) * RANK + col) = make_float2(cI[nf].z, cI[nf].w);
        *(float2*)(g_proj_err + (size_t)row * RANK + col)       = make_float2(cE[nf].x, cE[nf].y);
        *(float2*)(g_proj_err + (size_t)(row + 8) * RANK + col) = make_float2(cE[nf].z, cE[nf].w);
    }
}

// ---------------- kernel 4: dA / dB ----------------
__global__ __launch_bounds__(128) void delta_kernel(const float* __restrict__ x)
{
    int c = blockIdx.x, part = blockIdx.y, mode = blockIdx.z;
    __shared__ float sp[CHUNK][RANK];
    const float* P = (mode == 0 ? g_proj_in : g_proj_err) + (size_t)c * CHUNK * RANK;
    for (int i = threadIdx.x; i < CHUNK * RANK; i += 128)
        sp[i >> 4][i & 15] = P[i];
    __syncthreads();

    int col = part * 128 + threadIdx.x;
    const float* src = (mode == 0 ? g_V : x) + (size_t)c * CHUNK * KDIM + col;

    float acc[RANK];
    #pragma unroll
    for (int r = 0; r < RANK; r++) acc[r] = 0.f;

    #pragma unroll 4
    for (int i = 0; i < CHUNK; i++) {
        float v = src[(size_t)i * KDIM];
        #pragma unroll
        for (int r = 0; r < RANK; r++) acc[r] += v * sp[i][r];
    }

    if (mode == 0) {
        float* d = g_dA + (size_t)c * HDIM * RANK + (size_t)col * RANK;
        #pragma unroll
        for (int r = 0; r < RANK; r += 4)
            *(float4*)(d + r) = make_float4(acc[r], acc[r+1], acc[r+2], acc[r+3]);
    } else {
        float* d = g_dB + (size_t)c * RANK * KDIM + col;
        #pragma unroll
        for (int r = 0; r < RANK; r++) d[(size_t)r * KDIM] = acc[r];
    }
}

// ---------------- kernel 5: exclusive cumsum over chunks ----------------
__global__ __launch_bounds__(256) void cumsum_kernel()
{
    int e = blockIdx.x * 256 + threadIdx.x;
    int b = blockIdx.y;
    float* base = blockIdx.z ? g_dB : g_dA;
    float run = 0.f;
    #pragma unroll
    for (int j = 0; j < NCH; j++) {
        size_t off = ((size_t)(b * NCH + j)) * (HDIM * RANK) + e;
        float t = base[off];
        base[off] = run;
        run += t;
    }
}

// ---------------- kernel 6: fused clip + effective weights ----------------
__global__ __launch_bounds__(256) void clip_eff_kernel(
    const float* __restrict__ iA, const float* __restrict__ iB)
{
    int c = blockIdx.x;
    const float* A = g_dA + (size_t)c * (HDIM * RANK);
    const float* B = g_dB + (size_t)c * (RANK * KDIM);
    float s = 0.f;
    for (int i = threadIdx.x; i < HDIM * RANK; i += 256) {
        float a = A[i]; s += a * a;
        float b = B[i]; s += b * b;
    }
    #pragma unroll
    for (int o = 16; o; o >>= 1) s += __shfl_xor_sync(0xffffffffu, s, o);
    __shared__ float sm[8];
    __shared__ float s_coef;
    int w = threadIdx.x >> 5, l = threadIdx.x & 31;
    if (!l) sm[w] = s;
    __syncthreads();
    if (threadIdx.x == 0) {
        float t = 0.f;
        #pragma unroll
        for (int i = 0; i < 8; i++) t += sm[i];
        float norm = LRC * sqrtf(t);
        s_coef = LRC * fminf(1.0f, CLIP / (norm + 1e-6f));
    }
    __syncthreads();
    float sc = s_coef;
    float* Ae = g_Aeff + (size_t)c * (HDIM * RANK);
    float* Be = g_Beff + (size_t)c * (RANK * KDIM);
    for (int i = threadIdx.x; i < HDIM * RANK; i += 256) {
        Ae[i] = iA[i] - sc * A[i];
        Be[i] = iB[i] - sc * B[i];
    }
}

// ---------------- kernel 7: mid = Z @ B_eff^T via tf32 mma ----------------
__global__ __launch_bounds__(256) void mid_mma_kernel(const float* __restrict__ x)
{
    int tid  = threadIdx.x;
    int wid  = tid >> 5;
    int lane = tid & 31;
    int grp  = lane >> 2;
    int tig  = lane & 3;

    int rowbase = blockIdx.x * 128;
    int c = rowbase >> 8;
    const float* Xb = x + (size_t)rowbase * KDIM;
    const float* Be = g_Beff + (size_t)c * (RANK * KDIM);

    float4 cI[2];
    cI[0] = make_float4(0,0,0,0); cI[1] = make_float4(0,0,0,0);

    auto load_stage = [&](int stage, int k0) {
        uint32_t sx = smem_u32(sm_dyn) + stage * (PROJ_STAGE * 4);
        #pragma unroll
        for (int i = 0; i < 4; i++) {
            int idx = tid + i * 256;
            int row = idx >> 3, seg = idx & 7;
            cp16(sx + row * (PLDA * 4) + seg * 16, Xb + (size_t)row * KDIM + k0 + seg * 4);
        }
        asm volatile("cp.async.commit_group;" ::: "memory");
    };

    load_stage(0, 0);

    const int NITP = KDIM / 32;
    for (int it = 0; it < NITP; it++) {
        int k0 = it * 32;
        uint32_t bI[4][2][2];
        #pragma unroll
        for (int kk = 0; kk < 4; kk++) {
            int kidx = k0 + kk * 8 + tig;
            #pragma unroll
            for (int nf = 0; nf < 2; nf++) {
                int n = nf * 8 + grp;
                bI[kk][nf][0] = __float_as_uint(Be[(size_t)n * KDIM + kidx]);
                bI[kk][nf][1] = __float_as_uint(Be[(size_t)n * KDIM + kidx + 4]);
            }
        }

        asm volatile("cp.async.wait_group 0;" ::: "memory");
        __syncthreads();
        if (it + 1 < NITP) load_stage((it + 1) & 1, k0 + 32);

        const float* sx = sm_dyn + (it & 1) * PROJ_STAGE;

        #pragma unroll
        for (int kk = 0; kk < 4; kk++) {
            uint32_t ax[4];
            const float* px = sx + (wid * 16 + grp) * PLDA + kk * 8 + tig;
            ax[0] = __float_as_uint(px[0]);
            ax[1] = __float_as_uint(px[8 * PLDA]);
            ax[2] = __float_as_uint(px[4]);
            ax[3] = __float_as_uint(px[8 * PLDA + 4]);
            #pragma unroll
            for (int nf = 0; nf < 2; nf++)
                mma_tf32(cI[nf], ax, bI[kk][nf]);
        }
        __syncthreads();
    }

    int row = rowbase + wid * 16 + grp;
    #pragma unroll
    for (int nf = 0; nf < 2; nf++) {
        int col = nf * 8 + 2 * tig;
        *(float2*)(g_mid + (size_t)row * RANK + col)       = make_float2(cI[nf].x, cI[nf].y);
        *(float2*)(g_mid + (size_t)(row + 8) * RANK + col) = make_float2(cI[nf].z, cI[nf].w);
    }
}

// ---------------- launch ----------------
extern "C" void kernel_launch(void* const* d_in, const int* in_sizes, int n_in,
                              void* d_out, int out_size)
{
    const float* x   = (const float*)d_in[0];
    const float* Wb  = (const float*)d_in[1];
    const float* iA  = (const float*)d_in[2];
    const float* iB  = (const float*)d_in[3];
    const float* gam = (const float*)d_in[4];
    const float* bet = (const float*)d_in[5];
    const float* Wp  = (const float*)d_in[6];
    float* out = (float*)d_out;

    cudaFuncSetAttribute(gemm_f16,        cudaFuncAttributeMaxDynamicSharedMemorySize, SMEM_GEMM);
    cudaFuncSetAttribute(proj_mma_kernel, cudaFuncAttributeMaxDynamicSharedMemorySize, SMEM_PROJ);
    cudaFuncSetAttribute(mid_mma_kernel,  cudaFuncAttributeMaxDynamicSharedMemorySize, SMEM_MID);

    __half* xh; cudaGetSymbolAddress((void**)&xh, g_x_h);
    __half* wbh; cudaGetSymbolAddress((void**)&wbh, g_Wb_h);
    __half* wph; cudaGetSymbolAddress((void**)&wph, g_Wp_h);

    // fp16 conversions
    conv_h_kernel<<<(M_TOT * KDIM) / 2048, 256>>>(x,  xh);
    conv_h_kernel<<<(HDIM * KDIM) / 2048, 256>>>(Wb, wbh);
    conv_h_kernel<<<(HDIM * KDIM) / 2048, 256>>>(Wp, wph);

    ln_shift_kernel<<<M_TOT, 256>>>(x, gam, bet);

    dim3 gg(HDIM / BN, M_TOT / BM);
    gemm_f16<<<gg, 256, SMEM_GEMM>>>(nullptr, 1);              // V = shifted @ Wp^T
    proj_mma_kernel<<<M_TOT / 128, 256, SMEM_PROJ>>>(x, iA, iB);
    delta_kernel<<<dim3(NBC, KDIM / 128, 2), 128>>>(x);
    cumsum_kernel<<<dim3((HDIM * RANK) / 256, NBATCH, 2), 256>>>();
    clip_eff_kernel<<<NBC, 256>>>(iA, iB);
    mid_mma_kernel<<<M_TOT / 128, 256, SMEM_MID>>>(x);
    gemm_f16<<<gg, 256, SMEM_GEMM>>>(out, 0);                  // out = x @ Wb^T + lora
}

// round 15
// speedup vs baseline: 4.0258x; 1.1096x over previous
#include <cuda_runtime.h>
#include <cuda_fp16.h>
#include <math.h>
#include <stdint.h>

// ---------------- problem constants ----------------
#define M_TOT   16384
#define SEQ     8192
#define KDIM    1024
#define HDIM    1024
#define RANK    16
#define CHUNK   256
#define NCH     32
#define NBATCH  2
#define NBC     64
#define LRC     0.02f
#define SCALE   2.0f
#define CLIP    1.0f
#define LN_EPS  1e-5f

// ---------------- fp16 GEMM tiling ----------------
#define BM 128
#define BN 128
#define BK 32
#define ROW_B 80                                 // bytes per smem row (32 halves + pad)
#define A_REGION (BM * ROW_B)                    // 10240 B
#define STAGE_BYTES_H ((BM + BN) * ROW_B)        // 20480 B
#define NSTAGE 3
#define SMEM_GEMM (NSTAGE * STAGE_BYTES_H)       // 61440 B
#define NIT (KDIM / BK)                          // 32

// proj/mid fp16 kernels
#define PROJ_TILE (128 * ROW_B)                  // 10240 B per tile
#define SMEM_PROJ (2 * 2 * PROJ_TILE)            // 40960 B
#define SMEM_MID  (2 * PROJ_TILE)                // 20480 B

// ---------------- device scratch ----------------
__device__ __align__(128) __half g_x_h      [M_TOT * KDIM];   // 32 MB
__device__ __align__(128) __half g_shifted_h[M_TOT * KDIM];   // 32 MB
__device__ __align__(128) __half g_V_h      [M_TOT * KDIM];   // 32 MB
__device__ __align__(128) __half g_Wb_h     [HDIM * KDIM];    // 2 MB
__device__ __align__(128) __half g_Wp_h     [HDIM * KDIM];    // 2 MB
__device__ __align__(128) __half g_iB_h    [RANK * KDIM];     // 32 KB  [R,K]
__device__ __align__(128) __half g_iA_t_h  [RANK * KDIM];     // 32 KB  iA^T -> [R,K]
__device__ __align__(128) __half g_Beff_h  [NBC * RANK * KDIM]; // 2 MB
__device__ __align__(128) float g_proj_in [NBC * CHUNK * RANK];
__device__ __align__(128) float g_proj_err[NBC * CHUNK * RANK];
__device__ __align__(128) float g_dA  [NBC * HDIM * RANK];
__device__ __align__(128) float g_dB  [NBC * RANK * KDIM];
__device__ __align__(128) float g_Aeff[NBC * HDIM * RANK];
__device__ __align__(128) float g_mid [M_TOT * RANK];

// ---------------- helpers ----------------
__device__ __forceinline__ uint32_t smem_u32(const void* p) {
    uint32_t a;
    asm("{ .reg .u64 t; cvta.to.shared.u64 t, %1; cvt.u32.u64 %0, t; }" : "=r"(a) : "l"(p));
    return a;
}
__device__ __forceinline__ void cp16(uint32_t d, const void* s) {
    asm volatile("cp.async.cg.shared.global [%0], [%1], 16;" :: "r"(d), "l"(s));
}
__device__ __forceinline__ void mma_f16(float4& c, const uint32_t a[4], const uint32_t b[2]) {
    asm volatile(
        "mma.sync.aligned.m16n8k16.row.col.f32.f16.f16.f32 "
        "{%0,%1,%2,%3}, {%4,%5,%6,%7}, {%8,%9}, {%0,%1,%2,%3};"
        : "+f"(c.x), "+f"(c.y), "+f"(c.z), "+f"(c.w)
        : "r"(a[0]), "r"(a[1]), "r"(a[2]), "r"(a[3]), "r"(b[0]), "r"(b[1]));
}
__device__ __forceinline__ void ldsm4(uint32_t r[4], uint32_t addr) {
    asm volatile("ldmatrix.sync.aligned.m8n8.x4.shared.b16 {%0,%1,%2,%3}, [%4];"
                 : "=r"(r[0]), "=r"(r[1]), "=r"(r[2]), "=r"(r[3]) : "r"(addr));
}
__device__ __forceinline__ uint32_t packh2(float x, float y) {
    __half2 h = __floats2half2_rn(x, y);
    return *reinterpret_cast<uint32_t*>(&h);
}

// ---------------- kernel 0a: fp32 -> fp16 convert (8 elems / thread) ----------------
__global__ __launch_bounds__(256) void conv_h_kernel(
    const float* __restrict__ s, __half* __restrict__ d)
{
    int i = blockIdx.x * 256 + threadIdx.x;
    float4 v0 = ((const float4*)s)[2 * i];
    float4 v1 = ((const float4*)s)[2 * i + 1];
    uint4 o;
    o.x = packh2(v0.x, v0.y);
    o.y = packh2(v0.z, v0.w);
    o.z = packh2(v1.x, v1.y);
    o.w = packh2(v1.z, v1.w);
    ((uint4*)d)[i] = o;
}

// ---------------- kernel 0b: iA [K,R] -> iA^T fp16 [R,K] ----------------
__global__ __launch_bounds__(256) void conv_iA_t_kernel(const float* __restrict__ iA)
{
    int idx = blockIdx.x * 256 + threadIdx.x;   // 0..16383
    int r = idx >> 10, k = idx & (KDIM - 1);
    g_iA_t_h[(size_t)r * KDIM + k] = __float2half(iA[(size_t)k * RANK + r]);
}

// ---------------- kernel 1: LayerNorm + shift (fp16) + x->fp16 ----------------
__global__ __launch_bounds__(256) void ln_shift_kernel(
    const float* __restrict__ x,
    const float* __restrict__ gam,
    const float* __restrict__ bet)
{
    int row = blockIdx.x;
    int s   = row & (SEQ - 1);
    const float4* xr = (const float4*)(x + (size_t)row * KDIM);
    float4 v = xr[threadIdx.x];

    // fused x -> fp16
    {
        uint2* d = (uint2*)(g_x_h + (size_t)row * KDIM);
        d[threadIdx.x] = make_uint2(packh2(v.x, v.y), packh2(v.z, v.w));
    }

    float sum = v.x + v.y + v.z + v.w;
    float ssq = v.x*v.x + v.y*v.y + v.z*v.z + v.w*v.w;
    #pragma unroll
    for (int o = 16; o; o >>= 1) {
        sum += __shfl_xor_sync(0xffffffffu, sum, o);
        ssq += __shfl_xor_sync(0xffffffffu, ssq, o);
    }
    __shared__ float s1[8], s2[8];
    int w = threadIdx.x >> 5, l = threadIdx.x & 31;
    if (!l) { s1[w] = sum; s2[w] = ssq; }
    __syncthreads();
    if (threadIdx.x == 0) {
        float a = 0.f, b = 0.f;
        #pragma unroll
        for (int i = 0; i < 8; i++) { a += s1[i]; b += s2[i]; }
        s1[0] = a; s2[0] = b;
    }
    __syncthreads();
    float mu   = s1[0] * (1.0f / KDIM);
    float var  = s2[0] * (1.0f / KDIM) - mu * mu;
    float rstd = rsqrtf(var + LN_EPS);

    if (s == 0) {
        uint2* d = (uint2*)(g_shifted_h + ((size_t)row + SEQ - 1) * KDIM);
        d[threadIdx.x] = make_uint2(0u, 0u);
    } else {
        float4 g4 = ((const float4*)gam)[threadIdx.x];
        float4 b4 = ((const float4*)bet)[threadIdx.x];
        float ox = (v.x - mu) * rstd * g4.x + b4.x;
        float oy = (v.y - mu) * rstd * g4.y + b4.y;
        float oz = (v.z - mu) * rstd * g4.z + b4.z;
        float ow = (v.w - mu) * rstd * g4.w + b4.w;
        uint2* d = (uint2*)(g_shifted_h + (size_t)(row - 1) * KDIM);
        d[threadIdx.x] = make_uint2(packh2(ox, oy), packh2(oz, ow));
    }
}

// ---------------- kernel 2: FP16 mma GEMM ----------------
// mode 0: out(fp32) = x_h @ Wb_h^T + SCALE * mid @ Aeff^T   (runs LAST)
// mode 1: g_V_h(fp16) = shifted_h @ Wp_h^T
extern __shared__ float sm_dyn[];

__device__ __forceinline__ void gemm_load_stage_h(
    uint32_t sbase, int stage, const __half* Ah, const __half* Wh, int k0, int tid)
{
    uint32_t sa = sbase + stage * STAGE_BYTES_H;
    #pragma unroll
    for (int i = 0; i < 4; i++) {
        int idx = tid + i * 256;          // 0..1023
        int row = idx >> 2;               // 0..255
        int seg = idx & 3;                // 16 B segment
        if (row < BM) {
            cp16(sa + row * ROW_B + seg * 16,
                 Ah + (size_t)row * KDIM + k0 + seg * 8);
        } else {
            int rb = row - BM;
            cp16(sa + A_REGION + rb * ROW_B + seg * 16,
                 Wh + (size_t)rb * KDIM + k0 + seg * 8);
        }
    }
    asm volatile("cp.async.commit_group;" ::: "memory");
}

__global__ __launch_bounds__(256, 2) void gemm_f16(
    float* __restrict__ out, int mode)
{
    const __half* A;
    const __half* W;
    if (mode == 0) { A = g_x_h;       W = g_Wb_h; }
    else           { A = g_shifted_h; W = g_Wp_h; }

    int tid  = threadIdx.x;
    int wid  = tid >> 5;
    int lane = tid & 31;
    int grp  = lane >> 2;
    int tig  = lane & 3;
    int wm   = wid & 1;
    int wn   = wid >> 1;

    int mbase = blockIdx.y * BM;
    int nbase = blockIdx.x * BN;
    const __half* Ab = A + (size_t)mbase * KDIM;
    const __half* Wb = W + (size_t)nbase * KDIM;

    uint32_t sbase = smem_u32(sm_dyn);

    int quad = lane >> 3, lr = lane & 7;
    uint32_t aOff = (uint32_t)(wm * 64 + ((quad & 1) << 3) + lr) * ROW_B +
                    ((quad >> 1) << 4);
    uint32_t bOff = (uint32_t)A_REGION +
                    (uint32_t)(wn * 32 + ((quad & 1) << 3) + lr) * ROW_B +
                    ((quad >> 1) << 4);

    float4 c[4][4];
    #pragma unroll
    for (int i = 0; i < 4; i++)
        #pragma unroll
        for (int j = 0; j < 4; j++) c[i][j] = make_float4(0.f, 0.f, 0.f, 0.f);

    gemm_load_stage_h(sbase, 0, Ab, Wb, 0, tid);
    gemm_load_stage_h(sbase, 1, Ab, Wb, BK, tid);

    for (int it = 0; it < NIT; it++) {
        if (it == NIT - 1) asm volatile("cp.async.wait_group 0;" ::: "memory");
        else               asm volatile("cp.async.wait_group 1;" ::: "memory");
        __syncthreads();
        if (it + 2 < NIT)
            gemm_load_stage_h(sbase, (it + 2) % NSTAGE, Ab, Wb, (it + 2) * BK, tid);

        uint32_t stge = sbase + (it % NSTAGE) * STAGE_BYTES_H;
        uint32_t aB = stge + aOff;
        uint32_t bB = stge + bOff;

        #pragma unroll
        for (int k16 = 0; k16 < 2; k16++) {
            uint32_t a[4][4], b[4][2];
            #pragma unroll
            for (int mf = 0; mf < 4; mf++)
                ldsm4(a[mf], aB + mf * (16 * ROW_B) + k16 * 32);
            #pragma unroll
            for (int p = 0; p < 2; p++) {
                uint32_t r[4];
                ldsm4(r, bB + p * (16 * ROW_B) + k16 * 32);
                b[2*p][0]   = r[0]; b[2*p][1]   = r[2];
                b[2*p+1][0] = r[1]; b[2*p+1][1] = r[3];
            }
            #pragma unroll
            for (int mf = 0; mf < 4; mf++)
                #pragma unroll
                for (int nf = 0; nf < 4; nf++)
                    mma_f16(c[mf][nf], a[mf], b[nf]);
        }
    }

    if (mode == 0) {
        // fold lora: c += (SCALE*mid) @ Aeff^T  (rank16 = one k16 mma)
        const float* midp = g_mid + (size_t)mbase * RANK;
        const float* Ae   = g_Aeff + (size_t)(mbase >> 8) * (HDIM * RANK);
        uint32_t a[4][4], b[4][2];
        #pragma unroll
        for (int mf = 0; mf < 4; mf++) {
            int r0 = wm * 64 + mf * 16 + grp;
            const float* m0 = midp + (size_t)r0 * RANK;
            const float* m1 = midp + (size_t)(r0 + 8) * RANK;
            a[mf][0] = packh2(SCALE * m0[2*tig],     SCALE * m0[2*tig + 1]);
            a[mf][1] = packh2(SCALE * m1[2*tig],     SCALE * m1[2*tig + 1]);
            a[mf][2] = packh2(SCALE * m0[8 + 2*tig], SCALE * m0[8 + 2*tig + 1]);
            a[mf][3] = packh2(SCALE * m1[8 + 2*tig], SCALE * m1[8 + 2*tig + 1]);
        }
        #pragma unroll
        for (int nf = 0; nf < 4; nf++) {
            int col = nbase + wn * 32 + nf * 8 + grp;
            const float* ap = Ae + (size_t)col * RANK;
            b[nf][0] = packh2(ap[2*tig],     ap[2*tig + 1]);
            b[nf][1] = packh2(ap[8 + 2*tig], ap[8 + 2*tig + 1]);
        }
        #pragma unroll
        for (int mf = 0; mf < 4; mf++)
            #pragma unroll
            for (int nf = 0; nf < 4; nf++)
                mma_f16(c[mf][nf], a[mf], b[nf]);

        #pragma unroll
        for (int mf = 0; mf < 4; mf++) {
            int row0 = mbase + wm * 64 + mf * 16 + grp;
            #pragma unroll
            for (int nf = 0; nf < 4; nf++) {
                int col = nbase + wn * 32 + nf * 8 + 2 * tig;
                *(float2*)(out + (size_t)row0 * HDIM + col)       = make_float2(c[mf][nf].x, c[mf][nf].y);
                *(float2*)(out + (size_t)(row0 + 8) * HDIM + col) = make_float2(c[mf][nf].z, c[mf][nf].w);
            }
        }
    } else {
        // store V as fp16
        #pragma unroll
        for (int mf = 0; mf < 4; mf++) {
            int row0 = mbase + wm * 64 + mf * 16 + grp;
            #pragma unroll
            for (int nf = 0; nf < 4; nf++) {
                int col = nbase + wn * 32 + nf * 8 + 2 * tig;
                *(uint32_t*)(g_V_h + (size_t)row0 * HDIM + col)       = packh2(c[mf][nf].x, c[mf][nf].y);
                *(uint32_t*)(g_V_h + (size_t)(row0 + 8) * HDIM + col) = packh2(c[mf][nf].z, c[mf][nf].w);
            }
        }
    }
}

// ---------------- kernel 3: proj via fp16 mma ----------------
// proj_in = x_h @ iB_h^T ; proj_err = V_h @ iA_t_h^T
__global__ __launch_bounds__(256) void proj_f16_kernel()
{
    int tid  = threadIdx.x;
    int wid  = tid >> 5;
    int lane = tid & 31;
    int grp  = lane >> 2;
    int tig  = lane & 3;

    int rowbase = blockIdx.x * 128;
    const __half* Xb = g_x_h + (size_t)rowbase * KDIM;
    const __half* Vb = g_V_h + (size_t)rowbase * KDIM;

    float4 cI[2], cE[2];
    cI[0] = make_float4(0,0,0,0); cI[1] = make_float4(0,0,0,0);
    cE[0] = make_float4(0,0,0,0); cE[1] = make_float4(0,0,0,0);

    uint32_t sbase = smem_u32(sm_dyn);

    auto load_stage = [&](int stage, int k0) {
        uint32_t sx = sbase + stage * (2 * PROJ_TILE);
        #pragma unroll
        for (int i = 0; i < 4; i++) {
            int idx = tid + i * 256;     // 0..1023
            int row = idx >> 2;          // 0..255
            int seg = idx & 3;
            if (row < 128)
                cp16(sx + row * ROW_B + seg * 16, Xb + (size_t)row * KDIM + k0 + seg * 8);
            else
                cp16(sx + PROJ_TILE + (row - 128) * ROW_B + seg * 16,
                     Vb + (size_t)(row - 128) * KDIM + k0 + seg * 8);
        }
        asm volatile("cp.async.commit_group;" ::: "memory");
    };

    load_stage(0, 0);

    int quad = lane >> 3, lr = lane & 7;
    uint32_t aOff = (uint32_t)(wid * 16 + ((quad & 1) << 3) + lr) * ROW_B +
                    ((quad >> 1) << 4);

    for (int it = 0; it < NIT; it++) {
        int k0 = it * BK;
        uint32_t bI[2][2][2], bE[2][2][2];
        #pragma unroll
        for (int kk = 0; kk < 2; kk++) {
            int kb = k0 + kk * 16;
            #pragma unroll
            for (int nf = 0; nf < 2; nf++) {
                int n = nf * 8 + grp;
                bI[kk][nf][0] = *(const uint32_t*)(g_iB_h   + (size_t)n * KDIM + kb + 2 * tig);
                bI[kk][nf][1] = *(const uint32_t*)(g_iB_h   + (size_t)n * KDIM + kb + 8 + 2 * tig);
                bE[kk][nf][0] = *(const uint32_t*)(g_iA_t_h + (size_t)n * KDIM + kb + 2 * tig);
                bE[kk][nf][1] = *(const uint32_t*)(g_iA_t_h + (size_t)n * KDIM + kb + 8 + 2 * tig);
            }
        }

        asm volatile("cp.async.wait_group 0;" ::: "memory");
        __syncthreads();
        if (it + 1 < NIT) load_stage((it + 1) & 1, k0 + BK);

        uint32_t sx = sbase + (it & 1) * (2 * PROJ_TILE);
        uint32_t sv = sx + PROJ_TILE;

        #pragma unroll
        for (int kk = 0; kk < 2; kk++) {
            uint32_t ax[4], av[4];
            ldsm4(ax, sx + aOff + kk * 32);
            ldsm4(av, sv + aOff + kk * 32);
            #pragma unroll
            for (int nf = 0; nf < 2; nf++) {
                mma_f16(cI[nf], ax, bI[kk][nf]);
                mma_f16(cE[nf], av, bE[kk][nf]);
            }
        }
        __syncthreads();
    }

    int row = rowbase + wid * 16 + grp;
    #pragma unroll
    for (int nf = 0; nf < 2; nf++) {
        int col = nf * 8 + 2 * tig;
        *(float2*)(g_proj_in  + (size_t)row * RANK + col)       = make_float2(cI[nf].x, cI[nf].y);
        *(float2*)(g_proj_in  + (size_t)(row + 8) * RANK + col) = make_float2(cI[nf].z, cI[nf].w);
        *(float2*)(g_proj_err + (size_t)row * RANK + col)       = make_float2(cE[nf].x, cE[nf].y);
        *(float2*)(g_proj_err + (size_t)(row + 8) * RANK + col) = make_float2(cE[nf].z, cE[nf].w);
    }
}

// ---------------- kernel 4: dA / dB (fp16 inputs) ----------------
__global__ __launch_bounds__(128) void delta_kernel()
{
    int c = blockIdx.x, part = blockIdx.y, mode = blockIdx.z;
    __shared__ float sp[CHUNK][RANK];
    const float* P = (mode == 0 ? g_proj_in : g_proj_err) + (size_t)c * CHUNK * RANK;
    for (int i = threadIdx.x; i < CHUNK * RANK; i += 128)
        sp[i >> 4][i & 15] = P[i];
    __syncthreads();

    int col = part * 128 + threadIdx.x;
    const __half* src = (mode == 0 ? g_V_h : g_x_h) + (size_t)c * CHUNK * KDIM + col;

    float acc[RANK];
    #pragma unroll
    for (int r = 0; r < RANK; r++) acc[r] = 0.f;

    #pragma unroll 4
    for (int i = 0; i < CHUNK; i++) {
        float v = __half2float(src[(size_t)i * KDIM]);
        #pragma unroll
        for (int r = 0; r < RANK; r++) acc[r] += v * sp[i][r];
    }

    if (mode == 0) {
        float* d = g_dA + (size_t)c * HDIM * RANK + (size_t)col * RANK;
        #pragma unroll
        for (int r = 0; r < RANK; r += 4)
            *(float4*)(d + r) = make_float4(acc[r], acc[r+1], acc[r+2], acc[r+3]);
    } else {
        float* d = g_dB + (size_t)c * RANK * KDIM + col;
        #pragma unroll
        for (int r = 0; r < RANK; r++) d[(size_t)r * KDIM] = acc[r];
    }
}

// ---------------- kernel 5: exclusive cumsum over chunks ----------------
__global__ __launch_bounds__(256) void cumsum_kernel()
{
    int e = blockIdx.x * 256 + threadIdx.x;
    int b = blockIdx.y;
    float* base = blockIdx.z ? g_dB : g_dA;
    float run = 0.f;
    #pragma unroll
    for (int j = 0; j < NCH; j++) {
        size_t off = ((size_t)(b * NCH + j)) * (HDIM * RANK) + e;
        float t = base[off];
        base[off] = run;
        run += t;
    }
}

// ---------------- kernel 6: fused clip + effective weights ----------------
__global__ __launch_bounds__(256) void clip_eff_kernel(
    const float* __restrict__ iA, const float* __restrict__ iB)
{
    int c = blockIdx.x;
    const float* A = g_dA + (size_t)c * (HDIM * RANK);
    const float* B = g_dB + (size_t)c * (RANK * KDIM);
    float s = 0.f;
    for (int i = threadIdx.x; i < HDIM * RANK; i += 256) {
        float a = A[i]; s += a * a;
        float b = B[i]; s += b * b;
    }
    #pragma unroll
    for (int o = 16; o; o >>= 1) s += __shfl_xor_sync(0xffffffffu, s, o);
    __shared__ float sm[8];
    __shared__ float s_coef;
    int w = threadIdx.x >> 5, l = threadIdx.x & 31;
    if (!l) sm[w] = s;
    __syncthreads();
    if (threadIdx.x == 0) {
        float t = 0.f;
        #pragma unroll
        for (int i = 0; i < 8; i++) t += sm[i];
        float norm = LRC * sqrtf(t);
        s_coef = LRC * fminf(1.0f, CLIP / (norm + 1e-6f));
    }
    __syncthreads();
    float sc = s_coef;
    float* Ae = g_Aeff + (size_t)c * (HDIM * RANK);
    __half* Beh = g_Beff_h + (size_t)c * (RANK * KDIM);
    for (int i = threadIdx.x; i < HDIM * RANK; i += 256) {
        Ae[i]  = iA[i] - sc * A[i];
        Beh[i] = __float2half(iB[i] - sc * B[i]);
    }
}

// ---------------- kernel 7: mid = x_h @ Beff_h^T via fp16 mma ----------------
__global__ __launch_bounds__(256) void mid_f16_kernel()
{
    int tid  = threadIdx.x;
    int wid  = tid >> 5;
    int lane = tid & 31;
    int grp  = lane >> 2;
    int tig  = lane & 3;

    int rowbase = blockIdx.x * 128;
    int c = rowbase >> 8;
    const __half* Xb = g_x_h + (size_t)rowbase * KDIM;
    const __half* Beh = g_Beff_h + (size_t)c * (RANK * KDIM);

    float4 cI[2];
    cI[0] = make_float4(0,0,0,0); cI[1] = make_float4(0,0,0,0);

    uint32_t sbase = smem_u32(sm_dyn);

    auto load_stage = [&](int stage, int k0) {
        uint32_t sx = sbase + stage * PROJ_TILE;
        #pragma unroll
        for (int i = 0; i < 2; i++) {
            int idx = tid + i * 256;     // 0..511
            int row = idx >> 2;          // 0..127
            int seg = idx & 3;
            cp16(sx + row * ROW_B + seg * 16, Xb + (size_t)row * KDIM + k0 + seg * 8);
        }
        asm volatile("cp.async.commit_group;" ::: "memory");
    };

    load_stage(0, 0);

    int quad = lane >> 3, lr = lane & 7;
    uint32_t aOff = (uint32_t)(wid * 16 + ((quad & 1) << 3) + lr) * ROW_B +
                    ((quad >> 1) << 4);

    for (int it = 0; it < NIT; it++) {
        int k0 = it * BK;
        uint32_t bI[2][2][2];
        #pragma unroll
        for (int kk = 0; kk < 2; kk++) {
            int kb = k0 + kk * 16;
            #pragma unroll
            for (int nf = 0; nf < 2; nf++) {
                int n = nf * 8 + grp;
                bI[kk][nf][0] = *(const uint32_t*)(Beh + (size_t)n * KDIM + kb + 2 * tig);
                bI[kk][nf][1] = *(const uint32_t*)(Beh + (size_t)n * KDIM + kb + 8 + 2 * tig);
            }
        }

        asm volatile("cp.async.wait_group 0;" ::: "memory");
        __syncthreads();
        if (it + 1 < NIT) load_stage((it + 1) & 1, k0 + BK);

        uint32_t sx = sbase + (it & 1) * PROJ_TILE;

        #pragma unroll
        for (int kk = 0; kk < 2; kk++) {
            uint32_t ax[4];
            ldsm4(ax, sx + aOff + kk * 32);
            #pragma unroll
            for (int nf = 0; nf < 2; nf++)
                mma_f16(cI[nf], ax, bI[kk][nf]);
        }
        __syncthreads();
    }

    int row = rowbase + wid * 16 + grp;
    #pragma unroll
    for (int nf = 0; nf < 2; nf++) {
        int col = nf * 8 + 2 * tig;
        *(float2*)(g_mid + (size_t)row * RANK + col)       = make_float2(cI[nf].x, cI[nf].y);
        *(float2*)(g_mid + (size_t)(row + 8) * RANK + col) = make_float2(cI[nf].z, cI[nf].w);
    }
}

// ---------------- launch ----------------
extern "C" void kernel_launch(void* const* d_in, const int* in_sizes, int n_in,
                              void* d_out, int out_size)
{
    const float* x   = (const float*)d_in[0];
    const float* Wb  = (const float*)d_in[1];
    const float* iA  = (const float*)d_in[2];
    const float* iB  = (const float*)d_in[3];
    const float* gam = (const float*)d_in[4];
    const float* bet = (const float*)d_in[5];
    const float* Wp  = (const float*)d_in[6];
    float* out = (float*)d_out;

    cudaFuncSetAttribute(gemm_f16,        cudaFuncAttributeMaxDynamicSharedMemorySize, SMEM_GEMM);
    cudaFuncSetAttribute(proj_f16_kernel, cudaFuncAttributeMaxDynamicSharedMemorySize, SMEM_PROJ);
    cudaFuncSetAttribute(mid_f16_kernel,  cudaFuncAttributeMaxDynamicSharedMemorySize, SMEM_MID);

    __half* wbh; cudaGetSymbolAddress((void**)&wbh, g_Wb_h);
    __half* wph; cudaGetSymbolAddress((void**)&wph, g_Wp_h);
    __half* ibh; cudaGetSymbolAddress((void**)&ibh, g_iB_h);

    conv_h_kernel<<<(HDIM * KDIM) / 2048, 256>>>(Wb, wbh);
    conv_h_kernel<<<(HDIM * KDIM) / 2048, 256>>>(Wp, wph);
    conv_h_kernel<<<(RANK * KDIM) / 2048, 256>>>(iB, ibh);
    conv_iA_t_kernel<<<(RANK * KDIM) / 256, 256>>>(iA);

    ln_shift_kernel<<<M_TOT, 256>>>(x, gam, bet);   // writes shifted_h + x_h

    dim3 gg(HDIM / BN, M_TOT / BM);
    gemm_f16<<<gg, 256, SMEM_GEMM>>>(nullptr, 1);             // V_h = shifted @ Wp^T
    proj_f16_kernel<<<M_TOT / 128, 256, SMEM_PROJ>>>();
    delta_kernel<<<dim3(NBC, KDIM / 128, 2), 128>>>();
    cumsum_kernel<<<dim3((HDIM * RANK) / 256, NBATCH, 2), 256>>>();
    clip_eff_kernel<<<NBC, 256>>>(iA, iB);
    mid_f16_kernel<<<M_TOT / 128, 256, SMEM_MID>>>();
    gemm_f16<<<gg, 256, SMEM_GEMM>>>(out, 0);                 // out = x @ Wb^T + lora
}

// round 16
// speedup vs baseline: 4.1659x; 1.0348x over previous
#include <cuda_runtime.h>
#include <cuda_fp16.h>
#include <math.h>
#include <stdint.h>

// ---------------- problem constants ----------------
#define M_TOT   16384
#define SEQ     8192
#define KDIM    1024
#define HDIM    1024
#define RANK    16
#define CHUNK   256
#define NCH     32
#define NBATCH  2
#define NBC     64
#define LRC     0.02f
#define SCALE   2.0f
#define CLIP    1.0f
#define LN_EPS  1e-5f

// ---------------- fp16 GEMM tiling (BK=64) ----------------
#define BM 128
#define BN 128
#define BK 64
#define ROW_B 144                                // 64 halves (128B) + 16B pad
#define A_REGION (BM * ROW_B)                    // 18432 B
#define STAGE_BYTES_H ((BM + BN) * ROW_B)        // 36864 B
#define NSTAGE 3
#define SMEM_GEMM (NSTAGE * STAGE_BYTES_H)       // 110592 B
#define NIT (KDIM / BK)                          // 16

// proj/mid fp16 kernels (BK=32 tiles, 80B rows)
#define PROW_B 80
#define PROJ_TILE (128 * PROW_B)                 // 10240 B
#define SMEM_PROJ (2 * 2 * PROJ_TILE)            // 40960 B
#define SMEM_MID  (2 * PROJ_TILE)                // 20480 B
#define PNIT (KDIM / 32)                         // 32

// ---------------- device scratch ----------------
__device__ __align__(128) __half g_x_h      [M_TOT * KDIM];
__device__ __align__(128) __half g_shifted_h[M_TOT * KDIM];
__device__ __align__(128) __half g_V_h      [M_TOT * KDIM];
__device__ __align__(128) __half g_Wb_h     [HDIM * KDIM];
__device__ __align__(128) __half g_Wp_h     [HDIM * KDIM];
__device__ __align__(128) __half g_iB_h    [RANK * KDIM];
__device__ __align__(128) __half g_iA_t_h  [RANK * KDIM];
__device__ __align__(128) __half g_Beff_h  [NBC * RANK * KDIM];
__device__ __align__(128) float g_proj_in [NBC * CHUNK * RANK];
__device__ __align__(128) float g_proj_err[NBC * CHUNK * RANK];
__device__ __align__(128) float g_dA  [NBC * HDIM * RANK];
__device__ __align__(128) float g_dB  [NBC * RANK * KDIM];
__device__ __align__(128) float g_Aeff[NBC * HDIM * RANK];
__device__ __align__(128) float g_mid [M_TOT * RANK];

// ---------------- helpers ----------------
__device__ __forceinline__ uint32_t smem_u32(const void* p) {
    uint32_t a;
    asm("{ .reg .u64 t; cvta.to.shared.u64 t, %1; cvt.u32.u64 %0, t; }" : "=r"(a) : "l"(p));
    return a;
}
__device__ __forceinline__ void cp16(uint32_t d, const void* s) {
    asm volatile("cp.async.cg.shared.global [%0], [%1], 16;" :: "r"(d), "l"(s));
}
__device__ __forceinline__ void mma_f16(float4& c, const uint32_t a[4], const uint32_t b[2]) {
    asm volatile(
        "mma.sync.aligned.m16n8k16.row.col.f32.f16.f16.f32 "
        "{%0,%1,%2,%3}, {%4,%5,%6,%7}, {%8,%9}, {%0,%1,%2,%3};"
        : "+f"(c.x), "+f"(c.y), "+f"(c.z), "+f"(c.w)
        : "r"(a[0]), "r"(a[1]), "r"(a[2]), "r"(a[3]), "r"(b[0]), "r"(b[1]));
}
__device__ __forceinline__ void ldsm4(uint32_t r[4], uint32_t addr) {
    asm volatile("ldmatrix.sync.aligned.m8n8.x4.shared.b16 {%0,%1,%2,%3}, [%4];"
                 : "=r"(r[0]), "=r"(r[1]), "=r"(r[2]), "=r"(r[3]) : "r"(addr));
}
__device__ __forceinline__ uint32_t packh2(float x, float y) {
    __half2 h = __floats2half2_rn(x, y);
    return *reinterpret_cast<uint32_t*>(&h);
}

// ---------------- kernel 0a: merged fp32->fp16 conversion (Wb | Wp | iB) ----------------
// blocks [0,512): Wb, [512,1024): Wp, [1024,1032): iB   (8 elems/thread)
__global__ __launch_bounds__(256) void conv_merged_kernel(
    const float* __restrict__ Wb, const float* __restrict__ Wp,
    const float* __restrict__ iB)
{
    int b = blockIdx.x;
    const float* s;
    __half* d;
    int base;
    if (b < 512)       { s = Wb; d = g_Wb_h; base = b; }
    else if (b < 1024) { s = Wp; d = g_Wp_h; base = b - 512; }
    else               { s = iB; d = g_iB_h; base = b - 1024; }
    int i = base * 256 + threadIdx.x;
    float4 v0 = ((const float4*)s)[2 * i];
    float4 v1 = ((const float4*)s)[2 * i + 1];
    uint4 o;
    o.x = packh2(v0.x, v0.y);
    o.y = packh2(v0.z, v0.w);
    o.z = packh2(v1.x, v1.y);
    o.w = packh2(v1.z, v1.w);
    ((uint4*)d)[i] = o;
}

// ---------------- kernel 0b: iA [K,R] -> iA^T fp16 [R,K] ----------------
__global__ __launch_bounds__(256) void conv_iA_t_kernel(const float* __restrict__ iA)
{
    int idx = blockIdx.x * 256 + threadIdx.x;
    int r = idx >> 10, k = idx & (KDIM - 1);
    g_iA_t_h[(size_t)r * KDIM + k] = __float2half(iA[(size_t)k * RANK + r]);
}

// ---------------- kernel 1: LayerNorm + shift (fp16) + x->fp16 ----------------
__global__ __launch_bounds__(256) void ln_shift_kernel(
    const float* __restrict__ x,
    const float* __restrict__ gam,
    const float* __restrict__ bet)
{
    int row = blockIdx.x;
    int s   = row & (SEQ - 1);
    const float4* xr = (const float4*)(x + (size_t)row * KDIM);
    float4 v = xr[threadIdx.x];

    {
        uint2* d = (uint2*)(g_x_h + (size_t)row * KDIM);
        d[threadIdx.x] = make_uint2(packh2(v.x, v.y), packh2(v.z, v.w));
    }

    float sum = v.x + v.y + v.z + v.w;
    float ssq = v.x*v.x + v.y*v.y + v.z*v.z + v.w*v.w;
    #pragma unroll
    for (int o = 16; o; o >>= 1) {
        sum += __shfl_xor_sync(0xffffffffu, sum, o);
        ssq += __shfl_xor_sync(0xffffffffu, ssq, o);
    }
    __shared__ float s1[8], s2[8];
    int w = threadIdx.x >> 5, l = threadIdx.x & 31;
    if (!l) { s1[w] = sum; s2[w] = ssq; }
    __syncthreads();
    if (threadIdx.x == 0) {
        float a = 0.f, b = 0.f;
        #pragma unroll
        for (int i = 0; i < 8; i++) { a += s1[i]; b += s2[i]; }
        s1[0] = a; s2[0] = b;
    }
    __syncthreads();
    float mu   = s1[0] * (1.0f / KDIM);
    float var  = s2[0] * (1.0f / KDIM) - mu * mu;
    float rstd = rsqrtf(var + LN_EPS);

    if (s == 0) {
        uint2* d = (uint2*)(g_shifted_h + ((size_t)row + SEQ - 1) * KDIM);
        d[threadIdx.x] = make_uint2(0u, 0u);
    } else {
        float4 g4 = ((const float4*)gam)[threadIdx.x];
        float4 b4 = ((const float4*)bet)[threadIdx.x];
        float ox = (v.x - mu) * rstd * g4.x + b4.x;
        float oy = (v.y - mu) * rstd * g4.y + b4.y;
        float oz = (v.z - mu) * rstd * g4.z + b4.z;
        float ow = (v.w - mu) * rstd * g4.w + b4.w;
        uint2* d = (uint2*)(g_shifted_h + (size_t)(row - 1) * KDIM);
        d[threadIdx.x] = make_uint2(packh2(ox, oy), packh2(oz, ow));
    }
}

// ---------------- kernel 2: FP16 mma GEMM (BK=64) ----------------
// mode 0: out(fp32) = x_h @ Wb_h^T + SCALE * mid @ Aeff^T   (runs LAST)
// mode 1: g_V_h(fp16) = shifted_h @ Wp_h^T
extern __shared__ float sm_dyn[];

__device__ __forceinline__ void gemm_load_stage_h(
    uint32_t sbase, int stage, const __half* Ah, const __half* Wh, int k0, int tid)
{
    uint32_t sa = sbase + stage * STAGE_BYTES_H;
    #pragma unroll
    for (int i = 0; i < 8; i++) {
        int idx = tid + i * 256;          // 0..2047
        int row = idx >> 3;               // 0..255
        int seg = idx & 7;                // 16 B segment (8 per 128B row)
        if (row < BM) {
            cp16(sa + row * ROW_B + seg * 16,
                 Ah + (size_t)row * KDIM + k0 + seg * 8);
        } else {
            int rb = row - BM;
            cp16(sa + A_REGION + rb * ROW_B + seg * 16,
                 Wh + (size_t)rb * KDIM + k0 + seg * 8);
        }
    }
    asm volatile("cp.async.commit_group;" ::: "memory");
}

__global__ __launch_bounds__(256, 2) void gemm_f16(
    float* __restrict__ out, int mode)
{
    const __half* A;
    const __half* W;
    if (mode == 0) { A = g_x_h;       W = g_Wb_h; }
    else           { A = g_shifted_h; W = g_Wp_h; }

    int tid  = threadIdx.x;
    int wid  = tid >> 5;
    int lane = tid & 31;
    int grp  = lane >> 2;
    int tig  = lane & 3;
    int wm   = wid & 1;
    int wn   = wid >> 1;

    int mbase = blockIdx.y * BM;
    int nbase = blockIdx.x * BN;
    const __half* Ab = A + (size_t)mbase * KDIM;
    const __half* Wb = W + (size_t)nbase * KDIM;

    uint32_t sbase = smem_u32(sm_dyn);

    int quad = lane >> 3, lr = lane & 7;
    uint32_t aOff = (uint32_t)(wm * 64 + ((quad & 1) << 3) + lr) * ROW_B +
                    ((quad >> 1) << 4);
    uint32_t bOff = (uint32_t)A_REGION +
                    (uint32_t)(wn * 32 + ((quad & 1) << 3) + lr) * ROW_B +
                    ((quad >> 1) << 4);

    float4 c[4][4];
    #pragma unroll
    for (int i = 0; i < 4; i++)
        #pragma unroll
        for (int j = 0; j < 4; j++) c[i][j] = make_float4(0.f, 0.f, 0.f, 0.f);

    gemm_load_stage_h(sbase, 0, Ab, Wb, 0, tid);
    gemm_load_stage_h(sbase, 1, Ab, Wb, BK, tid);

    for (int it = 0; it < NIT; it++) {
        if (it == NIT - 1) asm volatile("cp.async.wait_group 0;" ::: "memory");
        else               asm volatile("cp.async.wait_group 1;" ::: "memory");
        __syncthreads();
        if (it + 2 < NIT)
            gemm_load_stage_h(sbase, (it + 2) % NSTAGE, Ab, Wb, (it + 2) * BK, tid);

        uint32_t stge = sbase + (it % NSTAGE) * STAGE_BYTES_H;
        uint32_t aB = stge + aOff;
        uint32_t bB = stge + bOff;

        #pragma unroll
        for (int k16 = 0; k16 < 4; k16++) {
            uint32_t a[4][4], b[4][2];
            #pragma unroll
            for (int mf = 0; mf < 4; mf++)
                ldsm4(a[mf], aB + mf * (16 * ROW_B) + k16 * 32);
            #pragma unroll
            for (int p = 0; p < 2; p++) {
                uint32_t r[4];
                ldsm4(r, bB + p * (16 * ROW_B) + k16 * 32);
                b[2*p][0]   = r[0]; b[2*p][1]   = r[2];
                b[2*p+1][0] = r[1]; b[2*p+1][1] = r[3];
            }
            #pragma unroll
            for (int mf = 0; mf < 4; mf++)
                #pragma unroll
                for (int nf = 0; nf < 4; nf++)
                    mma_f16(c[mf][nf], a[mf], b[nf]);
        }
    }

    if (mode == 0) {
        // fold lora: c += (SCALE*mid) @ Aeff^T  (rank16 = one k16 mma)
        const float* midp = g_mid + (size_t)mbase * RANK;
        const float* Ae   = g_Aeff + (size_t)(mbase >> 8) * (HDIM * RANK);
        uint32_t a[4][4], b[4][2];
        #pragma unroll
        for (int mf = 0; mf < 4; mf++) {
            int r0 = wm * 64 + mf * 16 + grp;
            const float* m0 = midp + (size_t)r0 * RANK;
            const float* m1 = midp + (size_t)(r0 + 8) * RANK;
            a[mf][0] = packh2(SCALE * m0[2*tig],     SCALE * m0[2*tig + 1]);
            a[mf][1] = packh2(SCALE * m1[2*tig],     SCALE * m1[2*tig + 1]);
            a[mf][2] = packh2(SCALE * m0[8 + 2*tig], SCALE * m0[8 + 2*tig + 1]);
            a[mf][3] = packh2(SCALE * m1[8 + 2*tig], SCALE * m1[8 + 2*tig + 1]);
        }
        #pragma unroll
        for (int nf = 0; nf < 4; nf++) {
            int col = nbase + wn * 32 + nf * 8 + grp;
            const float* ap = Ae + (size_t)col * RANK;
            b[nf][0] = packh2(ap[2*tig],     ap[2*tig + 1]);
            b[nf][1] = packh2(ap[8 + 2*tig], ap[8 + 2*tig + 1]);
        }
        #pragma unroll
        for (int mf = 0; mf < 4; mf++)
            #pragma unroll
            for (int nf = 0; nf < 4; nf++)
                mma_f16(c[mf][nf], a[mf], b[nf]);

        #pragma unroll
        for (int mf = 0; mf < 4; mf++) {
            int row0 = mbase + wm * 64 + mf * 16 + grp;
            #pragma unroll
            for (int nf = 0; nf < 4; nf++) {
                int col = nbase + wn * 32 + nf * 8 + 2 * tig;
                *(float2*)(out + (size_t)row0 * HDIM + col)       = make_float2(c[mf][nf].x, c[mf][nf].y);
                *(float2*)(out + (size_t)(row0 + 8) * HDIM + col) = make_float2(c[mf][nf].z, c[mf][nf].w);
            }
        }
    } else {
        #pragma unroll
        for (int mf = 0; mf < 4; mf++) {
            int row0 = mbase + wm * 64 + mf * 16 + grp;
            #pragma unroll
            for (int nf = 0; nf < 4; nf++) {
                int col = nbase + wn * 32 + nf * 8 + 2 * tig;
                *(uint32_t*)(g_V_h + (size_t)row0 * HDIM + col)       = packh2(c[mf][nf].x, c[mf][nf].y);
                *(uint32_t*)(g_V_h + (size_t)(row0 + 8) * HDIM + col) = packh2(c[mf][nf].z, c[mf][nf].w);
            }
        }
    }
}

// ---------------- kernel 3: proj via fp16 mma ----------------
__global__ __launch_bounds__(256) void proj_f16_kernel()
{
    int tid  = threadIdx.x;
    int wid  = tid >> 5;
    int lane = tid & 31;
    int grp  = lane >> 2;
    int tig  = lane & 3;

    int rowbase = blockIdx.x * 128;
    const __half* Xb = g_x_h + (size_t)rowbase * KDIM;
    const __half* Vb = g_V_h + (size_t)rowbase * KDIM;

    float4 cI[2], cE[2];
    cI[0] = make_float4(0,0,0,0); cI[1] = make_float4(0,0,0,0);
    cE[0] = make_float4(0,0,0,0); cE[1] = make_float4(0,0,0,0);

    uint32_t sbase = smem_u32(sm_dyn);

    auto load_stage = [&](int stage, int k0) {
        uint32_t sx = sbase + stage * (2 * PROJ_TILE);
        #pragma unroll
        for (int i = 0; i < 4; i++) {
            int idx = tid + i * 256;
            int row = idx >> 2;
            int seg = idx & 3;
            if (row < 128)
                cp16(sx + row * PROW_B + seg * 16, Xb + (size_t)row * KDIM + k0 + seg * 8);
            else
                cp16(sx + PROJ_TILE + (row - 128) * PROW_B + seg * 16,
                     Vb + (size_t)(row - 128) * KDIM + k0 + seg * 8);
        }
        asm volatile("cp.async.commit_group;" ::: "memory");
    };

    load_stage(0, 0);

    int quad = lane >> 3, lr = lane & 7;
    uint32_t aOff = (uint32_t)(wid * 16 + ((quad & 1) << 3) + lr) * PROW_B +
                    ((quad >> 1) << 4);

    for (int it = 0; it < PNIT; it++) {
        int k0 = it * 32;
        uint32_t bI[2][2][2], bE[2][2][2];
        #pragma unroll
        for (int kk = 0; kk < 2; kk++) {
            int kb = k0 + kk * 16;
            #pragma unroll
            for (int nf = 0; nf < 2; nf++) {
                int n = nf * 8 + grp;
                bI[kk][nf][0] = *(const uint32_t*)(g_iB_h   + (size_t)n * KDIM + kb + 2 * tig);
                bI[kk][nf][1] = *(const uint32_t*)(g_iB_h   + (size_t)n * KDIM + kb + 8 + 2 * tig);
                bE[kk][nf][0] = *(const uint32_t*)(g_iA_t_h + (size_t)n * KDIM + kb + 2 * tig);
                bE[kk][nf][1] = *(const uint32_t*)(g_iA_t_h + (size_t)n * KDIM + kb + 8 + 2 * tig);
            }
        }

        asm volatile("cp.async.wait_group 0;" ::: "memory");
        __syncthreads();
        if (it + 1 < PNIT) load_stage((it + 1) & 1, k0 + 32);

        uint32_t sx = sbase + (it & 1) * (2 * PROJ_TILE);
        uint32_t sv = sx + PROJ_TILE;

        #pragma unroll
        for (int kk = 0; kk < 2; kk++) {
            uint32_t ax[4], av[4];
            ldsm4(ax, sx + aOff + kk * 32);
            ldsm4(av, sv + aOff + kk * 32);
            #pragma unroll
            for (int nf = 0; nf < 2; nf++) {
                mma_f16(cI[nf], ax, bI[kk][nf]);
                mma_f16(cE[nf], av, bE[kk][nf]);
            }
        }
        __syncthreads();
    }

    int row = rowbase + wid * 16 + grp;
    #pragma unroll
    for (int nf = 0; nf < 2; nf++) {
        int col = nf * 8 + 2 * tig;
        *(float2*)(g_proj_in  + (size_t)row * RANK + col)       = make_float2(cI[nf].x, cI[nf].y);
        *(float2*)(g_proj_in  + (size_t)(row + 8) * RANK + col) = make_float2(cI[nf].z, cI[nf].w);
        *(float2*)(g_proj_err + (size_t)row * RANK + col)       = make_float2(cE[nf].x, cE[nf].y);
        *(float2*)(g_proj_err + (size_t)(row + 8) * RANK + col) = make_float2(cE[nf].z, cE[nf].w);
    }
}

// ---------------- kernel 4: dA / dB (half2, 2 cols/thread) ----------------
__global__ __launch_bounds__(128) void delta_kernel()
{
    int c = blockIdx.x, part = blockIdx.y, mode = blockIdx.z;
    __shared__ float sp[CHUNK][RANK];
    const float* P = (mode == 0 ? g_proj_in : g_proj_err) + (size_t)c * CHUNK * RANK;
    for (int i = threadIdx.x; i < CHUNK * RANK; i += 128)
        sp[i >> 4][i & 15] = P[i];
    __syncthreads();

    int col = part * 256 + threadIdx.x * 2;
    const __half2* src = (const __half2*)(
        (mode == 0 ? g_V_h : g_x_h) + (size_t)c * CHUNK * KDIM + col);

    float a0[RANK], a1[RANK];
    #pragma unroll
    for (int r = 0; r < RANK; r++) { a0[r] = 0.f; a1[r] = 0.f; }

    #pragma unroll 2
    for (int i = 0; i < CHUNK; i++) {
        float2 f = __half22float2(src[(size_t)i * (KDIM / 2)]);
        #pragma unroll
        for (int r = 0; r < RANK; r++) {
            a0[r] += f.x * sp[i][r];
            a1[r] += f.y * sp[i][r];
        }
    }

    if (mode == 0) {
        float* d = g_dA + (size_t)c * HDIM * RANK + (size_t)col * RANK;
        #pragma unroll
        for (int r = 0; r < RANK; r += 4) {
            *(float4*)(d + r)        = make_float4(a0[r], a0[r+1], a0[r+2], a0[r+3]);
            *(float4*)(d + RANK + r) = make_float4(a1[r], a1[r+1], a1[r+2], a1[r+3]);
        }
    } else {
        float* d = g_dB + (size_t)c * RANK * KDIM + col;
        #pragma unroll
        for (int r = 0; r < RANK; r++)
            *(float2*)(d + (size_t)r * KDIM) = make_float2(a0[r], a1[r]);
    }
}

// ---------------- kernel 5: exclusive cumsum over chunks ----------------
__global__ __launch_bounds__(256) void cumsum_kernel()
{
    int e = blockIdx.x * 256 + threadIdx.x;
    int b = blockIdx.y;
    float* base = blockIdx.z ? g_dB : g_dA;
    float run = 0.f;
    #pragma unroll
    for (int j = 0; j < NCH; j++) {
        size_t off = ((size_t)(b * NCH + j)) * (HDIM * RANK) + e;
        float t = base[off];
        base[off] = run;
        run += t;
    }
}

// ---------------- kernel 6: fused clip + effective weights ----------------
__global__ __launch_bounds__(256) void clip_eff_kernel(
    const float* __restrict__ iA, const float* __restrict__ iB)
{
    int c = blockIdx.x;
    const float* A = g_dA + (size_t)c * (HDIM * RANK);
    const float* B = g_dB + (size_t)c * (RANK * KDIM);
    float s = 0.f;
    for (int i = threadIdx.x; i < HDIM * RANK; i += 256) {
        float a = A[i]; s += a * a;
        float b = B[i]; s += b * b;
    }
    #pragma unroll
    for (int o = 16; o; o >>= 1) s += __shfl_xor_sync(0xffffffffu, s, o);
    __shared__ float sm[8];
    __shared__ float s_coef;
    int w = threadIdx.x >> 5, l = threadIdx.x & 31;
    if (!l) sm[w] = s;
    __syncthreads();
    if (threadIdx.x == 0) {
        float t = 0.f;
        #pragma unroll
        for (int i = 0; i < 8; i++) t += sm[i];
        float norm = LRC * sqrtf(t);
        s_coef = LRC * fminf(1.0f, CLIP / (norm + 1e-6f));
    }
    __syncthreads();
    float sc = s_coef;
    float* Ae = g_Aeff + (size_t)c * (HDIM * RANK);
    __half* Beh = g_Beff_h + (size_t)c * (RANK * KDIM);
    for (int i = threadIdx.x; i < HDIM * RANK; i += 256) {
        Ae[i]  = iA[i] - sc * A[i];
        Beh[i] = __float2half(iB[i] - sc * B[i]);
    }
}

// ---------------- kernel 7: mid = x_h @ Beff_h^T via fp16 mma ----------------
__global__ __launch_bounds__(256) void mid_f16_kernel()
{
    int tid  = threadIdx.x;
    int wid  = tid >> 5;
    int lane = tid & 31;
    int grp  = lane >> 2;
    int tig  = lane & 3;

    int rowbase = blockIdx.x * 128;
    int c = rowbase >> 8;
    const __half* Xb = g_x_h + (size_t)rowbase * KDIM;
    const __half* Beh = g_Beff_h + (size_t)c * (RANK * KDIM);

    float4 cI[2];
    cI[0] = make_float4(0,0,0,0); cI[1] = make_float4(0,0,0,0);

    uint32_t sbase = smem_u32(sm_dyn);

    auto load_stage = [&](int stage, int k0) {
        uint32_t sx = sbase + stage * PROJ_TILE;
        #pragma unroll
        for (int i = 0; i < 2; i++) {
            int idx = tid + i * 256;
            int row = idx >> 2;
            int seg = idx & 3;
            cp16(sx + row * PROW_B + seg * 16, Xb + (size_t)row * KDIM + k0 + seg * 8);
        }
        asm volatile("cp.async.commit_group;" ::: "memory");
    };

    load_stage(0, 0);

    int quad = lane >> 3, lr = lane & 7;
    uint32_t aOff = (uint32_t)(wid * 16 + ((quad & 1) << 3) + lr) * PROW_B +
                    ((quad >> 1) << 4);

    for (int it = 0; it < PNIT; it++) {
        int k0 = it * 32;
        uint32_t bI[2][2][2];
        #pragma unroll
        for (int kk = 0; kk < 2; kk++) {
            int kb = k0 + kk * 16;
            #pragma unroll
            for (int nf = 0; nf < 2; nf++) {
                int n = nf * 8 + grp;
                bI[kk][nf][0] = *(const uint32_t*)(Beh + (size_t)n * KDIM + kb + 2 * tig);
                bI[kk][nf][1] = *(const uint32_t*)(Beh + (size_t)n * KDIM + kb + 8 + 2 * tig);
            }
        }

        asm volatile("cp.async.wait_group 0;" ::: "memory");
        __syncthreads();
        if (it + 1 < PNIT) load_stage((it + 1) & 1, k0 + 32);

        uint32_t sx = sbase + (it & 1) * PROJ_TILE;

        #pragma unroll
        for (int kk = 0; kk < 2; kk++) {
            uint32_t ax[4];
            ldsm4(ax, sx + aOff + kk * 32);
            #pragma unroll
            for (int nf = 0; nf < 2; nf++)
                mma_f16(cI[nf], ax, bI[kk][nf]);
        }
        __syncthreads();
    }

    int row = rowbase + wid * 16 + grp;
    #pragma unroll
    for (int nf = 0; nf < 2; nf++) {
        int col = nf * 8 + 2 * tig;
        *(float2*)(g_mid + (size_t)row * RANK + col)       = make_float2(cI[nf].x, cI[nf].y);
        *(float2*)(g_mid + (size_t)(row + 8) * RANK + col) = make_float2(cI[nf].z, cI[nf].w);
    }
}

// ---------------- launch ----------------
extern "C" void kernel_launch(void* const* d_in, const int* in_sizes, int n_in,
                              void* d_out, int out_size)
{
    const float* x   = (const float*)d_in[0];
    const float* Wb  = (const float*)d_in[1];
    const float* iA  = (const float*)d_in[2];
    const float* iB  = (const float*)d_in[3];
    const float* gam = (const float*)d_in[4];
    const float* bet = (const float*)d_in[5];
    const float* Wp  = (const float*)d_in[6];
    float* out = (float*)d_out;

    cudaFuncSetAttribute(gemm_f16,        cudaFuncAttributeMaxDynamicSharedMemorySize, SMEM_GEMM);
    cudaFuncSetAttribute(proj_f16_kernel, cudaFuncAttributeMaxDynamicSharedMemorySize, SMEM_PROJ);
    cudaFuncSetAttribute(mid_f16_kernel,  cudaFuncAttributeMaxDynamicSharedMemorySize, SMEM_MID);

    conv_merged_kernel<<<1032, 256>>>(Wb, Wp, iB);
    conv_iA_t_kernel<<<(RANK * KDIM) / 256, 256>>>(iA);

    ln_shift_kernel<<<M_TOT, 256>>>(x, gam, bet);   // writes shifted_h + x_h

    dim3 gg(HDIM / BN, M_TOT / BM);
    gemm_f16<<<gg, 256, SMEM_GEMM>>>(nullptr, 1);             // V_h = shifted @ Wp^T
    proj_f16_kernel<<<M_TOT / 128, 256, SMEM_PROJ>>>();
    delta_kernel<<<dim3(NBC, KDIM / 256, 2), 128>>>();
    cumsum_kernel<<<dim3((HDIM * RANK) / 256, NBATCH, 2), 256>>>();
    clip_eff_kernel<<<NBC, 256>>>(iA, iB);
    mid_f16_kernel<<<M_TOT / 128, 256, SMEM_MID>>>();
    gemm_f16<<<gg, 256, SMEM_GEMM>>>(out, 0);                 // out = x @ Wb^T + lora
}